// round 1
// baseline (speedup 1.0000x reference)
#include <cuda_runtime.h>
#include <cuda_bf16.h>

// Problem constants
#define BATCH 2
#define NA 256
#define NB 256
#define EDIM 512
#define H1 300
#define H2 100

typedef unsigned long long ull;

// ---------------- scratch (device globals; no allocation) ----------------
__device__ float g_hAa[BATCH * NA * H1]; // Phi_A @ W1a + b1
__device__ float g_hAb[BATCH * NA * H1]; // Phi_A @ W1b
__device__ float g_hBa[BATCH * NB * H1]; // Phi_B @ W1a + b1
__device__ float g_hBb[BATCH * NB * H1]; // Phi_B @ W1b
__device__ float g_R2[BATCH * NA * NB];  // R_est^2
__device__ float g_geo[BATCH * 16];      // [0..5] Minv sym (i00,i01,i02,i11,i12,i22), [6..8] g, [9..11] qbar
__device__ float g_y1[BATCH * 64 * NA];  // pointnet layer0 output

// ---------------- helpers ----------------
__device__ __forceinline__ ull ffma2(ull a, ull b, ull c) {
    ull d;
    asm("fma.rn.f32x2 %0, %1, %2, %3;" : "=l"(d) : "l"(a), "l"(b), "l"(c));
    return d;
}
__device__ __forceinline__ ull pack2(float x) {
    ull v = (ull)__float_as_uint(x);
    return v | (v << 32);
}
__device__ __forceinline__ float lo32(ull v) { return __uint_as_float((unsigned)(v & 0xffffffffull)); }
__device__ __forceinline__ float hi32(ull v) { return __uint_as_float((unsigned)(v >> 32)); }

// =========================================================================
// K1: h matrices.  C[n,j] = sum_e emb[e,n] * W1[half*512+e, j]  (+ b1 if half==0)
// grid (5 jtile, 4 ntile, bi+src*2+half*4), block (16,16). Tile 64x64, K-chunk 16.
// =========================================================================
__global__ void k1_h(const float* __restrict__ actE, const float* __restrict__ anchE,
                     const float* __restrict__ W1, const float* __restrict__ b1) {
    int bi   = blockIdx.z & 1;
    int src  = (blockIdx.z >> 1) & 1;
    int half = blockIdx.z >> 2;
    const float* emb = (src ? anchE : actE) + bi * EDIM * NA;
    float* outp = (half == 0 ? (src ? g_hBa : g_hAa) : (src ? g_hBb : g_hAb)) + bi * NA * H1;

    int n0 = blockIdx.y * 64;
    int j0 = blockIdx.x * 64;
    int tx = threadIdx.x, ty = threadIdx.y;
    int tid = ty * 16 + tx;

    __shared__ float As[16 * 64];
    __shared__ float Bs[16 * 64];

    float acc[4][4];
#pragma unroll
    for (int i = 0; i < 4; ++i)
#pragma unroll
        for (int j = 0; j < 4; ++j) acc[i][j] = 0.f;

    int wbase = half * 512;
    int lkk = tid / 16;
    int l4  = (tid % 16) * 4;

    for (int k0 = 0; k0 < EDIM; k0 += 16) {
        __syncthreads();
        // load A chunk: As[kk][m] = emb[(k0+kk)*NA + n0+m]
        *(float4*)&As[lkk * 64 + l4] = *(const float4*)&emb[(k0 + lkk) * NA + n0 + l4];
        // load B chunk: Bs[kk][jj] = W1[(wbase+k0+kk)*H1 + j0+jj] (0 if j>=300)
        {
            int jg = j0 + l4;
            float4 bv = make_float4(0.f, 0.f, 0.f, 0.f);
            if (jg < H1) bv = *(const float4*)&W1[(wbase + k0 + lkk) * H1 + jg];
            *(float4*)&Bs[lkk * 64 + l4] = bv;
        }
        __syncthreads();
#pragma unroll
        for (int kk = 0; kk < 16; ++kk) {
            float4 a4 = *(const float4*)&As[kk * 64 + ty * 4];
            float4 b4 = *(const float4*)&Bs[kk * 64 + tx * 4];
            float av[4] = {a4.x, a4.y, a4.z, a4.w};
            float bv[4] = {b4.x, b4.y, b4.z, b4.w};
#pragma unroll
            for (int i = 0; i < 4; ++i)
#pragma unroll
                for (int j = 0; j < 4; ++j) acc[i][j] = fmaf(av[i], bv[j], acc[i][j]);
        }
    }
#pragma unroll
    for (int i = 0; i < 4; ++i) {
        int n = n0 + ty * 4 + i;
#pragma unroll
        for (int j = 0; j < 4; ++j) {
            int jg = j0 + tx * 4 + j;
            if (jg < H1) {
                float v = acc[i][j];
                if (half == 0) v += b1[jg];
                outp[n * H1 + jg] = v;
            }
        }
    }
}

// =========================================================================
// K2: pairwise MLP (dominant).  Tile 16 a x 8 b = 128 pairs, 256 threads
// (2 threads/pair splitting 100 output cols as 52/48, padded to 104).
// Both sides v1,v2 share W2 smem loads. FFMA2 (f32x2) main loop.
// grid (32 btile, 16 atile, 2 bi), block 256.
// =========================================================================
__global__ void __launch_bounds__(256) k2_pair(const float* __restrict__ W2,
                                               const float* __restrict__ b2,
                                               const float* __restrict__ W3,
                                               const float* __restrict__ b3p) {
    const int tid = threadIdx.x;
    const int jh = tid & 1;
    const int p  = tid >> 1;
    const int bl = p & 7;
    const int al = p >> 3;
    const int b0 = blockIdx.x * 8;
    const int a0 = blockIdx.y * 16;
    const int bi = blockIdx.z;
    const int jbase = jh * 52;

    __shared__ float hAa_c[16 * 50];
    __shared__ float hAb_c[16 * 50];
    __shared__ float hBa_c[8 * 50];
    __shared__ float hBb_c[8 * 50];
    __shared__ float W2s[50 * 104];
    __shared__ float b2s[104];
    __shared__ float W3s[104];

    if (tid < 104) {
        b2s[tid] = (tid < H2) ? b2[tid] : 0.f;
        W3s[tid] = (tid < H2) ? W3[tid] : 0.f;
    }
    if (tid < 50) {
        W2s[tid * 104 + 100] = 0.f;
        W2s[tid * 104 + 101] = 0.f;
        W2s[tid * 104 + 102] = 0.f;
        W2s[tid * 104 + 103] = 0.f;
    }

    ull acc1[26], acc2[26];
#pragma unroll
    for (int v = 0; v < 26; ++v) { acc1[v] = 0ull; acc2[v] = 0ull; }

    const float* baseAa = g_hAa + (bi * NA + a0) * H1;
    const float* baseAb = g_hAb + (bi * NA + a0) * H1;
    const float* baseBa = g_hBa + (bi * NB + b0) * H1;
    const float* baseBb = g_hBb + (bi * NB + b0) * H1;

    const float* hA1 = hAa_c + al * 50; // v1: hA_a[a]
    const float* hB1 = hBb_c + bl * 50; // v1: hB_b[b]
    const float* hA2 = hAb_c + al * 50; // v2: hA_b[a]
    const float* hB2 = hBa_c + bl * 50; // v2: hB_a[b]

    for (int c = 0; c < 6; ++c) {
        const int k0 = c * 50;
        __syncthreads();
        // W2 chunk [50 x 100] -> smem pitch 104 (float4)
        for (int v = tid; v < 1250; v += 256) {
            int kk = v / 25, j4 = (v % 25) * 4;
            *(float4*)&W2s[kk * 104 + j4] = *(const float4*)&W2[(k0 + kk) * H2 + j4];
        }
        // h chunks (float2; 50-offset is 8B aligned)
        for (int v = tid; v < 400; v += 256) {
            int r = v / 25, kp = (v % 25) * 2;
            *(float2*)&hAa_c[r * 50 + kp] = *(const float2*)&baseAa[r * H1 + k0 + kp];
        }
        for (int v = tid; v < 400; v += 256) {
            int r = v / 25, kp = (v % 25) * 2;
            *(float2*)&hAb_c[r * 50 + kp] = *(const float2*)&baseAb[r * H1 + k0 + kp];
        }
        for (int v = tid; v < 200; v += 256) {
            int r = v / 25, kp = (v % 25) * 2;
            *(float2*)&hBa_c[r * 50 + kp] = *(const float2*)&baseBa[r * H1 + k0 + kp];
        }
        for (int v = tid; v < 200; v += 256) {
            int r = v / 25, kp = (v % 25) * 2;
            *(float2*)&hBb_c[r * 50 + kp] = *(const float2*)&baseBb[r * H1 + k0 + kp];
        }
        __syncthreads();

#pragma unroll 2
        for (int kk = 0; kk < 50; ++kk) {
            float x1 = fmaxf(hA1[kk] + hB1[kk], 0.f);
            float x2 = fmaxf(hB2[kk] + hA2[kk], 0.f);
            ull X1 = pack2(x1);
            ull X2 = pack2(x2);
            const float* wr = W2s + kk * 104 + jbase;
#pragma unroll
            for (int v = 0; v < 13; ++v) {
                longlong2 w = *(const longlong2*)(wr + v * 4);
                ull wlo = (ull)w.x, whi = (ull)w.y;
                acc1[2 * v]     = ffma2(X1, wlo, acc1[2 * v]);
                acc1[2 * v + 1] = ffma2(X1, whi, acc1[2 * v + 1]);
                acc2[2 * v]     = ffma2(X2, wlo, acc2[2 * v]);
                acc2[2 * v + 1] = ffma2(X2, whi, acc2[2 * v + 1]);
            }
        }
    }

    // epilogue: h2 = relu(acc + b2); v = sum h2*W3
    float vp1 = 0.f, vp2 = 0.f;
#pragma unroll
    for (int v = 0; v < 13; ++v) {
        int j = jbase + v * 4;
        float a_, b_;
        a_ = lo32(acc1[2 * v]);     vp1 += fmaxf(a_ + b2s[j + 0], 0.f) * W3s[j + 0];
        b_ = hi32(acc1[2 * v]);     vp1 += fmaxf(b_ + b2s[j + 1], 0.f) * W3s[j + 1];
        a_ = lo32(acc1[2 * v + 1]); vp1 += fmaxf(a_ + b2s[j + 2], 0.f) * W3s[j + 2];
        b_ = hi32(acc1[2 * v + 1]); vp1 += fmaxf(b_ + b2s[j + 3], 0.f) * W3s[j + 3];
        a_ = lo32(acc2[2 * v]);     vp2 += fmaxf(a_ + b2s[j + 0], 0.f) * W3s[j + 0];
        b_ = hi32(acc2[2 * v]);     vp2 += fmaxf(b_ + b2s[j + 1], 0.f) * W3s[j + 1];
        a_ = lo32(acc2[2 * v + 1]); vp2 += fmaxf(a_ + b2s[j + 2], 0.f) * W3s[j + 2];
        b_ = hi32(acc2[2 * v + 1]); vp2 += fmaxf(b_ + b2s[j + 3], 0.f) * W3s[j + 3];
    }
    vp1 += __shfl_xor_sync(0xffffffffu, vp1, 1);
    vp2 += __shfl_xor_sync(0xffffffffu, vp2, 1);
    if (jh == 0) {
        float b3 = b3p[0];
        float v1 = vp1 + b3, v2 = vp2 + b3;
        float s = 0.5f * (v1 + v2);
        float sp = fmaxf(s, 0.f) + log1pf(expf(-fabsf(s)));  // stable softplus
        g_R2[(bi * NA + (a0 + al)) * NB + (b0 + bl)] = sp * sp;
    }
}

// =========================================================================
// K3: per-batch geometry: qbar, M^-1 (3x3 symmetric via adjugate), g[i]=sum Amat_i*|p|^2
// grid (2), block 256 (one thread per anchor). Deterministic tree reductions.
// =========================================================================
__global__ void k3_geo(const float* __restrict__ anch) {
    int bi = blockIdx.x, t = threadIdx.x;
    __shared__ float buf[9 * 256];
    __shared__ float q[3];
    const float* ap = anch + bi * 3 * NB;
    float px = ap[t], py = ap[NB + t], pz = ap[2 * NB + t];
    buf[t] = px; buf[256 + t] = py; buf[512 + t] = pz;
    __syncthreads();
    for (int s = 128; s; s >>= 1) {
        if (t < s)
            for (int cc = 0; cc < 3; ++cc) buf[cc * 256 + t] += buf[cc * 256 + t + s];
        __syncthreads();
    }
    if (t == 0) { q[0] = buf[0] / NB; q[1] = buf[256] / NB; q[2] = buf[512] / NB; }
    __syncthreads();
    float ax = 2.f * (px - q[0]), ay = 2.f * (py - q[1]), az = 2.f * (pz - q[2]);
    float cv = px * px + py * py + pz * pz;
    buf[t] = ax * ax;          buf[256 + t] = ax * ay;   buf[512 + t] = ax * az;
    buf[768 + t] = ay * ay;    buf[1024 + t] = ay * az;  buf[1280 + t] = az * az;
    buf[1536 + t] = ax * cv;   buf[1792 + t] = ay * cv;  buf[2048 + t] = az * cv;
    __syncthreads();
    for (int s = 128; s; s >>= 1) {
        if (t < s)
            for (int cc = 0; cc < 9; ++cc) buf[cc * 256 + t] += buf[cc * 256 + t + s];
        __syncthreads();
    }
    if (t == 0) {
        float m00 = buf[0], m01 = buf[256], m02 = buf[512];
        float m11 = buf[768], m12 = buf[1024], m22 = buf[1280];
        float det = m00 * (m11 * m22 - m12 * m12) - m01 * (m01 * m22 - m12 * m02)
                  + m02 * (m01 * m12 - m11 * m02);
        float inv = 1.f / det;
        float* geo = g_geo + bi * 16;
        geo[0] = (m11 * m22 - m12 * m12) * inv;
        geo[1] = (m02 * m12 - m01 * m22) * inv;
        geo[2] = (m01 * m12 - m02 * m11) * inv;
        geo[3] = (m00 * m22 - m02 * m02) * inv;
        geo[4] = (m02 * m01 - m00 * m12) * inv;
        geo[5] = (m00 * m11 - m01 * m01) * inv;
        geo[6] = buf[1536]; geo[7] = buf[1792]; geo[8] = buf[2048];
        geo[9] = q[0]; geo[10] = q[1]; geo[11] = q[2];
    }
}

// =========================================================================
// K4: flow.  rhs[a,i] = g[i] - sum_b Amat[b,i]*R2[a,b]; pred = Minv*rhs; flow = pred - P_A
// grid (256 a, 2 bi), block 64.
// =========================================================================
__global__ void k4_flow(const float* __restrict__ anch, const float* __restrict__ actp,
                        float* __restrict__ out) {
    int a = blockIdx.x, bi = blockIdx.y, t = threadIdx.x;
    __shared__ float sx[64], sy[64], sz[64];
    const float* geo = g_geo + bi * 16;
    float q0 = geo[9], q1 = geo[10], q2 = geo[11];
    const float* ap = anch + bi * 3 * NB;
    const float* r2row = g_R2 + (bi * NA + a) * NB;
    float s0 = 0.f, s1 = 0.f, s2 = 0.f;
    for (int b = t; b < NB; b += 64) {
        float r2 = r2row[b];
        s0 += 2.f * (ap[b] - q0) * r2;
        s1 += 2.f * (ap[NB + b] - q1) * r2;
        s2 += 2.f * (ap[2 * NB + b] - q2) * r2;
    }
    sx[t] = s0; sy[t] = s1; sz[t] = s2;
    __syncthreads();
    for (int s = 32; s; s >>= 1) {
        if (t < s) { sx[t] += sx[t + s]; sy[t] += sy[t + s]; sz[t] += sz[t + s]; }
        __syncthreads();
    }
    if (t == 0) {
        float r0 = geo[6] - sx[0], r1 = geo[7] - sy[0], r2_ = geo[8] - sz[0];
        float p0 = geo[0] * r0 + geo[1] * r1 + geo[2] * r2_;
        float p1 = geo[1] * r0 + geo[3] * r1 + geo[4] * r2_;
        float p2 = geo[2] * r0 + geo[4] * r1 + geo[5] * r2_;
        const float* app = actp + bi * 3 * NA;
        out[bi * 4 * NA + 0 * NA + a] = p0 - app[a];
        out[bi * 4 * NA + 1 * NA + a] = p1 - app[NA + a];
        out[bi * 4 * NA + 2 * NA + a] = p2 - app[2 * NA + a];
    }
}

// =========================================================================
// K5: pointnet layer0 (512 -> 64). grid (64 o, 2 bi), block 256 (n).
// =========================================================================
__global__ void k5_pn0(const float* __restrict__ actE, const float* __restrict__ W0,
                       const float* __restrict__ b0) {
    int o = blockIdx.x, bi = blockIdx.y, n = threadIdx.x;
    const float* x = actE + bi * EDIM * NA;
    const float* w = W0 + o * EDIM;
    float acc = b0[o];
#pragma unroll 8
    for (int i = 0; i < EDIM; ++i) acc = fmaf(w[i], x[i * NA + n], acc);
    g_y1[(bi * 64 + o) * NA + n] = fmaxf(acc, 0.f);
}

// =========================================================================
// K6: pointnet layers 1..4 + head, fused per n-tile of 8. grid (32 ntile, 2 bi), 256 thr.
// =========================================================================
__global__ void k6_pn(const float* __restrict__ W1, const float* __restrict__ b1,
                      const float* __restrict__ W2, const float* __restrict__ b2,
                      const float* __restrict__ W3, const float* __restrict__ b3,
                      const float* __restrict__ W4, const float* __restrict__ b4,
                      const float* __restrict__ hW, float* __restrict__ out) {
    int bi = blockIdx.y, n0 = blockIdx.x * 8;
    int t = threadIdx.x, nn = t & 7, og = t >> 3;
    __shared__ float ya[64 * 8];
    __shared__ float yb[64 * 8];
    __shared__ float yc[128 * 8];
    __shared__ float part[32 * 8];

    for (int f = t; f < 512; f += 256) {
        int i = f >> 3, nn2 = f & 7;
        ya[f] = g_y1[(bi * 64 + i) * NA + n0 + nn2];
    }
    __syncthreads();
    // L1: ya(64) -> yb(64)
    for (int o = og; o < 64; o += 32) {
        float acc = b1[o];
        for (int i = 0; i < 64; ++i) acc = fmaf(W1[o * 64 + i], ya[i * 8 + nn], acc);
        yb[o * 8 + nn] = fmaxf(acc, 0.f);
    }
    __syncthreads();
    // L2: yb(64) -> ya(64)
    for (int o = og; o < 64; o += 32) {
        float acc = b2[o];
        for (int i = 0; i < 64; ++i) acc = fmaf(W2[o * 64 + i], yb[i * 8 + nn], acc);
        ya[o * 8 + nn] = fmaxf(acc, 0.f);
    }
    __syncthreads();
    // L3: ya(64) -> yc(128)
    for (int o = og; o < 128; o += 32) {
        float acc = b3[o];
        for (int i = 0; i < 64; ++i) acc = fmaf(W3[o * 64 + i], ya[i * 8 + nn], acc);
        yc[o * 8 + nn] = fmaxf(acc, 0.f);
    }
    __syncthreads();
    // L4 (128 -> 512) + head fused
    float wp = 0.f;
    for (int o = og; o < 512; o += 32) {
        float acc = b4[o];
        for (int i = 0; i < 128; ++i) acc = fmaf(W4[o * 128 + i], yc[i * 8 + nn], acc);
        wp = fmaf(hW[o], fmaxf(acc, 0.f), wp);
    }
    part[og * 8 + nn] = wp;
    __syncthreads();
    for (int s = 16; s; s >>= 1) {
        if (og < s) part[og * 8 + nn] += part[(og + s) * 8 + nn];
        __syncthreads();
    }
    if (og == 0) out[bi * 4 * NA + 3 * NA + n0 + nn] = part[nn];
}

// =========================================================================
extern "C" void kernel_launch(void* const* d_in, const int* in_sizes, int n_in,
                              void* d_out, int out_size) {
    const float* actE  = (const float*)d_in[0];   // (2,512,256)
    const float* anchE = (const float*)d_in[1];   // (2,512,256)
    const float* actP  = (const float*)d_in[2];   // (2,3,256)
    const float* anchP = (const float*)d_in[3];   // (2,3,256)
    const float* W1    = (const float*)d_in[4];   // (1024,300)
    const float* b1    = (const float*)d_in[5];   // (300)
    const float* W2    = (const float*)d_in[6];   // (300,100)
    const float* b2    = (const float*)d_in[7];   // (100)
    const float* W3    = (const float*)d_in[8];   // (100,1)
    const float* b3    = (const float*)d_in[9];   // (1)
    const float* pnW0  = (const float*)d_in[10];  // (64,512)
    const float* pnb0  = (const float*)d_in[11];
    const float* pnW1  = (const float*)d_in[12];  // (64,64)
    const float* pnb1  = (const float*)d_in[13];
    const float* pnW2  = (const float*)d_in[14];  // (64,64)
    const float* pnb2  = (const float*)d_in[15];
    const float* pnW3  = (const float*)d_in[16];  // (128,64)
    const float* pnb3  = (const float*)d_in[17];
    const float* pnW4  = (const float*)d_in[18];  // (512,128)
    const float* pnb4  = (const float*)d_in[19];
    const float* headW = (const float*)d_in[20];  // (1,512)
    float* out = (float*)d_out;

    k1_h<<<dim3(5, 4, 8), dim3(16, 16)>>>(actE, anchE, W1, b1);
    k5_pn0<<<dim3(64, 2), 256>>>(actE, pnW0, pnb0);
    k2_pair<<<dim3(32, 16, 2), 256>>>(W2, b2, W3, b3);
    k3_geo<<<2, 256>>>(anchP);
    k6_pn<<<dim3(32, 2), 256>>>(pnW1, pnb1, pnW2, pnb2, pnW3, pnb3, pnW4, pnb4, headW, out);
    k4_flow<<<dim3(256, 2), 64>>>(anchP, actP, out);
}

// round 4
// speedup vs baseline: 1.8514x; 1.8514x over previous
#include <cuda_runtime.h>
#include <cuda_bf16.h>
#include <cstdint>

// Problem constants
#define BATCH 2
#define NA 256
#define NB 256
#define EDIM 512
#define H1 300
#define H2 100

// ---------------- scratch (device globals; no allocation) ----------------
__device__ float g_hAa[BATCH * NA * H1]; // Phi_A @ W1a + b1
__device__ float g_hAb[BATCH * NA * H1]; // Phi_A @ W1b
__device__ float g_hBa[BATCH * NB * H1]; // Phi_B @ W1a + b1
__device__ float g_hBb[BATCH * NB * H1]; // Phi_B @ W1b
__device__ float g_R2[BATCH * NA * NB];  // R_est^2
__device__ float g_geo[BATCH * 16];
__device__ float g_y1[BATCH * 64 * NA];
// W2 hi/lo bf16 images, [k 0..319][n 0..103] linear (pitch 104), zero padded.
__device__ __nv_bfloat16 g_Wh[320 * 104];
__device__ __nv_bfloat16 g_Wl[320 * 104];

// ---------------- helpers (baseline PTX only; no 'a'-suffix features) ----
__device__ __forceinline__ uint32_t smem_u32(const void* p) {
    uint32_t a;
    asm("{ .reg .u64 t; cvta.to.shared.u64 t, %1; cvt.u32.u64 %0, t; }" : "=r"(a) : "l"(p));
    return a;
}
__device__ __forceinline__ void ldsm_x4(uint32_t addr, uint32_t& r0, uint32_t& r1,
                                        uint32_t& r2, uint32_t& r3) {
    asm volatile("ldmatrix.sync.aligned.m8n8.x4.shared.b16 {%0,%1,%2,%3}, [%4];"
                 : "=r"(r0), "=r"(r1), "=r"(r2), "=r"(r3) : "r"(addr));
}
__device__ __forceinline__ void ldsm_x2t(uint32_t addr, uint32_t& r0, uint32_t& r1) {
    asm volatile("ldmatrix.sync.aligned.m8n8.x2.trans.shared.b16 {%0,%1}, [%2];"
                 : "=r"(r0), "=r"(r1) : "r"(addr));
}
__device__ __forceinline__ void mma16816(float* c, const uint32_t* a, const uint32_t* b) {
    asm volatile("mma.sync.aligned.m16n8k16.row.col.f32.bf16.bf16.f32 "
                 "{%0,%1,%2,%3}, {%4,%5,%6,%7}, {%8,%9}, {%0,%1,%2,%3};"
                 : "+f"(c[0]), "+f"(c[1]), "+f"(c[2]), "+f"(c[3])
                 : "r"(a[0]), "r"(a[1]), "r"(a[2]), "r"(a[3]), "r"(b[0]), "r"(b[1]));
}

// smem layout for k2 (byte offsets)
#define XPITCH_B 144           // 72 bf16 per row -> conflict-free ldmatrix (144 % 128 = 16)
#define WPITCH_B 208           // 104 bf16 per row (208 % 128 = 80, 8-row distinct banks)
#define SM_WH    0             // 320*208 = 66560
#define SM_WL    66560         // 66560
#define SM_X     133120        // [side][hi/lo] 4 arrays of 128*144 = 18432 -> 73728
#define SM_EXCH  206848        // 128 floats
#define SM_B2    207360        // 104 floats (pad 512)
#define SM_W3    207872        // 104 floats (pad 512)
#define SM_TOTAL 208384

// =========================================================================
// K0: W2 -> hi/lo bf16 images [320][104], zero padded (k>=300, n>=100).
// =========================================================================
__global__ void k0_wprep(const float* __restrict__ W2) {
    int idx = blockIdx.x * 256 + threadIdx.x;
    if (idx >= 320 * 104) return;
    int k = idx / 104, n = idx % 104;
    float w = (k < H1 && n < H2) ? W2[k * H2 + n] : 0.f;
    __nv_bfloat16 hi = __float2bfloat16(w);
    __nv_bfloat16 lo = __float2bfloat16(w - __bfloat162float(hi));
    g_Wh[idx] = hi;
    g_Wl[idx] = lo;
}

// =========================================================================
// K1: h matrices (fp32 SIMT GEMM) — validated in R1.
// =========================================================================
__global__ void k1_h(const float* __restrict__ actE, const float* __restrict__ anchE,
                     const float* __restrict__ W1, const float* __restrict__ b1) {
    int bi   = blockIdx.z & 1;
    int src  = (blockIdx.z >> 1) & 1;
    int half = blockIdx.z >> 2;
    const float* emb = (src ? anchE : actE) + bi * EDIM * NA;
    float* outp = (half == 0 ? (src ? g_hBa : g_hAa) : (src ? g_hBb : g_hAb)) + bi * NA * H1;

    int n0 = blockIdx.y * 64;
    int j0 = blockIdx.x * 64;
    int tx = threadIdx.x, ty = threadIdx.y;
    int tid = ty * 16 + tx;

    __shared__ float As[16 * 64];
    __shared__ float Bs[16 * 64];

    float acc[4][4];
#pragma unroll
    for (int i = 0; i < 4; ++i)
#pragma unroll
        for (int j = 0; j < 4; ++j) acc[i][j] = 0.f;

    int wbase = half * 512;
    int lkk = tid / 16;
    int l4  = (tid % 16) * 4;

    for (int k0 = 0; k0 < EDIM; k0 += 16) {
        __syncthreads();
        *(float4*)&As[lkk * 64 + l4] = *(const float4*)&emb[(k0 + lkk) * NA + n0 + l4];
        {
            int jg = j0 + l4;
            float4 bv = make_float4(0.f, 0.f, 0.f, 0.f);
            if (jg < H1) bv = *(const float4*)&W1[(wbase + k0 + lkk) * H1 + jg];
            *(float4*)&Bs[lkk * 64 + l4] = bv;
        }
        __syncthreads();
#pragma unroll
        for (int kk = 0; kk < 16; ++kk) {
            float4 a4 = *(const float4*)&As[kk * 64 + ty * 4];
            float4 b4 = *(const float4*)&Bs[kk * 64 + tx * 4];
            float av[4] = {a4.x, a4.y, a4.z, a4.w};
            float bv[4] = {b4.x, b4.y, b4.z, b4.w};
#pragma unroll
            for (int i = 0; i < 4; ++i)
#pragma unroll
                for (int j = 0; j < 4; ++j) acc[i][j] = fmaf(av[i], bv[j], acc[i][j]);
        }
    }
#pragma unroll
    for (int i = 0; i < 4; ++i) {
        int n = n0 + ty * 4 + i;
#pragma unroll
        for (int j = 0; j < 4; ++j) {
            int jg = j0 + tx * 4 + j;
            if (jg < H1) {
                float v = acc[i][j];
                if (half == 0) v += b1[jg];
                outp[n * H1 + jg] = v;
            }
        }
    }
}

// =========================================================================
// K2: PERSISTENT pair-MLP GEMM on tensor cores via mma.sync (bf16 split x3).
// grid 148, 256 threads. Tile = 128 pairs (16a x 8b) x 2 sides = 256 M rows.
// Warps 0-3: side0 rows (wid&3)*32..+31; warps 4-7: side1. acc fp32 in regs.
// Full W2 hi/lo image resident in smem; X built per 64-k chunk.
// =========================================================================
__global__ void __launch_bounds__(256, 1) k2_hmma(const float* __restrict__ b2,
                                                  const float* __restrict__ W3,
                                                  const float* __restrict__ b3p) {
    extern __shared__ char smem[];
    const uint32_t sbase = smem_u32(smem);
    const int tid = threadIdx.x;
    const int wid = tid >> 5;
    const int lane = tid & 31;

    // load constants
    if (tid < 104) {
        *(float*)(smem + SM_B2 + tid * 4) = (tid < H2) ? b2[tid] : 0.f;
        *(float*)(smem + SM_W3 + tid * 4) = (tid < H2) ? W3[tid] : 0.f;
    }
    // W images -> smem (once per CTA): 4160 uint4 each
    {
        uint4* dh = (uint4*)(smem + SM_WH);
        uint4* dl = (uint4*)(smem + SM_WL);
        const uint4* sh = (const uint4*)g_Wh;
        const uint4* sl = (const uint4*)g_Wl;
        for (int i = tid; i < 4160; i += 256) { dh[i] = sh[i]; dl[i] = sl[i]; }
    }
    __syncthreads();

    const float b3 = b3p[0];
    const float* b2s = (const float*)(smem + SM_B2);
    const float* W3s = (const float*)(smem + SM_W3);
    float* exch = (float*)(smem + SM_EXCH);

    // per-warp geometry
    const int side = wid >> 2;
    const int mbase = (wid & 3) * 32;
    const uint32_t xbh = sbase + SM_X + side * 36864;
    const uint32_t xbl = xbh + 18432;
    const int lrow = (lane & 7) + ((lane >> 3) & 1) * 8;       // 0..15
    const uint32_t lkoff = ((lane >> 4) & 1) * 16;             // +8 bf16 cols (bytes)
    const int blane = lane & 15;                               // B ldmatrix row lane

    // X-build thread geometry
    const int br = tid >> 1;            // row 0..127
    const int bkh = (tid & 1) * 32;     // k offset within chunk
    const int bal = br >> 3, bbl = br & 7;

    for (int t = blockIdx.x; t < 1024; t += 148) {
        const int bi = t >> 9;
        const int rem = t & 511;
        const int a0 = (rem >> 5) << 4;
        const int b0 = (rem & 31) << 3;

        const float* srcA0 = g_hAa + (bi * NA + a0) * H1;
        const float* srcB0 = g_hBb + (bi * NB + b0) * H1;
        const float* srcA1 = g_hAb + (bi * NA + a0) * H1;
        const float* srcB1 = g_hBa + (bi * NB + b0) * H1;

        float acc[2][13][4];
#pragma unroll
        for (int mt = 0; mt < 2; ++mt)
#pragma unroll
            for (int n = 0; n < 13; ++n)
#pragma unroll
                for (int q = 0; q < 4; ++q) acc[mt][n][q] = 0.f;

        for (int c = 0; c < 5; ++c) {
            __syncthreads();  // X free (prev chunk's mma done by all warps)
            // ---- build X chunk: rows 0..127, k = c*64 + [0,64), both sides ----
#pragma unroll 1
            for (int s = 0; s < 2; ++s) {
                const float* rowA = (s ? srcA1 : srcA0) + bal * H1;
                const float* rowB = (s ? srcB1 : srcB0) + bbl * H1;
                char* xh = smem + SM_X + s * 36864;
                char* xl = xh + 18432;
#pragma unroll
                for (int i = 0; i < 16; ++i) {
                    int k = c * 64 + bkh + 2 * i;
                    float x0 = 0.f, x1 = 0.f;
                    if (k < H1) {
                        float2 av = *(const float2*)(rowA + k);
                        float2 bv = *(const float2*)(rowB + k);
                        x0 = fmaxf(av.x + bv.x, 0.f);
                        x1 = fmaxf(av.y + bv.y, 0.f);
                    }
                    __nv_bfloat162 hi = __float22bfloat162_rn(make_float2(x0, x1));
                    float2 hf = __bfloat1622float2(hi);
                    __nv_bfloat162 lo = __float22bfloat162_rn(make_float2(x0 - hf.x, x1 - hf.y));
                    uint32_t off = br * XPITCH_B + (bkh + 2 * i) * 2;
                    *(uint32_t*)(xh + off) = *(uint32_t*)&hi;
                    *(uint32_t*)(xl + off) = *(uint32_t*)&lo;
                }
            }
            __syncthreads();
            // ---- 4 k16-steps of MMA ----
#pragma unroll 1
            for (int ks = 0; ks < 4; ++ks) {
                uint32_t ah0[4], ah1[4], al0[4], al1[4];
                uint32_t aoff = (uint32_t)(mbase + lrow) * XPITCH_B + ks * 32 + lkoff;
                ldsm_x4(xbh + aoff, ah0[0], ah0[1], ah0[2], ah0[3]);
                ldsm_x4(xbh + aoff + 16 * XPITCH_B, ah1[0], ah1[1], ah1[2], ah1[3]);
                ldsm_x4(xbl + aoff, al0[0], al0[1], al0[2], al0[3]);
                ldsm_x4(xbl + aoff + 16 * XPITCH_B, al1[0], al1[1], al1[2], al1[3]);
                uint32_t wrow = (uint32_t)(c * 64 + ks * 16 + blane) * WPITCH_B;
#pragma unroll
                for (int n = 0; n < 13; ++n) {
                    uint32_t bh[2], bl[2];
                    ldsm_x2t(sbase + SM_WH + wrow + n * 16, bh[0], bh[1]);
                    ldsm_x2t(sbase + SM_WL + wrow + n * 16, bl[0], bl[1]);
                    mma16816(acc[0][n], ah0, bh);
                    mma16816(acc[0][n], al0, bh);
                    mma16816(acc[0][n], ah0, bl);
                    mma16816(acc[1][n], ah1, bh);
                    mma16816(acc[1][n], al1, bh);
                    mma16816(acc[1][n], ah1, bl);
                }
            }
        }
        // ---- epilogue: vp[row] = sum_j relu(D+b2)*W3 ----
        const int g = lane >> 2;
        const int tq = lane & 3;
        float vs[2][2]; // [mt][row-half]
#pragma unroll
        for (int mt = 0; mt < 2; ++mt) {
            float s0 = 0.f, s1 = 0.f;
#pragma unroll
            for (int n = 0; n < 13; ++n) {
                int j0 = n * 8 + tq * 2;
                float w30 = W3s[j0], w31 = W3s[j0 + 1];
                float bb0 = b2s[j0], bb1 = b2s[j0 + 1];
                s0 += fmaxf(acc[mt][n][0] + bb0, 0.f) * w30 + fmaxf(acc[mt][n][1] + bb1, 0.f) * w31;
                s1 += fmaxf(acc[mt][n][2] + bb0, 0.f) * w30 + fmaxf(acc[mt][n][3] + bb1, 0.f) * w31;
            }
            s0 += __shfl_xor_sync(0xffffffffu, s0, 1);
            s0 += __shfl_xor_sync(0xffffffffu, s0, 2);
            s1 += __shfl_xor_sync(0xffffffffu, s1, 1);
            s1 += __shfl_xor_sync(0xffffffffu, s1, 2);
            vs[mt][0] = s0; vs[mt][1] = s1;
        }
        __syncthreads(); // exch reusable
        if (side == 1 && tq == 0) {
#pragma unroll
            for (int mt = 0; mt < 2; ++mt) {
                exch[mbase + mt * 16 + g] = vs[mt][0];
                exch[mbase + mt * 16 + g + 8] = vs[mt][1];
            }
        }
        __syncthreads();
        if (side == 0 && tq == 0) {
#pragma unroll
            for (int mt = 0; mt < 2; ++mt)
#pragma unroll
                for (int h = 0; h < 2; ++h) {
                    int p = mbase + mt * 16 + g + h * 8;
                    float s = 0.5f * (vs[mt][h] + exch[p]) + b3;
                    float sp = fmaxf(s, 0.f) + log1pf(expf(-fabsf(s)));
                    int al = p >> 3, bl = p & 7;
                    g_R2[(bi * NA + a0 + al) * NB + b0 + bl] = sp * sp;
                }
        }
        __syncthreads(); // protect exch / X before next tile
    }
}

// =========================================================================
// K3: per-batch geometry (validated R1)
// =========================================================================
__global__ void k3_geo(const float* __restrict__ anch) {
    int bi = blockIdx.x, t = threadIdx.x;
    __shared__ float buf[9 * 256];
    __shared__ float q[3];
    const float* ap = anch + bi * 3 * NB;
    float px = ap[t], py = ap[NB + t], pz = ap[2 * NB + t];
    buf[t] = px; buf[256 + t] = py; buf[512 + t] = pz;
    __syncthreads();
    for (int s = 128; s; s >>= 1) {
        if (t < s)
            for (int cc = 0; cc < 3; ++cc) buf[cc * 256 + t] += buf[cc * 256 + t + s];
        __syncthreads();
    }
    if (t == 0) { q[0] = buf[0] / NB; q[1] = buf[256] / NB; q[2] = buf[512] / NB; }
    __syncthreads();
    float ax = 2.f * (px - q[0]), ay = 2.f * (py - q[1]), az = 2.f * (pz - q[2]);
    float cv = px * px + py * py + pz * pz;
    buf[t] = ax * ax;          buf[256 + t] = ax * ay;   buf[512 + t] = ax * az;
    buf[768 + t] = ay * ay;    buf[1024 + t] = ay * az;  buf[1280 + t] = az * az;
    buf[1536 + t] = ax * cv;   buf[1792 + t] = ay * cv;  buf[2048 + t] = az * cv;
    __syncthreads();
    for (int s = 128; s; s >>= 1) {
        if (t < s)
            for (int cc = 0; cc < 9; ++cc) buf[cc * 256 + t] += buf[cc * 256 + t + s];
        __syncthreads();
    }
    if (t == 0) {
        float m00 = buf[0], m01 = buf[256], m02 = buf[512];
        float m11 = buf[768], m12 = buf[1024], m22 = buf[1280];
        float det = m00 * (m11 * m22 - m12 * m12) - m01 * (m01 * m22 - m12 * m02)
                  + m02 * (m01 * m12 - m11 * m02);
        float inv = 1.f / det;
        float* geo = g_geo + bi * 16;
        geo[0] = (m11 * m22 - m12 * m12) * inv;
        geo[1] = (m02 * m12 - m01 * m22) * inv;
        geo[2] = (m01 * m12 - m02 * m11) * inv;
        geo[3] = (m00 * m22 - m02 * m02) * inv;
        geo[4] = (m02 * m01 - m00 * m12) * inv;
        geo[5] = (m00 * m11 - m01 * m01) * inv;
        geo[6] = buf[1536]; geo[7] = buf[1792]; geo[8] = buf[2048];
        geo[9] = q[0]; geo[10] = q[1]; geo[11] = q[2];
    }
}

// =========================================================================
// K4: flow (validated R1)
// =========================================================================
__global__ void k4_flow(const float* __restrict__ anch, const float* __restrict__ actp,
                        float* __restrict__ out) {
    int a = blockIdx.x, bi = blockIdx.y, t = threadIdx.x;
    __shared__ float sx[64], sy[64], sz[64];
    const float* geo = g_geo + bi * 16;
    float q0 = geo[9], q1 = geo[10], q2 = geo[11];
    const float* ap = anch + bi * 3 * NB;
    const float* r2row = g_R2 + (bi * NA + a) * NB;
    float s0 = 0.f, s1 = 0.f, s2 = 0.f;
    for (int b = t; b < NB; b += 64) {
        float r2 = r2row[b];
        s0 += 2.f * (ap[b] - q0) * r2;
        s1 += 2.f * (ap[NB + b] - q1) * r2;
        s2 += 2.f * (ap[2 * NB + b] - q2) * r2;
    }
    sx[t] = s0; sy[t] = s1; sz[t] = s2;
    __syncthreads();
    for (int s = 32; s; s >>= 1) {
        if (t < s) { sx[t] += sx[t + s]; sy[t] += sy[t + s]; sz[t] += sz[t + s]; }
        __syncthreads();
    }
    if (t == 0) {
        float r0 = geo[6] - sx[0], r1 = geo[7] - sy[0], r2_ = geo[8] - sz[0];
        float p0 = geo[0] * r0 + geo[1] * r1 + geo[2] * r2_;
        float p1 = geo[1] * r0 + geo[3] * r1 + geo[4] * r2_;
        float p2 = geo[2] * r0 + geo[4] * r1 + geo[5] * r2_;
        const float* app = actp + bi * 3 * NA;
        out[bi * 4 * NA + 0 * NA + a] = p0 - app[a];
        out[bi * 4 * NA + 1 * NA + a] = p1 - app[NA + a];
        out[bi * 4 * NA + 2 * NA + a] = p2 - app[2 * NA + a];
    }
}

// =========================================================================
// K5: pointnet layer0 (validated R1)
// =========================================================================
__global__ void k5_pn0(const float* __restrict__ actE, const float* __restrict__ W0,
                       const float* __restrict__ b0) {
    int o = blockIdx.x, bi = blockIdx.y, n = threadIdx.x;
    const float* x = actE + bi * EDIM * NA;
    const float* w = W0 + o * EDIM;
    float acc = b0[o];
#pragma unroll 8
    for (int i = 0; i < EDIM; ++i) acc = fmaf(w[i], x[i * NA + n], acc);
    g_y1[(bi * 64 + o) * NA + n] = fmaxf(acc, 0.f);
}

// =========================================================================
// K6: pointnet layers 1..4 + head (validated R1)
// =========================================================================
__global__ void k6_pn(const float* __restrict__ W1, const float* __restrict__ b1,
                      const float* __restrict__ W2, const float* __restrict__ b2,
                      const float* __restrict__ W3, const float* __restrict__ b3,
                      const float* __restrict__ W4, const float* __restrict__ b4,
                      const float* __restrict__ hW, float* __restrict__ out) {
    int bi = blockIdx.y, n0 = blockIdx.x * 8;
    int t = threadIdx.x, nn = t & 7, og = t >> 3;
    __shared__ float ya[64 * 8];
    __shared__ float yb[64 * 8];
    __shared__ float yc[128 * 8];
    __shared__ float part[32 * 8];

    for (int f = t; f < 512; f += 256) {
        int i = f >> 3, nn2 = f & 7;
        ya[f] = g_y1[(bi * 64 + i) * NA + n0 + nn2];
    }
    __syncthreads();
    for (int o = og; o < 64; o += 32) {
        float acc = b1[o];
        for (int i = 0; i < 64; ++i) acc = fmaf(W1[o * 64 + i], ya[i * 8 + nn], acc);
        yb[o * 8 + nn] = fmaxf(acc, 0.f);
    }
    __syncthreads();
    for (int o = og; o < 64; o += 32) {
        float acc = b2[o];
        for (int i = 0; i < 64; ++i) acc = fmaf(W2[o * 64 + i], yb[i * 8 + nn], acc);
        ya[o * 8 + nn] = fmaxf(acc, 0.f);
    }
    __syncthreads();
    for (int o = og; o < 128; o += 32) {
        float acc = b3[o];
        for (int i = 0; i < 64; ++i) acc = fmaf(W3[o * 64 + i], ya[i * 8 + nn], acc);
        yc[o * 8 + nn] = fmaxf(acc, 0.f);
    }
    __syncthreads();
    float wp = 0.f;
    for (int o = og; o < 512; o += 32) {
        float acc = b4[o];
        for (int i = 0; i < 128; ++i) acc = fmaf(W4[o * 128 + i], yc[i * 8 + nn], acc);
        wp = fmaf(hW[o], fmaxf(acc, 0.f), wp);
    }
    part[og * 8 + nn] = wp;
    __syncthreads();
    for (int s = 16; s; s >>= 1) {
        if (og < s) part[og * 8 + nn] += part[(og + s) * 8 + nn];
        __syncthreads();
    }
    if (og == 0) out[bi * 4 * NA + 3 * NA + n0 + nn] = part[nn];
}

// =========================================================================
extern "C" void kernel_launch(void* const* d_in, const int* in_sizes, int n_in,
                              void* d_out, int out_size) {
    const float* actE  = (const float*)d_in[0];
    const float* anchE = (const float*)d_in[1];
    const float* actP  = (const float*)d_in[2];
    const float* anchP = (const float*)d_in[3];
    const float* W1    = (const float*)d_in[4];
    const float* b1    = (const float*)d_in[5];
    const float* W2    = (const float*)d_in[6];
    const float* b2    = (const float*)d_in[7];
    const float* W3    = (const float*)d_in[8];
    const float* b3    = (const float*)d_in[9];
    const float* pnW0  = (const float*)d_in[10];
    const float* pnb0  = (const float*)d_in[11];
    const float* pnW1  = (const float*)d_in[12];
    const float* pnb1  = (const float*)d_in[13];
    const float* pnW2  = (const float*)d_in[14];
    const float* pnb2  = (const float*)d_in[15];
    const float* pnW3  = (const float*)d_in[16];
    const float* pnb3  = (const float*)d_in[17];
    const float* pnW4  = (const float*)d_in[18];
    const float* pnb4  = (const float*)d_in[19];
    const float* headW = (const float*)d_in[20];
    float* out = (float*)d_out;

    cudaFuncSetAttribute(k2_hmma, cudaFuncAttributeMaxDynamicSharedMemorySize, SM_TOTAL);

    k0_wprep<<<131, 256>>>(W2);
    k1_h<<<dim3(5, 4, 8), dim3(16, 16)>>>(actE, anchE, W1, b1);
    k5_pn0<<<dim3(64, 2), 256>>>(actE, pnW0, pnb0);
    k2_hmma<<<148, 256, SM_TOTAL>>>(b2, W3, b3);
    k3_geo<<<2, 256>>>(anchP);
    k6_pn<<<dim3(32, 2), 256>>>(pnW1, pnb1, pnW2, pnb2, pnW3, pnb3, pnW4, pnb4, headW, out);
    k4_flow<<<dim3(256, 2), 64>>>(anchP, actP, out);
}

// round 7
// speedup vs baseline: 2.6109x; 1.4102x over previous
#include <cuda_runtime.h>
#include <cuda_bf16.h>
#include <cstdint>

// Problem constants
#define BATCH 2
#define NA 256
#define NB 256
#define EDIM 512
#define H1 300
#define H2 100

// ---------------- scratch (device globals; no allocation) ----------------
__device__ float g_hAa[BATCH * NA * H1]; // Phi_A @ W1a + b1
__device__ float g_hAb[BATCH * NA * H1]; // Phi_A @ W1b
__device__ float g_hBa[BATCH * NB * H1]; // Phi_B @ W1a + b1
__device__ float g_hBb[BATCH * NB * H1]; // Phi_B @ W1b
__device__ float g_R2[BATCH * NA * NB];  // R_est^2
__device__ float g_geo[BATCH * 16];
__device__ float g_y1[BATCH * 64 * NA];
// W2 hi/lo bf16 images: [k 0..319][n 0..119], pitch 240 B. hi at 0, lo at 76800.
__device__ uint4 g_Wimg[9600]; // 153600 bytes

// ---------------- helpers (baseline PTX only) ----------------------------
__device__ __forceinline__ uint32_t smem_u32(const void* p) {
    uint32_t a;
    asm("{ .reg .u64 t; cvta.to.shared.u64 t, %1; cvt.u32.u64 %0, t; }" : "=r"(a) : "l"(p));
    return a;
}
__device__ __forceinline__ void ldsm_x2t(uint32_t addr, uint32_t& r0, uint32_t& r1) {
    asm volatile("ldmatrix.sync.aligned.m8n8.x2.trans.shared.b16 {%0,%1}, [%2];"
                 : "=r"(r0), "=r"(r1) : "r"(addr));
}
__device__ __forceinline__ void mma16816(float* c, const uint32_t* a, uint32_t b0, uint32_t b1) {
    asm volatile("mma.sync.aligned.m16n8k16.row.col.f32.bf16.bf16.f32 "
                 "{%0,%1,%2,%3}, {%4,%5,%6,%7}, {%8,%9}, {%0,%1,%2,%3};"
                 : "+f"(c[0]), "+f"(c[1]), "+f"(c[2]), "+f"(c[3])
                 : "r"(a[0]), "r"(a[1]), "r"(a[2]), "r"(a[3]), "r"(b0), "r"(b1));
}
__device__ __forceinline__ uint32_t cvt_bf2(float x0, float x1) {
    __nv_bfloat162 h = __float22bfloat162_rn(make_float2(x0, x1));
    return *(uint32_t*)&h;
}

// smem layout for k2 (byte offsets; all 16B aligned)
#define WPITCH   240           // 120 bf16 cols per k-row
#define SPITCH   332           // stage pitch in floats (1328 B)
#define SM_WH    0             // 320*240 = 76800
#define SM_WL    76800         // 76800 -> 153600
#define SM_S     153600        // 48*332*4 = 63744 -> 217344
#define SM_B2    217344        // 128 floats -> 217856
#define SM_W3    217856        // 128 floats -> 218368
#define SM_VACC  218368        // 256 floats -> 219392
#define SM_VFIN  219392        // 256 floats -> 220416
#define SM_TOTAL 220416

// =========================================================================
// K0: W2 -> hi/lo bf16 images [320][120], pitch 240B, zero padded.
// =========================================================================
__global__ void k0_wprep(const float* __restrict__ W2) {
    int idx = blockIdx.x * 256 + threadIdx.x;
    if (idx >= 320 * 120) return;
    int k = idx / 120, n = idx % 120;
    float w = (k < H1 && n < H2) ? W2[k * H2 + n] : 0.f;
    __nv_bfloat16 hi = __float2bfloat16(w);
    __nv_bfloat16 lo = __float2bfloat16(w - __bfloat162float(hi));
    __nv_bfloat16* base = (__nv_bfloat16*)g_Wimg;
    base[idx] = hi;
    base[38400 + idx] = lo;
}

// =========================================================================
// K1: h matrices (fp32 SIMT GEMM) — validated.
// =========================================================================
__global__ void k1_h(const float* __restrict__ actE, const float* __restrict__ anchE,
                     const float* __restrict__ W1, const float* __restrict__ b1) {
    int bi   = blockIdx.z & 1;
    int src  = (blockIdx.z >> 1) & 1;
    int half = blockIdx.z >> 2;
    const float* emb = (src ? anchE : actE) + bi * EDIM * NA;
    float* outp = (half == 0 ? (src ? g_hBa : g_hAa) : (src ? g_hBb : g_hAb)) + bi * NA * H1;

    int n0 = blockIdx.y * 64;
    int j0 = blockIdx.x * 64;
    int tx = threadIdx.x, ty = threadIdx.y;
    int tid = ty * 16 + tx;

    __shared__ float As[16 * 64];
    __shared__ float Bs[16 * 64];

    float acc[4][4];
#pragma unroll
    for (int i = 0; i < 4; ++i)
#pragma unroll
        for (int j = 0; j < 4; ++j) acc[i][j] = 0.f;

    int wbase = half * 512;
    int lkk = tid / 16;
    int l4  = (tid % 16) * 4;

    for (int k0 = 0; k0 < EDIM; k0 += 16) {
        __syncthreads();
        *(float4*)&As[lkk * 64 + l4] = *(const float4*)&emb[(k0 + lkk) * NA + n0 + l4];
        {
            int jg = j0 + l4;
            float4 bv = make_float4(0.f, 0.f, 0.f, 0.f);
            if (jg < H1) bv = *(const float4*)&W1[(wbase + k0 + lkk) * H1 + jg];
            *(float4*)&Bs[lkk * 64 + l4] = bv;
        }
        __syncthreads();
#pragma unroll
        for (int kk = 0; kk < 16; ++kk) {
            float4 a4 = *(const float4*)&As[kk * 64 + ty * 4];
            float4 b4 = *(const float4*)&Bs[kk * 64 + tx * 4];
            float av[4] = {a4.x, a4.y, a4.z, a4.w};
            float bv[4] = {b4.x, b4.y, b4.z, b4.w};
#pragma unroll
            for (int i = 0; i < 4; ++i)
#pragma unroll
                for (int j = 0; j < 4; ++j) acc[i][j] = fmaf(av[i], bv[j], acc[i][j]);
        }
    }
#pragma unroll
    for (int i = 0; i < 4; ++i) {
        int n = n0 + ty * 4 + i;
#pragma unroll
        for (int j = 0; j < 4; ++j) {
            int jg = j0 + tx * 4 + j;
            if (jg < H1) {
                float v = acc[i][j];
                if (half == 0) v += b1[jg];
                outp[n * H1 + jg] = v;
            }
        }
    }
}

// =========================================================================
// K2: PERSISTENT pair-MLP tensor GEMM, fragment-direct A, 2-term bf16 split.
// 512 threads (16 warps): warp = (rg 0..3, side 0..1, h 0..1).
//   rg: 32 M-rows (pairs mbase..mbase+31); side: v1/v2; h: n-column half.
// A frags built in registers from smem-staged fp32 h rows (broadcast LDS).
// B (W2 hi+lo) resident in smem, ldmatrix.x2.trans (R4-validated path).
// =========================================================================
__global__ void __launch_bounds__(512, 1) k2_hmma(const float* __restrict__ b2,
                                                  const float* __restrict__ W3,
                                                  const float* __restrict__ b3p) {
    extern __shared__ char smem[];
    const uint32_t sbase = smem_u32(smem);
    const int tid = threadIdx.x;
    const int wid = tid >> 5;
    const int lane = tid & 31;

    const int rg = wid >> 2;
    const int side = (wid >> 1) & 1;
    const int h = wid & 1;
    const int mbase = rg * 32;
    const int jt0 = h * 7;              // first n-tile
    const int g = lane >> 2;            // 0..7
    const int tq = lane & 3;
    const int c0 = tq * 2;
    const int blane = lane & 15;        // B ldmatrix row lane (x2t, validated R4)

    // constants
    if (tid < 128) {
        *(float*)(smem + SM_B2 + tid * 4) = (tid < H2) ? b2[tid] : 0.f;
        *(float*)(smem + SM_W3 + tid * 4) = (tid < H2) ? W3[tid] : 0.f;
    }
    // W images -> smem once per CTA (153600 B = 9600 uint4)
    {
        uint4* dst = (uint4*)(smem + SM_WH);
        for (int i = tid; i < 9600; i += 512) dst[i] = g_Wimg[i];
    }

    const float b3 = b3p[0];
    const float* b2s = (const float*)(smem + SM_B2);
    const float* W3s = (const float*)(smem + SM_W3);
    float* vacc = (float*)(smem + SM_VACC);
    float* vfin = (float*)(smem + SM_VFIN);
    float* S = (float*)(smem + SM_S);

    // per-warp constant row offsets into stage
    const int sb_off = (32 + side * 8 + g) * SPITCH;   // hB row (lane-dep via g)
    const int sa_base = (side * 16 + rg * 4) * SPITCH; // + (mt*2+half)*SPITCH

#pragma unroll 1
    for (int t = blockIdx.x; t < 1024; t += 148) {
        const int bi = t >> 9;
        const int rem = t & 511;
        const int a0 = (rem >> 5) << 4;
        const int b0 = (rem & 31) << 3;

        // ---- stage 48 h-rows (fp32) into smem ----
        __syncthreads();  // prev tile fully done with stage + vfin
        for (int idx = tid; idx < 48 * 80; idx += 512) {
            int row = idx / 80, i4 = idx % 80;
            const float* src;
            if (row < 16)      src = g_hAa + (bi * NA + a0 + row) * H1;
            else if (row < 32) src = g_hAb + (bi * NA + a0 + row - 16) * H1;
            else if (row < 40) src = g_hBb + (bi * NB + b0 + row - 32) * H1;
            else               src = g_hBa + (bi * NB + b0 + row - 40) * H1;
            float4 v = make_float4(0.f, 0.f, 0.f, 0.f);
            if (i4 < 75) v = *(const float4*)(src + i4 * 4);
            *(float4*)&S[row * SPITCH + i4 * 4] = v;
        }
        __syncthreads();

        float acc[2][7][4];
#pragma unroll
        for (int mt = 0; mt < 2; ++mt)
#pragma unroll
            for (int n = 0; n < 7; ++n)
#pragma unroll
                for (int q = 0; q < 4; ++q) acc[mt][n][q] = 0.f;

#pragma unroll 1
        for (int ks = 0; ks < 20; ++ks) {
            const int kc = ks * 16 + c0;
            // ---- A fragments (registers) ----
            uint32_t afrag[2][4];
            {
                float2 B0 = *(const float2*)&S[sb_off + kc];
                float2 B1 = *(const float2*)&S[sb_off + kc + 8];
#pragma unroll
                for (int mt = 0; mt < 2; ++mt)
#pragma unroll
                    for (int hf = 0; hf < 2; ++hf) {
                        const float* ap = &S[sa_base + (mt * 2 + hf) * SPITCH + kc];
                        float2 A0 = *(const float2*)ap;
                        float2 A1 = *(const float2*)(ap + 8);
                        afrag[mt][hf] = cvt_bf2(fmaxf(A0.x + B0.x, 0.f), fmaxf(A0.y + B0.y, 0.f));
                        afrag[mt][hf + 2] = cvt_bf2(fmaxf(A1.x + B1.x, 0.f), fmaxf(A1.y + B1.y, 0.f));
                    }
            }
            // ---- B fragments + MMA (x2t, one n-tile per load pair) ----
            const uint32_t wa = sbase + SM_WH + (uint32_t)(ks * 16 + blane) * WPITCH
                              + (uint32_t)jt0 * 16;
#pragma unroll
            for (int nt = 0; nt < 7; ++nt) {
                uint32_t bh0, bh1, bl0, bl1;
                ldsm_x2t(wa + nt * 16, bh0, bh1);
                ldsm_x2t(wa + 76800 + nt * 16, bl0, bl1);
                mma16816(acc[0][nt], afrag[0], bh0, bh1);
                mma16816(acc[0][nt], afrag[0], bl0, bl1);
                mma16816(acc[1][nt], afrag[1], bh0, bh1);
                mma16816(acc[1][nt], afrag[1], bl0, bl1);
            }
        }

        // ---- epilogue: per-row dot with W3 over this warp's 56 cols ----
        float vs[2][2];
#pragma unroll
        for (int mt = 0; mt < 2; ++mt) {
            float s0 = 0.f, s1 = 0.f;
#pragma unroll
            for (int nt = 0; nt < 7; ++nt) {
                int j = h * 56 + nt * 8 + c0;
                float w0 = W3s[j], w1 = W3s[j + 1];
                float bb0 = b2s[j], bb1 = b2s[j + 1];
                s0 += fmaxf(acc[mt][nt][0] + bb0, 0.f) * w0 + fmaxf(acc[mt][nt][1] + bb1, 0.f) * w1;
                s1 += fmaxf(acc[mt][nt][2] + bb0, 0.f) * w0 + fmaxf(acc[mt][nt][3] + bb1, 0.f) * w1;
            }
            s0 += __shfl_xor_sync(0xffffffffu, s0, 1);
            s0 += __shfl_xor_sync(0xffffffffu, s0, 2);
            s1 += __shfl_xor_sync(0xffffffffu, s1, 1);
            s1 += __shfl_xor_sync(0xffffffffu, s1, 2);
            vs[mt][0] = s0; vs[mt][1] = s1;
        }
        __syncthreads();
        if (h == 0 && tq == 0) {
#pragma unroll
            for (int mt = 0; mt < 2; ++mt)
#pragma unroll
                for (int hf = 0; hf < 2; ++hf)
                    vacc[side * 128 + mbase + mt * 16 + hf * 8 + g] = vs[mt][hf];
        }
        __syncthreads();
        if (h == 1 && tq == 0) {
#pragma unroll
            for (int mt = 0; mt < 2; ++mt)
#pragma unroll
                for (int hf = 0; hf < 2; ++hf) {
                    int p = mbase + mt * 16 + hf * 8 + g;
                    vfin[side * 128 + p] = vacc[side * 128 + p] + vs[mt][hf];
                }
        }
        __syncthreads();
        if (side == 0 && h == 1 && tq == 0) {
#pragma unroll
            for (int mt = 0; mt < 2; ++mt)
#pragma unroll
                for (int hf = 0; hf < 2; ++hf) {
                    int p = mbase + mt * 16 + hf * 8 + g;
                    float s = 0.5f * (vfin[p] + vfin[128 + p]) + b3;
                    float sp = fmaxf(s, 0.f) + log1pf(expf(-fabsf(s)));
                    g_R2[(bi * NA + a0 + (p >> 3)) * NB + b0 + (p & 7)] = sp * sp;
                }
        }
    }
}

// =========================================================================
// K3: per-batch geometry (validated)
// =========================================================================
__global__ void k3_geo(const float* __restrict__ anch) {
    int bi = blockIdx.x, t = threadIdx.x;
    __shared__ float buf[9 * 256];
    __shared__ float q[3];
    const float* ap = anch + bi * 3 * NB;
    float px = ap[t], py = ap[NB + t], pz = ap[2 * NB + t];
    buf[t] = px; buf[256 + t] = py; buf[512 + t] = pz;
    __syncthreads();
    for (int s = 128; s; s >>= 1) {
        if (t < s)
            for (int cc = 0; cc < 3; ++cc) buf[cc * 256 + t] += buf[cc * 256 + t + s];
        __syncthreads();
    }
    if (t == 0) { q[0] = buf[0] / NB; q[1] = buf[256] / NB; q[2] = buf[512] / NB; }
    __syncthreads();
    float ax = 2.f * (px - q[0]), ay = 2.f * (py - q[1]), az = 2.f * (pz - q[2]);
    float cv = px * px + py * py + pz * pz;
    buf[t] = ax * ax;          buf[256 + t] = ax * ay;   buf[512 + t] = ax * az;
    buf[768 + t] = ay * ay;    buf[1024 + t] = ay * az;  buf[1280 + t] = az * az;
    buf[1536 + t] = ax * cv;   buf[1792 + t] = ay * cv;  buf[2048 + t] = az * cv;
    __syncthreads();
    for (int s = 128; s; s >>= 1) {
        if (t < s)
            for (int cc = 0; cc < 9; ++cc) buf[cc * 256 + t] += buf[cc * 256 + t + s];
        __syncthreads();
    }
    if (t == 0) {
        float m00 = buf[0], m01 = buf[256], m02 = buf[512];
        float m11 = buf[768], m12 = buf[1024], m22 = buf[1280];
        float det = m00 * (m11 * m22 - m12 * m12) - m01 * (m01 * m22 - m12 * m02)
                  + m02 * (m01 * m12 - m11 * m02);
        float inv = 1.f / det;
        float* geo = g_geo + bi * 16;
        geo[0] = (m11 * m22 - m12 * m12) * inv;
        geo[1] = (m02 * m12 - m01 * m22) * inv;
        geo[2] = (m01 * m12 - m02 * m11) * inv;
        geo[3] = (m00 * m22 - m02 * m02) * inv;
        geo[4] = (m02 * m01 - m00 * m12) * inv;
        geo[5] = (m00 * m11 - m01 * m01) * inv;
        geo[6] = buf[1536]; geo[7] = buf[1792]; geo[8] = buf[2048];
        geo[9] = q[0]; geo[10] = q[1]; geo[11] = q[2];
    }
}

// =========================================================================
// K4: flow (validated)
// =========================================================================
__global__ void k4_flow(const float* __restrict__ anch, const float* __restrict__ actp,
                        float* __restrict__ out) {
    int a = blockIdx.x, bi = blockIdx.y, t = threadIdx.x;
    __shared__ float sx[64], sy[64], sz[64];
    const float* geo = g_geo + bi * 16;
    float q0 = geo[9], q1 = geo[10], q2 = geo[11];
    const float* ap = anch + bi * 3 * NB;
    const float* r2row = g_R2 + (bi * NA + a) * NB;
    float s0 = 0.f, s1 = 0.f, s2 = 0.f;
    for (int b = t; b < NB; b += 64) {
        float r2 = r2row[b];
        s0 += 2.f * (ap[b] - q0) * r2;
        s1 += 2.f * (ap[NB + b] - q1) * r2;
        s2 += 2.f * (ap[2 * NB + b] - q2) * r2;
    }
    sx[t] = s0; sy[t] = s1; sz[t] = s2;
    __syncthreads();
    for (int s = 32; s; s >>= 1) {
        if (t < s) { sx[t] += sx[t + s]; sy[t] += sy[t + s]; sz[t] += sz[t + s]; }
        __syncthreads();
    }
    if (t == 0) {
        float r0 = geo[6] - sx[0], r1 = geo[7] - sy[0], r2_ = geo[8] - sz[0];
        float p0 = geo[0] * r0 + geo[1] * r1 + geo[2] * r2_;
        float p1 = geo[1] * r0 + geo[3] * r1 + geo[4] * r2_;
        float p2 = geo[2] * r0 + geo[4] * r1 + geo[5] * r2_;
        const float* app = actp + bi * 3 * NA;
        out[bi * 4 * NA + 0 * NA + a] = p0 - app[a];
        out[bi * 4 * NA + 1 * NA + a] = p1 - app[NA + a];
        out[bi * 4 * NA + 2 * NA + a] = p2 - app[2 * NA + a];
    }
}

// =========================================================================
// K5: pointnet layer0 as tiled GEMM. C[o,n] = relu(b0[o] + sum_i W0[o,i]x[i,n])
// grid (4 ntile, 2 bi), block (16,16).
// =========================================================================
__global__ void k5_pn0(const float* __restrict__ actE, const float* __restrict__ W0,
                       const float* __restrict__ b0) {
    int bi = blockIdx.y, n0 = blockIdx.x * 64;
    const float* x = actE + bi * EDIM * NA;
    int tx = threadIdx.x, ty = threadIdx.y;
    int tid = ty * 16 + tx;
    __shared__ float As[16][64]; // [kk][o]
    __shared__ float Bs[16][64]; // [kk][n]
    float acc[4][4];
#pragma unroll
    for (int i = 0; i < 4; ++i)
#pragma unroll
        for (int j = 0; j < 4; ++j) acc[i][j] = 0.f;
    int o_l = tid & 63;
    int k4 = (tid >> 6) * 4;
    int lkk = tid / 16, l4 = (tid % 16) * 4;
    for (int k0 = 0; k0 < EDIM; k0 += 16) {
        __syncthreads();
        float4 w = *(const float4*)&W0[o_l * EDIM + k0 + k4];
        As[k4 + 0][o_l] = w.x; As[k4 + 1][o_l] = w.y;
        As[k4 + 2][o_l] = w.z; As[k4 + 3][o_l] = w.w;
        *(float4*)&Bs[lkk][l4] = *(const float4*)&x[(k0 + lkk) * NA + n0 + l4];
        __syncthreads();
#pragma unroll
        for (int kk = 0; kk < 16; ++kk) {
            float av[4], bv[4];
#pragma unroll
            for (int i = 0; i < 4; ++i) av[i] = As[kk][ty * 4 + i];
#pragma unroll
            for (int j = 0; j < 4; ++j) bv[j] = Bs[kk][tx * 4 + j];
#pragma unroll
            for (int i = 0; i < 4; ++i)
#pragma unroll
                for (int j = 0; j < 4; ++j) acc[i][j] = fmaf(av[i], bv[j], acc[i][j]);
        }
    }
#pragma unroll
    for (int i = 0; i < 4; ++i) {
        int o = ty * 4 + i;
        float bb = b0[o];
#pragma unroll
        for (int j = 0; j < 4; ++j) {
            int n = n0 + tx * 4 + j;
            g_y1[(bi * 64 + o) * NA + n] = fmaxf(acc[i][j] + bb, 0.f);
        }
    }
}

// =========================================================================
// K6: pointnet layers 1..4 + head (ILP-2 accumulators)
// =========================================================================
__global__ void k6_pn(const float* __restrict__ W1, const float* __restrict__ b1,
                      const float* __restrict__ W2, const float* __restrict__ b2,
                      const float* __restrict__ W3, const float* __restrict__ b3,
                      const float* __restrict__ W4, const float* __restrict__ b4,
                      const float* __restrict__ hW, float* __restrict__ out) {
    int bi = blockIdx.y, n0 = blockIdx.x * 8;
    int t = threadIdx.x, nn = t & 7, og = t >> 3;
    __shared__ float ya[64 * 8];
    __shared__ float yb[64 * 8];
    __shared__ float yc[128 * 8];
    __shared__ float part[32 * 8];

    for (int f = t; f < 512; f += 256) {
        int i = f >> 3, nn2 = f & 7;
        ya[f] = g_y1[(bi * 64 + i) * NA + n0 + nn2];
    }
    __syncthreads();
    for (int o = og; o < 64; o += 32) {
        float a0 = b1[o], a1 = 0.f;
        for (int i = 0; i < 64; i += 2) {
            a0 = fmaf(W1[o * 64 + i], ya[i * 8 + nn], a0);
            a1 = fmaf(W1[o * 64 + i + 1], ya[(i + 1) * 8 + nn], a1);
        }
        yb[o * 8 + nn] = fmaxf(a0 + a1, 0.f);
    }
    __syncthreads();
    for (int o = og; o < 64; o += 32) {
        float a0 = b2[o], a1 = 0.f;
        for (int i = 0; i < 64; i += 2) {
            a0 = fmaf(W2[o * 64 + i], yb[i * 8 + nn], a0);
            a1 = fmaf(W2[o * 64 + i + 1], yb[(i + 1) * 8 + nn], a1);
        }
        ya[o * 8 + nn] = fmaxf(a0 + a1, 0.f);
    }
    __syncthreads();
    for (int o = og; o < 128; o += 32) {
        float a0 = b3[o], a1 = 0.f;
        for (int i = 0; i < 64; i += 2) {
            a0 = fmaf(W3[o * 64 + i], ya[i * 8 + nn], a0);
            a1 = fmaf(W3[o * 64 + i + 1], ya[(i + 1) * 8 + nn], a1);
        }
        yc[o * 8 + nn] = fmaxf(a0 + a1, 0.f);
    }
    __syncthreads();
    float wp = 0.f;
    for (int o = og; o < 512; o += 32) {
        float a0 = b4[o], a1 = 0.f;
        for (int i = 0; i < 128; i += 2) {
            a0 = fmaf(W4[o * 128 + i], yc[i * 8 + nn], a0);
            a1 = fmaf(W4[o * 128 + i + 1], yc[(i + 1) * 8 + nn], a1);
        }
        wp = fmaf(hW[o], fmaxf(a0 + a1, 0.f), wp);
    }
    part[og * 8 + nn] = wp;
    __syncthreads();
    for (int s = 16; s; s >>= 1) {
        if (og < s) part[og * 8 + nn] += part[(og + s) * 8 + nn];
        __syncthreads();
    }
    if (og == 0) out[bi * 4 * NA + 3 * NA + n0 + nn] = part[nn];
}

// =========================================================================
extern "C" void kernel_launch(void* const* d_in, const int* in_sizes, int n_in,
                              void* d_out, int out_size) {
    const float* actE  = (const float*)d_in[0];
    const float* anchE = (const float*)d_in[1];
    const float* actP  = (const float*)d_in[2];
    const float* anchP = (const float*)d_in[3];
    const float* W1    = (const float*)d_in[4];
    const float* b1    = (const float*)d_in[5];
    const float* W2    = (const float*)d_in[6];
    const float* b2    = (const float*)d_in[7];
    const float* W3    = (const float*)d_in[8];
    const float* b3    = (const float*)d_in[9];
    const float* pnW0  = (const float*)d_in[10];
    const float* pnb0  = (const float*)d_in[11];
    const float* pnW1  = (const float*)d_in[12];
    const float* pnb1  = (const float*)d_in[13];
    const float* pnW2  = (const float*)d_in[14];
    const float* pnb2  = (const float*)d_in[15];
    const float* pnW3  = (const float*)d_in[16];
    const float* pnb3  = (const float*)d_in[17];
    const float* pnW4  = (const float*)d_in[18];
    const float* pnb4  = (const float*)d_in[19];
    const float* headW = (const float*)d_in[20];
    float* out = (float*)d_out;

    cudaFuncSetAttribute(k2_hmma, cudaFuncAttributeMaxDynamicSharedMemorySize, SM_TOTAL);

    k0_wprep<<<150, 256>>>(W2);
    k1_h<<<dim3(5, 4, 8), dim3(16, 16)>>>(actE, anchE, W1, b1);
    k5_pn0<<<dim3(4, 2), dim3(16, 16)>>>(actE, pnW0, pnb0);
    k2_hmma<<<148, 512, SM_TOTAL>>>(b2, W3, b3);
    k3_geo<<<2, 256>>>(anchP);
    k6_pn<<<dim3(32, 2), 256>>>(pnW1, pnb1, pnW2, pnb2, pnW3, pnb3, pnW4, pnb4, headW, out);
    k4_flow<<<dim3(256, 2), 64>>>(anchP, actP, out);
}

// round 8
// speedup vs baseline: 3.2561x; 1.2472x over previous
#include <cuda_runtime.h>
#include <cuda_fp16.h>
#include <cstdint>

// Problem constants
#define BATCH 2
#define NA 256
#define NB 256
#define EDIM 512
#define H1 300
#define H2 100
#define HP 304   // fp16 row pitch for h matrices (16B aligned: 304*2=608)

// ---------------- scratch (device globals; no allocation) ----------------
__device__ __half g_hAa[BATCH * NA * HP]; // Phi_A @ W1a + b1 (fp16, pitch 304)
__device__ __half g_hAb[BATCH * NA * HP];
__device__ __half g_hBa[BATCH * NB * HP];
__device__ __half g_hBb[BATCH * NB * HP];
__device__ float g_R2[BATCH * NA * NB];   // R_est^2
__device__ float g_geo[BATCH * 16];
__device__ float g_y1[BATCH * 64 * NA];
// W2 fp16 image: [k 0..319][n 0..119], pitch 240 B, zero padded.
__device__ __half g_Wimg[320 * 120];

// ---------------- helpers (baseline PTX only) ----------------------------
__device__ __forceinline__ uint32_t smem_u32(const void* p) {
    uint32_t a;
    asm("{ .reg .u64 t; cvta.to.shared.u64 t, %1; cvt.u32.u64 %0, t; }" : "=r"(a) : "l"(p));
    return a;
}
__device__ __forceinline__ void ldsm_x2t(uint32_t addr, uint32_t& r0, uint32_t& r1) {
    asm volatile("ldmatrix.sync.aligned.m8n8.x2.trans.shared.b16 {%0,%1}, [%2];"
                 : "=r"(r0), "=r"(r1) : "r"(addr));
}
__device__ __forceinline__ void mma16816(float* c, const uint32_t* a, uint32_t b0, uint32_t b1) {
    asm volatile("mma.sync.aligned.m16n8k16.row.col.f32.f16.f16.f32 "
                 "{%0,%1,%2,%3}, {%4,%5,%6,%7}, {%8,%9}, {%0,%1,%2,%3};"
                 : "+f"(c[0]), "+f"(c[1]), "+f"(c[2]), "+f"(c[3])
                 : "r"(a[0]), "r"(a[1]), "r"(a[2]), "r"(a[3]), "r"(b0), "r"(b1));
}

// smem layout for k2 (byte offsets; all 16B aligned)
#define WPITCH   240           // 120 fp16 cols per k-row
#define SPITCH_H 328           // stage pitch in halves (656 B; 656 mod 128 = 16 -> conflict-free)
#define SM_W     0             // 320*240 = 76800
#define SM_S     76800         // 48*656 = 31488 -> 108288
#define SM_B2    108288        // 128 floats -> 108800
#define SM_W3    108800        // 128 floats -> 109312
#define SM_VACC  109312        // 256 floats -> 110336
#define SM_VFIN  110336        // 256 floats -> 111360
#define SM_TOTAL 111360

// =========================================================================
// KP: fused prep. Blocks 0..149: W2 -> fp16 image. Blocks 150..157: pointnet
// layer0 tiled GEMM (k5). Both 256 threads.
// =========================================================================
__global__ void kp_prep(const float* __restrict__ W2,
                        const float* __restrict__ actE, const float* __restrict__ W0,
                        const float* __restrict__ b0) {
    if (blockIdx.x < 150) {
        int idx = blockIdx.x * 256 + threadIdx.x;
        if (idx >= 320 * 120) return;
        int k = idx / 120, n = idx % 120;
        float w = (k < H1 && n < H2) ? W2[k * H2 + n] : 0.f;
        g_Wimg[idx] = __float2half(w);
        return;
    }
    int bl = blockIdx.x - 150;          // 0..7
    int bi = bl >> 2;
    int n0 = (bl & 3) * 64;
    const float* x = actE + bi * EDIM * NA;
    int tid = threadIdx.x;
    int tx = tid & 15, ty = tid >> 4;
    __shared__ float As[16][64]; // [kk][o]
    __shared__ float Bs[16][64]; // [kk][n]
    float acc[4][4];
#pragma unroll
    for (int i = 0; i < 4; ++i)
#pragma unroll
        for (int j = 0; j < 4; ++j) acc[i][j] = 0.f;
    int o_l = tid & 63;
    int k4 = (tid >> 6) * 4;
    int lkk = tid / 16, l4 = (tid % 16) * 4;
    for (int k0 = 0; k0 < EDIM; k0 += 16) {
        __syncthreads();
        float4 w = *(const float4*)&W0[o_l * EDIM + k0 + k4];
        As[k4 + 0][o_l] = w.x; As[k4 + 1][o_l] = w.y;
        As[k4 + 2][o_l] = w.z; As[k4 + 3][o_l] = w.w;
        *(float4*)&Bs[lkk][l4] = *(const float4*)&x[(k0 + lkk) * NA + n0 + l4];
        __syncthreads();
#pragma unroll
        for (int kk = 0; kk < 16; ++kk) {
            float av[4], bv[4];
#pragma unroll
            for (int i = 0; i < 4; ++i) av[i] = As[kk][ty * 4 + i];
#pragma unroll
            for (int j = 0; j < 4; ++j) bv[j] = Bs[kk][tx * 4 + j];
#pragma unroll
            for (int i = 0; i < 4; ++i)
#pragma unroll
                for (int j = 0; j < 4; ++j) acc[i][j] = fmaf(av[i], bv[j], acc[i][j]);
        }
    }
#pragma unroll
    for (int i = 0; i < 4; ++i) {
        int o = ty * 4 + i;
        float bb = b0[o];
#pragma unroll
        for (int j = 0; j < 4; ++j) {
            int n = n0 + tx * 4 + j;
            g_y1[(bi * 64 + o) * NA + n] = fmaxf(acc[i][j] + bb, 0.f);
        }
    }
}

// =========================================================================
// K1: h matrices (fp32 SIMT GEMM) -> fp16 output, pitch 304, zero pad.
// =========================================================================
__global__ void k1_h(const float* __restrict__ actE, const float* __restrict__ anchE,
                     const float* __restrict__ W1, const float* __restrict__ b1) {
    int bi   = blockIdx.z & 1;
    int src  = (blockIdx.z >> 1) & 1;
    int half = blockIdx.z >> 2;
    const float* emb = (src ? anchE : actE) + bi * EDIM * NA;
    __half* outp = (half == 0 ? (src ? g_hBa : g_hAa) : (src ? g_hBb : g_hAb)) + bi * NA * HP;

    int n0 = blockIdx.y * 64;
    int j0 = blockIdx.x * 64;
    int tx = threadIdx.x, ty = threadIdx.y;
    int tid = ty * 16 + tx;

    __shared__ float As[16 * 64];
    __shared__ float Bs[16 * 64];

    float acc[4][4];
#pragma unroll
    for (int i = 0; i < 4; ++i)
#pragma unroll
        for (int j = 0; j < 4; ++j) acc[i][j] = 0.f;

    int wbase = half * 512;
    int lkk = tid / 16;
    int l4  = (tid % 16) * 4;

    for (int k0 = 0; k0 < EDIM; k0 += 16) {
        __syncthreads();
        *(float4*)&As[lkk * 64 + l4] = *(const float4*)&emb[(k0 + lkk) * NA + n0 + l4];
        {
            int jg = j0 + l4;
            float4 bv = make_float4(0.f, 0.f, 0.f, 0.f);
            if (jg < H1) bv = *(const float4*)&W1[(wbase + k0 + lkk) * H1 + jg];
            *(float4*)&Bs[lkk * 64 + l4] = bv;
        }
        __syncthreads();
#pragma unroll
        for (int kk = 0; kk < 16; ++kk) {
            float4 a4 = *(const float4*)&As[kk * 64 + ty * 4];
            float4 b4 = *(const float4*)&Bs[kk * 64 + tx * 4];
            float av[4] = {a4.x, a4.y, a4.z, a4.w};
            float bv[4] = {b4.x, b4.y, b4.z, b4.w};
#pragma unroll
            for (int i = 0; i < 4; ++i)
#pragma unroll
                for (int j = 0; j < 4; ++j) acc[i][j] = fmaf(av[i], bv[j], acc[i][j]);
        }
    }
#pragma unroll
    for (int i = 0; i < 4; ++i) {
        int n = n0 + ty * 4 + i;
#pragma unroll
        for (int j = 0; j < 4; ++j) {
            int jg = j0 + tx * 4 + j;
            if (jg < H1) {
                float v = acc[i][j];
                if (half == 0) v += b1[jg];
                outp[n * HP + jg] = __float2half(v);
            } else if (jg < HP) {
                outp[n * HP + jg] = __float2half(0.f);
            }
        }
    }
}

// =========================================================================
// K2: PERSISTENT pair-MLP tensor GEMM, single-pass fp16.
// 768 threads (24 warps): warp = (rg 0..3, side 0..1, hh 0..2).
//   rg: 32 M-rows (pairs); side: v1/v2; hh: 5 n-tiles (15 total; cols>=100 zero).
// A frags: fp16 staged h rows, HADD2+HMAX2 (no cvt chain). B: ldmatrix.x2.trans.
// =========================================================================
__global__ void __launch_bounds__(768, 1) k2_hmma(const float* __restrict__ b2,
                                                  const float* __restrict__ W3,
                                                  const float* __restrict__ b3p) {
    extern __shared__ char smem[];
    const uint32_t sbase = smem_u32(smem);
    const int tid = threadIdx.x;
    const int wid = tid >> 5;
    const int lane = tid & 31;

    const int rg = wid / 6;
    const int r6 = wid % 6;
    const int side = r6 / 3;
    const int hh = r6 % 3;
    const int mbase = rg * 32;
    const int jt0 = hh * 5;             // first n-tile (of 15)
    const int g = lane >> 2;            // 0..7
    const int tq = lane & 3;
    const int c0 = tq * 2;
    const int blane = lane & 15;        // B ldmatrix row lane

    // constants
    if (tid < 128) {
        *(float*)(smem + SM_B2 + tid * 4) = (tid < H2) ? b2[tid] : 0.f;
        *(float*)(smem + SM_W3 + tid * 4) = (tid < H2) ? W3[tid] : 0.f;
    }
    // W image -> smem once per CTA (76800 B = 4800 uint4)
    {
        uint4* dst = (uint4*)(smem + SM_W);
        const uint4* src = (const uint4*)g_Wimg;
        for (int i = tid; i < 4800; i += 768) dst[i] = src[i];
    }

    const float b3 = b3p[0];
    const float* b2s = (const float*)(smem + SM_B2);
    const float* W3s = (const float*)(smem + SM_W3);
    float* vacc = (float*)(smem + SM_VACC);
    float* vfin = (float*)(smem + SM_VFIN);

    const int srowB = 32 + side * 8 + g;       // staged hB row for this lane
    const int sa_row0 = side * 16 + rg * 4;    // + mt*2+hf
    const __half2 z2 = __float2half2_rn(0.f);

#pragma unroll 1
    for (int t = blockIdx.x; t < 1024; t += 148) {
        const int bi = t >> 9;
        const int rem = t & 511;
        const int a0 = (rem >> 5) << 4;
        const int b0 = (rem & 31) << 3;

        // ---- stage 48 fp16 h-rows into smem ----
        __syncthreads();  // prev tile fully done with stage + vacc/vfin
        for (int idx = tid; idx < 48 * 41; idx += 768) {
            int row = idx / 41, i = idx % 41;
            uint4 v = make_uint4(0u, 0u, 0u, 0u);
            if (i < 38) {
                const uint4* srcp;
                int gr;
                if (row < 16)      { srcp = (const uint4*)g_hAa; gr = bi * NA + a0 + row; }
                else if (row < 32) { srcp = (const uint4*)g_hAb; gr = bi * NA + a0 + row - 16; }
                else if (row < 40) { srcp = (const uint4*)g_hBb; gr = bi * NB + b0 + row - 32; }
                else               { srcp = (const uint4*)g_hBa; gr = bi * NB + b0 + row - 40; }
                v = srcp[gr * 38 + i];
            }
            *(uint4*)(smem + SM_S + row * 656 + i * 16) = v;
        }
        __syncthreads();

        float acc[2][5][4];
#pragma unroll
        for (int mt = 0; mt < 2; ++mt)
#pragma unroll
            for (int n = 0; n < 5; ++n)
#pragma unroll
                for (int q = 0; q < 4; ++q) acc[mt][n][q] = 0.f;

        const __half2* S2 = (const __half2*)(smem + SM_S);

#pragma unroll 1
        for (int ks = 0; ks < 20; ++ks) {
            const int kc = ks * 16 + c0;
            // ---- A fragments: fp16 add+relu, no conversions ----
            __half2 Blo = S2[(srowB * SPITCH_H + kc) >> 1];
            __half2 Bhi = S2[(srowB * SPITCH_H + kc + 8) >> 1];
            uint32_t afrag[2][4];
#pragma unroll
            for (int mt = 0; mt < 2; ++mt)
#pragma unroll
                for (int hf = 0; hf < 2; ++hf) {
                    int srow = sa_row0 + mt * 2 + hf;
                    __half2 Alo = S2[(srow * SPITCH_H + kc) >> 1];
                    __half2 Ahi = S2[(srow * SPITCH_H + kc + 8) >> 1];
                    __half2 x0 = __hmax2(__hadd2(Alo, Blo), z2);
                    __half2 x1 = __hmax2(__hadd2(Ahi, Bhi), z2);
                    afrag[mt][hf] = *(uint32_t*)&x0;
                    afrag[mt][hf + 2] = *(uint32_t*)&x1;
                }
            // ---- B fragments + MMA ----
            const uint32_t wa = sbase + SM_W + (uint32_t)(ks * 16 + blane) * WPITCH
                              + (uint32_t)jt0 * 16;
#pragma unroll
            for (int nt = 0; nt < 5; ++nt) {
                uint32_t br0, br1;
                ldsm_x2t(wa + nt * 16, br0, br1);
                mma16816(acc[0][nt], afrag[0], br0, br1);
                mma16816(acc[1][nt], afrag[1], br0, br1);
            }
        }

        // ---- epilogue: per-row dot with W3 over this warp's 40 cols ----
        float vs[2][2];
#pragma unroll
        for (int mt = 0; mt < 2; ++mt) {
            float s0 = 0.f, s1 = 0.f;
#pragma unroll
            for (int nt = 0; nt < 5; ++nt) {
                int j = (jt0 + nt) * 8 + c0;
                float w0 = W3s[j], w1 = W3s[j + 1];
                float bb0 = b2s[j], bb1 = b2s[j + 1];
                s0 += fmaxf(acc[mt][nt][0] + bb0, 0.f) * w0 + fmaxf(acc[mt][nt][1] + bb1, 0.f) * w1;
                s1 += fmaxf(acc[mt][nt][2] + bb0, 0.f) * w0 + fmaxf(acc[mt][nt][3] + bb1, 0.f) * w1;
            }
            s0 += __shfl_xor_sync(0xffffffffu, s0, 1);
            s0 += __shfl_xor_sync(0xffffffffu, s0, 2);
            s1 += __shfl_xor_sync(0xffffffffu, s1, 1);
            s1 += __shfl_xor_sync(0xffffffffu, s1, 2);
            vs[mt][0] = s0; vs[mt][1] = s1;
        }
        __syncthreads();
        if (hh == 0 && tq == 0) {
#pragma unroll
            for (int mt = 0; mt < 2; ++mt)
#pragma unroll
                for (int hf = 0; hf < 2; ++hf)
                    vacc[side * 128 + mbase + mt * 16 + hf * 8 + g] = vs[mt][hf];
        }
        __syncthreads();
        if (hh == 1 && tq == 0) {
#pragma unroll
            for (int mt = 0; mt < 2; ++mt)
#pragma unroll
                for (int hf = 0; hf < 2; ++hf) {
                    int p = mbase + mt * 16 + hf * 8 + g;
                    vacc[side * 128 + p] += vs[mt][hf];
                }
        }
        __syncthreads();
        float tot[2][2];
        if (hh == 2 && tq == 0) {
#pragma unroll
            for (int mt = 0; mt < 2; ++mt)
#pragma unroll
                for (int hf = 0; hf < 2; ++hf) {
                    int p = mbase + mt * 16 + hf * 8 + g;
                    tot[mt][hf] = vacc[side * 128 + p] + vs[mt][hf];
                    if (side == 1) vfin[p] = tot[mt][hf];
                }
        }
        __syncthreads();
        if (hh == 2 && side == 0 && tq == 0) {
#pragma unroll
            for (int mt = 0; mt < 2; ++mt)
#pragma unroll
                for (int hf = 0; hf < 2; ++hf) {
                    int p = mbase + mt * 16 + hf * 8 + g;
                    float s = 0.5f * (tot[mt][hf] + vfin[p]) + b3;
                    float sp = fmaxf(s, 0.f) + log1pf(expf(-fabsf(s)));
                    g_R2[(bi * NA + a0 + (p >> 3)) * NB + b0 + (p & 7)] = sp * sp;
                }
        }
    }
}

// =========================================================================
// K3: per-batch geometry (validated)
// =========================================================================
__global__ void k3_geo(const float* __restrict__ anch) {
    int bi = blockIdx.x, t = threadIdx.x;
    __shared__ float buf[9 * 256];
    __shared__ float q[3];
    const float* ap = anch + bi * 3 * NB;
    float px = ap[t], py = ap[NB + t], pz = ap[2 * NB + t];
    buf[t] = px; buf[256 + t] = py; buf[512 + t] = pz;
    __syncthreads();
    for (int s = 128; s; s >>= 1) {
        if (t < s)
            for (int cc = 0; cc < 3; ++cc) buf[cc * 256 + t] += buf[cc * 256 + t + s];
        __syncthreads();
    }
    if (t == 0) { q[0] = buf[0] / NB; q[1] = buf[256] / NB; q[2] = buf[512] / NB; }
    __syncthreads();
    float ax = 2.f * (px - q[0]), ay = 2.f * (py - q[1]), az = 2.f * (pz - q[2]);
    float cv = px * px + py * py + pz * pz;
    buf[t] = ax * ax;          buf[256 + t] = ax * ay;   buf[512 + t] = ax * az;
    buf[768 + t] = ay * ay;    buf[1024 + t] = ay * az;  buf[1280 + t] = az * az;
    buf[1536 + t] = ax * cv;   buf[1792 + t] = ay * cv;  buf[2048 + t] = az * cv;
    __syncthreads();
    for (int s = 128; s; s >>= 1) {
        if (t < s)
            for (int cc = 0; cc < 9; ++cc) buf[cc * 256 + t] += buf[cc * 256 + t + s];
        __syncthreads();
    }
    if (t == 0) {
        float m00 = buf[0], m01 = buf[256], m02 = buf[512];
        float m11 = buf[768], m12 = buf[1024], m22 = buf[1280];
        float det = m00 * (m11 * m22 - m12 * m12) - m01 * (m01 * m22 - m12 * m02)
                  + m02 * (m01 * m12 - m11 * m02);
        float inv = 1.f / det;
        float* geo = g_geo + bi * 16;
        geo[0] = (m11 * m22 - m12 * m12) * inv;
        geo[1] = (m02 * m12 - m01 * m22) * inv;
        geo[2] = (m01 * m12 - m02 * m11) * inv;
        geo[3] = (m00 * m22 - m02 * m02) * inv;
        geo[4] = (m02 * m01 - m00 * m12) * inv;
        geo[5] = (m00 * m11 - m01 * m01) * inv;
        geo[6] = buf[1536]; geo[7] = buf[1792]; geo[8] = buf[2048];
        geo[9] = q[0]; geo[10] = q[1]; geo[11] = q[2];
    }
}

// =========================================================================
// K4: flow (validated)
// =========================================================================
__global__ void k4_flow(const float* __restrict__ anch, const float* __restrict__ actp,
                        float* __restrict__ out) {
    int a = blockIdx.x, bi = blockIdx.y, t = threadIdx.x;
    __shared__ float sx[64], sy[64], sz[64];
    const float* geo = g_geo + bi * 16;
    float q0 = geo[9], q1 = geo[10], q2 = geo[11];
    const float* ap = anch + bi * 3 * NB;
    const float* r2row = g_R2 + (bi * NA + a) * NB;
    float s0 = 0.f, s1 = 0.f, s2 = 0.f;
    for (int b = t; b < NB; b += 64) {
        float r2 = r2row[b];
        s0 += 2.f * (ap[b] - q0) * r2;
        s1 += 2.f * (ap[NB + b] - q1) * r2;
        s2 += 2.f * (ap[2 * NB + b] - q2) * r2;
    }
    sx[t] = s0; sy[t] = s1; sz[t] = s2;
    __syncthreads();
    for (int s = 32; s; s >>= 1) {
        if (t < s) { sx[t] += sx[t + s]; sy[t] += sy[t + s]; sz[t] += sz[t + s]; }
        __syncthreads();
    }
    if (t == 0) {
        float r0 = geo[6] - sx[0], r1 = geo[7] - sy[0], r2_ = geo[8] - sz[0];
        float p0 = geo[0] * r0 + geo[1] * r1 + geo[2] * r2_;
        float p1 = geo[1] * r0 + geo[3] * r1 + geo[4] * r2_;
        float p2 = geo[2] * r0 + geo[4] * r1 + geo[5] * r2_;
        const float* app = actp + bi * 3 * NA;
        out[bi * 4 * NA + 0 * NA + a] = p0 - app[a];
        out[bi * 4 * NA + 1 * NA + a] = p1 - app[NA + a];
        out[bi * 4 * NA + 2 * NA + a] = p2 - app[2 * NA + a];
    }
}

// =========================================================================
// K6: pointnet layers 1..4 + head (ILP-2 accumulators)
// =========================================================================
__global__ void k6_pn(const float* __restrict__ W1, const float* __restrict__ b1,
                      const float* __restrict__ W2, const float* __restrict__ b2,
                      const float* __restrict__ W3, const float* __restrict__ b3,
                      const float* __restrict__ W4, const float* __restrict__ b4,
                      const float* __restrict__ hW, float* __restrict__ out) {
    int bi = blockIdx.y, n0 = blockIdx.x * 8;
    int t = threadIdx.x, nn = t & 7, og = t >> 3;
    __shared__ float ya[64 * 8];
    __shared__ float yb[64 * 8];
    __shared__ float yc[128 * 8];
    __shared__ float part[32 * 8];

    for (int f = t; f < 512; f += 256) {
        int i = f >> 3, nn2 = f & 7;
        ya[f] = g_y1[(bi * 64 + i) * NA + n0 + nn2];
    }
    __syncthreads();
    for (int o = og; o < 64; o += 32) {
        float a0 = b1[o], a1 = 0.f;
        for (int i = 0; i < 64; i += 2) {
            a0 = fmaf(W1[o * 64 + i], ya[i * 8 + nn], a0);
            a1 = fmaf(W1[o * 64 + i + 1], ya[(i + 1) * 8 + nn], a1);
        }
        yb[o * 8 + nn] = fmaxf(a0 + a1, 0.f);
    }
    __syncthreads();
    for (int o = og; o < 64; o += 32) {
        float a0 = b2[o], a1 = 0.f;
        for (int i = 0; i < 64; i += 2) {
            a0 = fmaf(W2[o * 64 + i], yb[i * 8 + nn], a0);
            a1 = fmaf(W2[o * 64 + i + 1], yb[(i + 1) * 8 + nn], a1);
        }
        ya[o * 8 + nn] = fmaxf(a0 + a1, 0.f);
    }
    __syncthreads();
    for (int o = og; o < 128; o += 32) {
        float a0 = b3[o], a1 = 0.f;
        for (int i = 0; i < 64; i += 2) {
            a0 = fmaf(W3[o * 64 + i], ya[i * 8 + nn], a0);
            a1 = fmaf(W3[o * 64 + i + 1], ya[(i + 1) * 8 + nn], a1);
        }
        yc[o * 8 + nn] = fmaxf(a0 + a1, 0.f);
    }
    __syncthreads();
    float wp = 0.f;
    for (int o = og; o < 512; o += 32) {
        float a0 = b4[o], a1 = 0.f;
        for (int i = 0; i < 128; i += 2) {
            a0 = fmaf(W4[o * 128 + i], yc[i * 8 + nn], a0);
            a1 = fmaf(W4[o * 128 + i + 1], yc[(i + 1) * 8 + nn], a1);
        }
        wp = fmaf(hW[o], fmaxf(a0 + a1, 0.f), wp);
    }
    part[og * 8 + nn] = wp;
    __syncthreads();
    for (int s = 16; s; s >>= 1) {
        if (og < s) part[og * 8 + nn] += part[(og + s) * 8 + nn];
        __syncthreads();
    }
    if (og == 0) out[bi * 4 * NA + 3 * NA + n0 + nn] = part[nn];
}

// =========================================================================
extern "C" void kernel_launch(void* const* d_in, const int* in_sizes, int n_in,
                              void* d_out, int out_size) {
    const float* actE  = (const float*)d_in[0];
    const float* anchE = (const float*)d_in[1];
    const float* actP  = (const float*)d_in[2];
    const float* anchP = (const float*)d_in[3];
    const float* W1    = (const float*)d_in[4];
    const float* b1    = (const float*)d_in[5];
    const float* W2    = (const float*)d_in[6];
    const float* b2    = (const float*)d_in[7];
    const float* W3    = (const float*)d_in[8];
    const float* b3    = (const float*)d_in[9];
    const float* pnW0  = (const float*)d_in[10];
    const float* pnb0  = (const float*)d_in[11];
    const float* pnW1  = (const float*)d_in[12];
    const float* pnb1  = (const float*)d_in[13];
    const float* pnW2  = (const float*)d_in[14];
    const float* pnb2  = (const float*)d_in[15];
    const float* pnW3  = (const float*)d_in[16];
    const float* pnb3  = (const float*)d_in[17];
    const float* pnW4  = (const float*)d_in[18];
    const float* pnb4  = (const float*)d_in[19];
    const float* headW = (const float*)d_in[20];
    float* out = (float*)d_out;

    cudaFuncSetAttribute(k2_hmma, cudaFuncAttributeMaxDynamicSharedMemorySize, SM_TOTAL);

    kp_prep<<<158, 256>>>(W2, actE, pnW0, pnb0);
    k1_h<<<dim3(5, 4, 8), dim3(16, 16)>>>(actE, anchE, W1, b1);
    k2_hmma<<<148, 768, SM_TOTAL>>>(b2, W3, b3);
    k3_geo<<<2, 256>>>(anchP);
    k6_pn<<<dim3(32, 2), 256>>>(pnW1, pnb1, pnW2, pnb2, pnW3, pnb3, pnW4, pnb4, headW, out);
    k4_flow<<<dim3(256, 2), 64>>>(anchP, actP, out);
}

// round 9
// speedup vs baseline: 3.4208x; 1.0506x over previous
#include <cuda_runtime.h>
#include <cuda_fp16.h>
#include <cstdint>

// Problem constants
#define BATCH 2
#define NA 256
#define NB 256
#define EDIM 512
#define H1 300
#define H2 100
#define HP 304   // fp16 row pitch for h matrices (38 uint4 per row)

// ---------------- scratch (device globals; no allocation) ----------------
__device__ __half g_hAa[BATCH * NA * HP];
__device__ __half g_hAb[BATCH * NA * HP];
__device__ __half g_hBa[BATCH * NB * HP];
__device__ __half g_hBb[BATCH * NB * HP];
__device__ float g_R2[BATCH * NA * NB];
__device__ float g_geo[BATCH * 16];
__device__ float g_y1[BATCH * 64 * NA];
__device__ __half g_Wimg[320 * 120];   // W2 fp16 image, pitch 240 B, zero padded

// ---------------- helpers (baseline PTX only) ----------------------------
__device__ __forceinline__ uint32_t smem_u32(const void* p) {
    uint32_t a;
    asm("{ .reg .u64 t; cvta.to.shared.u64 t, %1; cvt.u32.u64 %0, t; }" : "=r"(a) : "l"(p));
    return a;
}
__device__ __forceinline__ void ldsm_x2t(uint32_t addr, uint32_t& r0, uint32_t& r1) {
    asm volatile("ldmatrix.sync.aligned.m8n8.x2.trans.shared.b16 {%0,%1}, [%2];"
                 : "=r"(r0), "=r"(r1) : "r"(addr));
}
__device__ __forceinline__ void mma16816(float* c, const uint32_t* a, uint32_t b0, uint32_t b1) {
    asm volatile("mma.sync.aligned.m16n8k16.row.col.f32.f16.f16.f32 "
                 "{%0,%1,%2,%3}, {%4,%5,%6,%7}, {%8,%9}, {%0,%1,%2,%3};"
                 : "+f"(c[0]), "+f"(c[1]), "+f"(c[2]), "+f"(c[3])
                 : "r"(a[0]), "r"(a[1]), "r"(a[2]), "r"(a[3]), "r"(b0), "r"(b1));
}

// smem layout for k2 (byte offsets; all 16B aligned)
#define WPITCH   240
#define SPITCH_H 328           // stage pitch in halves (656 B)
#define SM_W     0             // 320*240 = 76800
#define SM_S     76800         // 48*656 = 31488 -> 108288
#define SM_B2    108288        // 128 floats -> 108800
#define SM_W3    108800        // 128 floats -> 109312
#define SM_VP    109312        // 3*256 floats = 3072 -> 112384
#define SM_TOTAL 112384

// =========================================================================
// KP: fused prep. Blocks 0..149: W2 -> fp16 image. Blocks 150..157: pointnet
// layer0 GEMM. Blocks 158..159: per-batch geometry (old k3).
// =========================================================================
__global__ void kp_prep(const float* __restrict__ W2,
                        const float* __restrict__ actE, const float* __restrict__ W0,
                        const float* __restrict__ b0, const float* __restrict__ anch) {
    if (blockIdx.x < 150) {
        int idx = blockIdx.x * 256 + threadIdx.x;
        if (idx >= 320 * 120) return;
        int k = idx / 120, n = idx % 120;
        float w = (k < H1 && n < H2) ? W2[k * H2 + n] : 0.f;
        g_Wimg[idx] = __float2half(w);
        return;
    }
    if (blockIdx.x < 158) {
        int bl = blockIdx.x - 150;
        int bi = bl >> 2;
        int n0 = (bl & 3) * 64;
        const float* x = actE + bi * EDIM * NA;
        int tid = threadIdx.x;
        int tx = tid & 15, ty = tid >> 4;
        __shared__ float As[16][64];
        __shared__ float Bs[16][64];
        float acc[4][4];
#pragma unroll
        for (int i = 0; i < 4; ++i)
#pragma unroll
            for (int j = 0; j < 4; ++j) acc[i][j] = 0.f;
        int o_l = tid & 63;
        int k4 = (tid >> 6) * 4;
        int lkk = tid / 16, l4 = (tid % 16) * 4;
        for (int k0 = 0; k0 < EDIM; k0 += 16) {
            __syncthreads();
            float4 w = *(const float4*)&W0[o_l * EDIM + k0 + k4];
            As[k4 + 0][o_l] = w.x; As[k4 + 1][o_l] = w.y;
            As[k4 + 2][o_l] = w.z; As[k4 + 3][o_l] = w.w;
            *(float4*)&Bs[lkk][l4] = *(const float4*)&x[(k0 + lkk) * NA + n0 + l4];
            __syncthreads();
#pragma unroll
            for (int kk = 0; kk < 16; ++kk) {
                float av[4], bv[4];
#pragma unroll
                for (int i = 0; i < 4; ++i) av[i] = As[kk][ty * 4 + i];
#pragma unroll
                for (int j = 0; j < 4; ++j) bv[j] = Bs[kk][tx * 4 + j];
#pragma unroll
                for (int i = 0; i < 4; ++i)
#pragma unroll
                    for (int j = 0; j < 4; ++j) acc[i][j] = fmaf(av[i], bv[j], acc[i][j]);
            }
        }
#pragma unroll
        for (int i = 0; i < 4; ++i) {
            int o = ty * 4 + i;
            float bb = b0[o];
#pragma unroll
            for (int j = 0; j < 4; ++j) {
                int n = n0 + tx * 4 + j;
                g_y1[(bi * 64 + o) * NA + n] = fmaxf(acc[i][j] + bb, 0.f);
            }
        }
        return;
    }
    // ---- geometry (old k3) ----
    {
        int bi = blockIdx.x - 158, t = threadIdx.x;
        __shared__ float buf[9 * 256];
        __shared__ float q[3];
        const float* ap = anch + bi * 3 * NB;
        float px = ap[t], py = ap[NB + t], pz = ap[2 * NB + t];
        buf[t] = px; buf[256 + t] = py; buf[512 + t] = pz;
        __syncthreads();
        for (int s = 128; s; s >>= 1) {
            if (t < s)
                for (int cc = 0; cc < 3; ++cc) buf[cc * 256 + t] += buf[cc * 256 + t + s];
            __syncthreads();
        }
        if (t == 0) { q[0] = buf[0] / NB; q[1] = buf[256] / NB; q[2] = buf[512] / NB; }
        __syncthreads();
        float ax = 2.f * (px - q[0]), ay = 2.f * (py - q[1]), az = 2.f * (pz - q[2]);
        float cv = px * px + py * py + pz * pz;
        buf[t] = ax * ax;          buf[256 + t] = ax * ay;   buf[512 + t] = ax * az;
        buf[768 + t] = ay * ay;    buf[1024 + t] = ay * az;  buf[1280 + t] = az * az;
        buf[1536 + t] = ax * cv;   buf[1792 + t] = ay * cv;  buf[2048 + t] = az * cv;
        __syncthreads();
        for (int s = 128; s; s >>= 1) {
            if (t < s)
                for (int cc = 0; cc < 9; ++cc) buf[cc * 256 + t] += buf[cc * 256 + t + s];
            __syncthreads();
        }
        if (t == 0) {
            float m00 = buf[0], m01 = buf[256], m02 = buf[512];
            float m11 = buf[768], m12 = buf[1024], m22 = buf[1280];
            float det = m00 * (m11 * m22 - m12 * m12) - m01 * (m01 * m22 - m12 * m02)
                      + m02 * (m01 * m12 - m11 * m02);
            float inv = 1.f / det;
            float* geo = g_geo + bi * 16;
            geo[0] = (m11 * m22 - m12 * m12) * inv;
            geo[1] = (m02 * m12 - m01 * m22) * inv;
            geo[2] = (m01 * m12 - m02 * m11) * inv;
            geo[3] = (m00 * m22 - m02 * m02) * inv;
            geo[4] = (m02 * m01 - m00 * m12) * inv;
            geo[5] = (m00 * m11 - m01 * m01) * inv;
            geo[6] = buf[1536]; geo[7] = buf[1792]; geo[8] = buf[2048];
            geo[9] = q[0]; geo[10] = q[1]; geo[11] = q[2];
        }
    }
}

// =========================================================================
// K1: h matrices (fp32 SIMT GEMM) -> fp16 output, pitch 304, zero pad.
// =========================================================================
__global__ void k1_h(const float* __restrict__ actE, const float* __restrict__ anchE,
                     const float* __restrict__ W1, const float* __restrict__ b1) {
    int bi   = blockIdx.z & 1;
    int src  = (blockIdx.z >> 1) & 1;
    int half = blockIdx.z >> 2;
    const float* emb = (src ? anchE : actE) + bi * EDIM * NA;
    __half* outp = (half == 0 ? (src ? g_hBa : g_hAa) : (src ? g_hBb : g_hAb)) + bi * NA * HP;

    int n0 = blockIdx.y * 64;
    int j0 = blockIdx.x * 64;
    int tx = threadIdx.x, ty = threadIdx.y;
    int tid = ty * 16 + tx;

    __shared__ float As[16 * 64];
    __shared__ float Bs[16 * 64];

    float acc[4][4];
#pragma unroll
    for (int i = 0; i < 4; ++i)
#pragma unroll
        for (int j = 0; j < 4; ++j) acc[i][j] = 0.f;

    int wbase = half * 512;
    int lkk = tid / 16;
    int l4  = (tid % 16) * 4;

    for (int k0 = 0; k0 < EDIM; k0 += 16) {
        __syncthreads();
        *(float4*)&As[lkk * 64 + l4] = *(const float4*)&emb[(k0 + lkk) * NA + n0 + l4];
        {
            int jg = j0 + l4;
            float4 bv = make_float4(0.f, 0.f, 0.f, 0.f);
            if (jg < H1) bv = *(const float4*)&W1[(wbase + k0 + lkk) * H1 + jg];
            *(float4*)&Bs[lkk * 64 + l4] = bv;
        }
        __syncthreads();
#pragma unroll
        for (int kk = 0; kk < 16; ++kk) {
            float4 a4 = *(const float4*)&As[kk * 64 + ty * 4];
            float4 b4 = *(const float4*)&Bs[kk * 64 + tx * 4];
            float av[4] = {a4.x, a4.y, a4.z, a4.w};
            float bv[4] = {b4.x, b4.y, b4.z, b4.w};
#pragma unroll
            for (int i = 0; i < 4; ++i)
#pragma unroll
                for (int j = 0; j < 4; ++j) acc[i][j] = fmaf(av[i], bv[j], acc[i][j]);
        }
    }
#pragma unroll
    for (int i = 0; i < 4; ++i) {
        int n = n0 + ty * 4 + i;
#pragma unroll
        for (int j = 0; j < 4; ++j) {
            int jg = j0 + tx * 4 + j;
            if (jg < H1) {
                float v = acc[i][j];
                if (half == 0) v += b1[jg];
                outp[n * HP + jg] = __float2half(v);
            } else if (jg < HP) {
                outp[n * HP + jg] = __float2half(0.f);
            }
        }
    }
}

// =========================================================================
// K2: PERSISTENT pair-MLP tensor GEMM, fp16, software-pipelined stage.
// 768 threads (24 warps): warp = (rg 0..3, side 0..1, hh 0..2).
// Per tile: 2 barriers (was 6); next tile's h-rows prefetched into regs.
// =========================================================================
__device__ __forceinline__ uint4 stage_ld(int idx, int bi, int a0, int b0) {
    int row = idx / 41, i = idx % 41;
    if (i >= 38) return make_uint4(0u, 0u, 0u, 0u);
    const uint4* srcp;
    int gr;
    if (row < 16)      { srcp = (const uint4*)g_hAa; gr = bi * NA + a0 + row; }
    else if (row < 32) { srcp = (const uint4*)g_hAb; gr = bi * NA + a0 + row - 16; }
    else if (row < 40) { srcp = (const uint4*)g_hBb; gr = bi * NB + b0 + row - 32; }
    else               { srcp = (const uint4*)g_hBa; gr = bi * NB + b0 + row - 40; }
    return srcp[gr * 38 + i];
}

__global__ void __launch_bounds__(768, 1) k2_hmma(const float* __restrict__ b2,
                                                  const float* __restrict__ W3,
                                                  const float* __restrict__ b3p) {
    extern __shared__ char smem[];
    const uint32_t sbase = smem_u32(smem);
    const int tid = threadIdx.x;
    const int wid = tid >> 5;
    const int lane = tid & 31;

    const int rg = wid / 6;
    const int r6 = wid % 6;
    const int side = r6 / 3;
    const int hh = r6 % 3;
    const int mbase = rg * 32;
    const int jt0 = hh * 5;
    const int g = lane >> 2;
    const int tq = lane & 3;
    const int c0 = tq * 2;
    const int blane = lane & 15;

    if (tid < 128) {
        *(float*)(smem + SM_B2 + tid * 4) = (tid < H2) ? b2[tid] : 0.f;
        *(float*)(smem + SM_W3 + tid * 4) = (tid < H2) ? W3[tid] : 0.f;
    }
    {
        uint4* dst = (uint4*)(smem + SM_W);
        const uint4* src = (const uint4*)g_Wimg;
        for (int i = tid; i < 4800; i += 768) dst[i] = src[i];
    }

    const float b3 = b3p[0];
    const float* b2s = (const float*)(smem + SM_B2);
    const float* W3s = (const float*)(smem + SM_W3);
    float* vp = (float*)(smem + SM_VP);

    const int srowB = 32 + side * 8 + g;
    const int sa_row0 = side * 16 + rg * 4;
    const __half2 z2 = __float2half2_rn(0.f);

    // initial prefetch for first tile
    uint4 pf0, pf1;
    {
        int t0 = blockIdx.x;
        if (t0 < 1024) {
            int bi = t0 >> 9, rem = t0 & 511;
            int a0 = (rem >> 5) << 4, b0 = (rem & 31) << 3;
            pf0 = stage_ld(tid, bi, a0, b0);
            pf1 = stage_ld(tid + 768, bi, a0, b0);
        }
    }
    __syncthreads();  // W image + constants visible

#pragma unroll 1
    for (int t = blockIdx.x; t < 1024; t += 148) {
        const int bi = t >> 9;
        const int rem = t & 511;
        const int a0 = (rem >> 5) << 4;
        const int b0 = (rem & 31) << 3;

        // ---- write stage from prefetched regs (+ small direct tail) ----
        {
            int row0 = tid / 41, i0 = tid % 41;
            *(uint4*)(smem + SM_S + row0 * 656 + i0 * 16) = pf0;
            int idx1 = tid + 768;
            int row1 = idx1 / 41, i1 = idx1 % 41;
            *(uint4*)(smem + SM_S + row1 * 656 + i1 * 16) = pf1;
            int idx2 = tid + 1536;
            if (idx2 < 1968) {
                uint4 v = stage_ld(idx2, bi, a0, b0);
                int row2 = idx2 / 41, i2 = idx2 % 41;
                *(uint4*)(smem + SM_S + row2 * 656 + i2 * 16) = v;
            }
        }
        __syncthreads();  // stage visible; also protects vp reuse (finalize done)

        float acc[2][5][4];
#pragma unroll
        for (int mt = 0; mt < 2; ++mt)
#pragma unroll
            for (int n = 0; n < 5; ++n)
#pragma unroll
                for (int q = 0; q < 4; ++q) acc[mt][n][q] = 0.f;

        const __half2* S2 = (const __half2*)(smem + SM_S);

#pragma unroll 1
        for (int ks = 0; ks < 20; ++ks) {
            const int kc = ks * 16 + c0;
            __half2 Blo = S2[(srowB * SPITCH_H + kc) >> 1];
            __half2 Bhi = S2[(srowB * SPITCH_H + kc + 8) >> 1];
            uint32_t afrag[2][4];
#pragma unroll
            for (int mt = 0; mt < 2; ++mt)
#pragma unroll
                for (int hf = 0; hf < 2; ++hf) {
                    int srow = sa_row0 + mt * 2 + hf;
                    __half2 Alo = S2[(srow * SPITCH_H + kc) >> 1];
                    __half2 Ahi = S2[(srow * SPITCH_H + kc + 8) >> 1];
                    __half2 x0 = __hmax2(__hadd2(Alo, Blo), z2);
                    __half2 x1 = __hmax2(__hadd2(Ahi, Bhi), z2);
                    afrag[mt][hf] = *(uint32_t*)&x0;
                    afrag[mt][hf + 2] = *(uint32_t*)&x1;
                }
            const uint32_t wa = sbase + SM_W + (uint32_t)(ks * 16 + blane) * WPITCH
                              + (uint32_t)jt0 * 16;
#pragma unroll
            for (int nt = 0; nt < 5; ++nt) {
                uint32_t br0, br1;
                ldsm_x2t(wa + nt * 16, br0, br1);
                mma16816(acc[0][nt], afrag[0], br0, br1);
                mma16816(acc[1][nt], afrag[1], br0, br1);
            }
        }

        // ---- prefetch next tile (overlaps epilogue) ----
        if (t + 148 < 1024) {
            int tn = t + 148;
            int bin = tn >> 9, remn = tn & 511;
            int a0n = (remn >> 5) << 4, b0n = (remn & 31) << 3;
            pf0 = stage_ld(tid, bin, a0n, b0n);
            pf1 = stage_ld(tid + 768, bin, a0n, b0n);
        }

        // ---- epilogue: partial dot with W3 over this warp's 40 cols ----
        float vs[2][2];
#pragma unroll
        for (int mt = 0; mt < 2; ++mt) {
            float s0 = 0.f, s1 = 0.f;
#pragma unroll
            for (int nt = 0; nt < 5; ++nt) {
                int j = (jt0 + nt) * 8 + c0;
                float w0 = W3s[j], w1 = W3s[j + 1];
                float bb0 = b2s[j], bb1 = b2s[j + 1];
                s0 += fmaxf(acc[mt][nt][0] + bb0, 0.f) * w0 + fmaxf(acc[mt][nt][1] + bb1, 0.f) * w1;
                s1 += fmaxf(acc[mt][nt][2] + bb0, 0.f) * w0 + fmaxf(acc[mt][nt][3] + bb1, 0.f) * w1;
            }
            s0 += __shfl_xor_sync(0xffffffffu, s0, 1);
            s0 += __shfl_xor_sync(0xffffffffu, s0, 2);
            s1 += __shfl_xor_sync(0xffffffffu, s1, 1);
            s1 += __shfl_xor_sync(0xffffffffu, s1, 2);
            vs[mt][0] = s0; vs[mt][1] = s1;
        }
        if (tq == 0) {
#pragma unroll
            for (int mt = 0; mt < 2; ++mt)
#pragma unroll
                for (int hf = 0; hf < 2; ++hf)
                    vp[hh * 256 + side * 128 + mbase + mt * 16 + hf * 8 + g] = vs[mt][hf];
        }
        __syncthreads();
        // ---- finalize: 128 threads combine 6 partials, softplus^2, store ----
        if (tid < 128) {
            float v1 = vp[tid] + vp[256 + tid] + vp[512 + tid];
            float v2 = vp[128 + tid] + vp[384 + tid] + vp[640 + tid];
            float s = 0.5f * (v1 + v2) + b3;
            float sp = fmaxf(s, 0.f) + log1pf(expf(-fabsf(s)));
            g_R2[(bi * NA + a0 + (tid >> 3)) * NB + b0 + (tid & 7)] = sp * sp;
        }
    }
}

// =========================================================================
// K46: fused pointnet tail (k6) + flow (k4).
// Blocks 0..63: k6 (bi = b>>5, n0 = (b&31)*8), 256 threads.
// Blocks 64..191: k4, 4 anchors per block in 64-thread groups.
// =========================================================================
__global__ void k46(const float* __restrict__ W1, const float* __restrict__ b1,
                    const float* __restrict__ W2, const float* __restrict__ b2,
                    const float* __restrict__ W3, const float* __restrict__ b3,
                    const float* __restrict__ W4, const float* __restrict__ b4,
                    const float* __restrict__ hW,
                    const float* __restrict__ anch, const float* __restrict__ actp,
                    float* __restrict__ out) {
    int t = threadIdx.x;
    if (blockIdx.x < 64) {
        int bi = blockIdx.x >> 5, n0 = (blockIdx.x & 31) * 8;
        int nn = t & 7, og = t >> 3;
        __shared__ float ya[64 * 8];
        __shared__ float yb[64 * 8];
        __shared__ float yc[128 * 8];
        __shared__ float part[32 * 8];

        for (int f = t; f < 512; f += 256) {
            int i = f >> 3, nn2 = f & 7;
            ya[f] = g_y1[(bi * 64 + i) * NA + n0 + nn2];
        }
        __syncthreads();
        for (int o = og; o < 64; o += 32) {
            float a0 = b1[o], a1 = 0.f;
            for (int i = 0; i < 64; i += 2) {
                a0 = fmaf(W1[o * 64 + i], ya[i * 8 + nn], a0);
                a1 = fmaf(W1[o * 64 + i + 1], ya[(i + 1) * 8 + nn], a1);
            }
            yb[o * 8 + nn] = fmaxf(a0 + a1, 0.f);
        }
        __syncthreads();
        for (int o = og; o < 64; o += 32) {
            float a0 = b2[o], a1 = 0.f;
            for (int i = 0; i < 64; i += 2) {
                a0 = fmaf(W2[o * 64 + i], yb[i * 8 + nn], a0);
                a1 = fmaf(W2[o * 64 + i + 1], yb[(i + 1) * 8 + nn], a1);
            }
            ya[o * 8 + nn] = fmaxf(a0 + a1, 0.f);
        }
        __syncthreads();
        for (int o = og; o < 128; o += 32) {
            float a0 = b3[o], a1 = 0.f;
            for (int i = 0; i < 64; i += 2) {
                a0 = fmaf(W3[o * 64 + i], ya[i * 8 + nn], a0);
                a1 = fmaf(W3[o * 64 + i + 1], ya[(i + 1) * 8 + nn], a1);
            }
            yc[o * 8 + nn] = fmaxf(a0 + a1, 0.f);
        }
        __syncthreads();
        float wp = 0.f;
        for (int o = og; o < 512; o += 32) {
            float a0 = b4[o], a1 = 0.f;
            for (int i = 0; i < 128; i += 2) {
                a0 = fmaf(W4[o * 128 + i], yc[i * 8 + nn], a0);
                a1 = fmaf(W4[o * 128 + i + 1], yc[(i + 1) * 8 + nn], a1);
            }
            wp = fmaf(hW[o], fmaxf(a0 + a1, 0.f), wp);
        }
        part[og * 8 + nn] = wp;
        __syncthreads();
        for (int s = 16; s; s >>= 1) {
            if (og < s) part[og * 8 + nn] += part[(og + s) * 8 + nn];
            __syncthreads();
        }
        if (og == 0) out[bi * 4 * NA + 3 * NA + n0 + nn] = part[nn];
        return;
    }
    // ---- flow: 4 anchors per block ----
    {
        int bl = blockIdx.x - 64;        // 0..127
        int bi = bl >> 6;
        int sub = t >> 6;                // 0..3
        int tt = t & 63;
        int a = (bl & 63) * 4 + sub;
        __shared__ float sx[256], sy[256], sz[256];
        const float* geo = g_geo + bi * 16;
        float q0 = geo[9], q1 = geo[10], q2 = geo[11];
        const float* ap = anch + bi * 3 * NB;
        const float* r2row = g_R2 + (bi * NA + a) * NB;
        float s0 = 0.f, s1 = 0.f, s2 = 0.f;
        for (int b = tt; b < NB; b += 64) {
            float r2 = r2row[b];
            s0 += 2.f * (ap[b] - q0) * r2;
            s1 += 2.f * (ap[NB + b] - q1) * r2;
            s2 += 2.f * (ap[2 * NB + b] - q2) * r2;
        }
        int base = sub * 64;
        sx[base + tt] = s0; sy[base + tt] = s1; sz[base + tt] = s2;
        __syncthreads();
        for (int s = 32; s; s >>= 1) {
            if (tt < s) {
                sx[base + tt] += sx[base + tt + s];
                sy[base + tt] += sy[base + tt + s];
                sz[base + tt] += sz[base + tt + s];
            }
            __syncthreads();
        }
        if (tt == 0) {
            float r0 = geo[6] - sx[base], r1 = geo[7] - sy[base], r2_ = geo[8] - sz[base];
            float p0 = geo[0] * r0 + geo[1] * r1 + geo[2] * r2_;
            float p1 = geo[1] * r0 + geo[3] * r1 + geo[4] * r2_;
            float p2 = geo[2] * r0 + geo[4] * r1 + geo[5] * r2_;
            const float* app = actp + bi * 3 * NA;
            out[bi * 4 * NA + 0 * NA + a] = p0 - app[a];
            out[bi * 4 * NA + 1 * NA + a] = p1 - app[NA + a];
            out[bi * 4 * NA + 2 * NA + a] = p2 - app[2 * NA + a];
        }
    }
}

// =========================================================================
extern "C" void kernel_launch(void* const* d_in, const int* in_sizes, int n_in,
                              void* d_out, int out_size) {
    const float* actE  = (const float*)d_in[0];
    const float* anchE = (const float*)d_in[1];
    const float* actP  = (const float*)d_in[2];
    const float* anchP = (const float*)d_in[3];
    const float* W1    = (const float*)d_in[4];
    const float* b1    = (const float*)d_in[5];
    const float* W2    = (const float*)d_in[6];
    const float* b2    = (const float*)d_in[7];
    const float* W3    = (const float*)d_in[8];
    const float* b3    = (const float*)d_in[9];
    const float* pnW0  = (const float*)d_in[10];
    const float* pnb0  = (const float*)d_in[11];
    const float* pnW1  = (const float*)d_in[12];
    const float* pnb1  = (const float*)d_in[13];
    const float* pnW2  = (const float*)d_in[14];
    const float* pnb2  = (const float*)d_in[15];
    const float* pnW3  = (const float*)d_in[16];
    const float* pnb3  = (const float*)d_in[17];
    const float* pnW4  = (const float*)d_in[18];
    const float* pnb4  = (const float*)d_in[19];
    const float* headW = (const float*)d_in[20];
    float* out = (float*)d_out;

    cudaFuncSetAttribute(k2_hmma, cudaFuncAttributeMaxDynamicSharedMemorySize, SM_TOTAL);

    kp_prep<<<160, 256>>>(W2, actE, pnW0, pnb0, anchP);
    k1_h<<<dim3(5, 4, 8), dim3(16, 16)>>>(actE, anchE, W1, b1);
    k2_hmma<<<148, 768, SM_TOTAL>>>(b2, W3, b3);
    k46<<<192, 256>>>(pnW1, pnb1, pnW2, pnb2, pnW3, pnb3, pnW4, pnb4, headW,
                      anchP, actP, out);
}

// round 11
// speedup vs baseline: 3.9939x; 1.1675x over previous
#include <cuda_runtime.h>
#include <cuda_fp16.h>
#include <cstdint>

// Problem constants
#define BATCH 2
#define NA 256
#define NB 256
#define EDIM 512
#define H1 300
#define H2 100
#define HP 304   // fp16 row pitch for h matrices (38 uint4 per row)

// ---------------- scratch (device globals; no allocation) ----------------
__device__ __half g_hAa[BATCH * NA * HP];
__device__ __half g_hAb[BATCH * NA * HP];
__device__ __half g_hBa[BATCH * NB * HP];
__device__ __half g_hBb[BATCH * NB * HP];
__device__ float g_R2[BATCH * NA * NB];
__device__ float g_geo[BATCH * 16];
__device__ float g_y1[BATCH * 64 * NA];
__device__ __half g_Wimg[320 * 120];   // W2 fp16 image, pitch 240 B, zero padded

// ---------------- helpers (baseline PTX only) ----------------------------
__device__ __forceinline__ uint32_t smem_u32(const void* p) {
    uint32_t a;
    asm("{ .reg .u64 t; cvta.to.shared.u64 t, %1; cvt.u32.u64 %0, t; }" : "=r"(a) : "l"(p));
    return a;
}
__device__ __forceinline__ void ldsm_x2t(uint32_t addr, uint32_t& r0, uint32_t& r1) {
    asm volatile("ldmatrix.sync.aligned.m8n8.x2.trans.shared.b16 {%0,%1}, [%2];"
                 : "=r"(r0), "=r"(r1) : "r"(addr));
}
__device__ __forceinline__ void mma16816(float* c, const uint32_t* a, uint32_t b0, uint32_t b1) {
    asm volatile("mma.sync.aligned.m16n8k16.row.col.f32.f16.f16.f32 "
                 "{%0,%1,%2,%3}, {%4,%5,%6,%7}, {%8,%9}, {%0,%1,%2,%3};"
                 : "+f"(c[0]), "+f"(c[1]), "+f"(c[2]), "+f"(c[3])
                 : "r"(a[0]), "r"(a[1]), "r"(a[2]), "r"(a[3]), "r"(b0), "r"(b1));
}

// smem layout for k2 (byte offsets; all 16B aligned)
#define WPITCH   240
#define SPITCH_H 328           // stage pitch in halves (656 B)
#define SM_W     0             // 320*240 = 76800
#define SM_S     76800         // 48*656 = 31488 -> 108288
#define SM_B2    108288        // 128 floats -> 108800
#define SM_W3    108800        // 128 floats -> 109312
#define SM_VP    109312        // 3*256 floats = 3072 -> 112384
#define SM_TOTAL 112384

// =========================================================================
// KP: fused prep. Blocks 0..149: W2 -> fp16 image. Blocks 150..157: pointnet
// layer0 GEMM. Blocks 158..159: per-batch geometry.
// =========================================================================
__global__ void kp_prep(const float* __restrict__ W2,
                        const float* __restrict__ actE, const float* __restrict__ W0,
                        const float* __restrict__ b0, const float* __restrict__ anch) {
    if (blockIdx.x < 150) {
        int idx = blockIdx.x * 256 + threadIdx.x;
        if (idx >= 320 * 120) return;
        int k = idx / 120, n = idx % 120;
        float w = (k < H1 && n < H2) ? W2[k * H2 + n] : 0.f;
        g_Wimg[idx] = __float2half(w);
        return;
    }
    if (blockIdx.x < 158) {
        int bl = blockIdx.x - 150;
        int bi = bl >> 2;
        int n0 = (bl & 3) * 64;
        const float* x = actE + bi * EDIM * NA;
        int tid = threadIdx.x;
        int tx = tid & 15, ty = tid >> 4;
        __shared__ float As[16][64];
        __shared__ float Bs[16][64];
        float acc[4][4];
#pragma unroll
        for (int i = 0; i < 4; ++i)
#pragma unroll
            for (int j = 0; j < 4; ++j) acc[i][j] = 0.f;
        int o_l = tid & 63;
        int k4 = (tid >> 6) * 4;
        int lkk = tid / 16, l4 = (tid % 16) * 4;
        for (int k0 = 0; k0 < EDIM; k0 += 16) {
            __syncthreads();
            float4 w = *(const float4*)&W0[o_l * EDIM + k0 + k4];
            As[k4 + 0][o_l] = w.x; As[k4 + 1][o_l] = w.y;
            As[k4 + 2][o_l] = w.z; As[k4 + 3][o_l] = w.w;
            *(float4*)&Bs[lkk][l4] = *(const float4*)&x[(k0 + lkk) * NA + n0 + l4];
            __syncthreads();
#pragma unroll
            for (int kk = 0; kk < 16; ++kk) {
                float av[4], bv[4];
#pragma unroll
                for (int i = 0; i < 4; ++i) av[i] = As[kk][ty * 4 + i];
#pragma unroll
                for (int j = 0; j < 4; ++j) bv[j] = Bs[kk][tx * 4 + j];
#pragma unroll
                for (int i = 0; i < 4; ++i)
#pragma unroll
                    for (int j = 0; j < 4; ++j) acc[i][j] = fmaf(av[i], bv[j], acc[i][j]);
            }
        }
#pragma unroll
        for (int i = 0; i < 4; ++i) {
            int o = ty * 4 + i;
            float bb = b0[o];
#pragma unroll
            for (int j = 0; j < 4; ++j) {
                int n = n0 + tx * 4 + j;
                g_y1[(bi * 64 + o) * NA + n] = fmaxf(acc[i][j] + bb, 0.f);
            }
        }
        return;
    }
    // ---- geometry ----
    {
        int bi = blockIdx.x - 158, t = threadIdx.x;
        __shared__ float buf[9 * 256];
        __shared__ float q[3];
        const float* ap = anch + bi * 3 * NB;
        float px = ap[t], py = ap[NB + t], pz = ap[2 * NB + t];
        buf[t] = px; buf[256 + t] = py; buf[512 + t] = pz;
        __syncthreads();
        for (int s = 128; s; s >>= 1) {
            if (t < s)
                for (int cc = 0; cc < 3; ++cc) buf[cc * 256 + t] += buf[cc * 256 + t + s];
            __syncthreads();
        }
        if (t == 0) { q[0] = buf[0] / NB; q[1] = buf[256] / NB; q[2] = buf[512] / NB; }
        __syncthreads();
        float ax = 2.f * (px - q[0]), ay = 2.f * (py - q[1]), az = 2.f * (pz - q[2]);
        float cv = px * px + py * py + pz * pz;
        buf[t] = ax * ax;          buf[256 + t] = ax * ay;   buf[512 + t] = ax * az;
        buf[768 + t] = ay * ay;    buf[1024 + t] = ay * az;  buf[1280 + t] = az * az;
        buf[1536 + t] = ax * cv;   buf[1792 + t] = ay * cv;  buf[2048 + t] = az * cv;
        __syncthreads();
        for (int s = 128; s; s >>= 1) {
            if (t < s)
                for (int cc = 0; cc < 9; ++cc) buf[cc * 256 + t] += buf[cc * 256 + t + s];
            __syncthreads();
        }
        if (t == 0) {
            float m00 = buf[0], m01 = buf[256], m02 = buf[512];
            float m11 = buf[768], m12 = buf[1024], m22 = buf[1280];
            float det = m00 * (m11 * m22 - m12 * m12) - m01 * (m01 * m22 - m12 * m02)
                      + m02 * (m01 * m12 - m11 * m02);
            float inv = 1.f / det;
            float* geo = g_geo + bi * 16;
            geo[0] = (m11 * m22 - m12 * m12) * inv;
            geo[1] = (m02 * m12 - m01 * m22) * inv;
            geo[2] = (m01 * m12 - m02 * m11) * inv;
            geo[3] = (m00 * m22 - m02 * m02) * inv;
            geo[4] = (m02 * m01 - m00 * m12) * inv;
            geo[5] = (m00 * m11 - m01 * m01) * inv;
            geo[6] = buf[1536]; geo[7] = buf[1792]; geo[8] = buf[2048];
            geo[9] = q[0]; geo[10] = q[1]; geo[11] = q[2];
        }
    }
}

// =========================================================================
// K1: h matrices (fp32 SIMT GEMM) -> fp16 output, pitch 304, zero pad.
// =========================================================================
__global__ void k1_h(const float* __restrict__ actE, const float* __restrict__ anchE,
                     const float* __restrict__ W1, const float* __restrict__ b1) {
    int bi   = blockIdx.z & 1;
    int src  = (blockIdx.z >> 1) & 1;
    int half = blockIdx.z >> 2;
    const float* emb = (src ? anchE : actE) + bi * EDIM * NA;
    __half* outp = (half == 0 ? (src ? g_hBa : g_hAa) : (src ? g_hBb : g_hAb)) + bi * NA * HP;

    int n0 = blockIdx.y * 64;
    int j0 = blockIdx.x * 64;
    int tx = threadIdx.x, ty = threadIdx.y;
    int tid = ty * 16 + tx;

    __shared__ float As[16 * 64];
    __shared__ float Bs[16 * 64];

    float acc[4][4];
#pragma unroll
    for (int i = 0; i < 4; ++i)
#pragma unroll
        for (int j = 0; j < 4; ++j) acc[i][j] = 0.f;

    int wbase = half * 512;
    int lkk = tid / 16;
    int l4  = (tid % 16) * 4;

    for (int k0 = 0; k0 < EDIM; k0 += 16) {
        __syncthreads();
        *(float4*)&As[lkk * 64 + l4] = *(const float4*)&emb[(k0 + lkk) * NA + n0 + l4];
        {
            int jg = j0 + l4;
            float4 bv = make_float4(0.f, 0.f, 0.f, 0.f);
            if (jg < H1) bv = *(const float4*)&W1[(wbase + k0 + lkk) * H1 + jg];
            *(float4*)&Bs[lkk * 64 + l4] = bv;
        }
        __syncthreads();
#pragma unroll
        for (int kk = 0; kk < 16; ++kk) {
            float4 a4 = *(const float4*)&As[kk * 64 + ty * 4];
            float4 b4 = *(const float4*)&Bs[kk * 64 + tx * 4];
            float av[4] = {a4.x, a4.y, a4.z, a4.w};
            float bv[4] = {b4.x, b4.y, b4.z, b4.w};
#pragma unroll
            for (int i = 0; i < 4; ++i)
#pragma unroll
                for (int j = 0; j < 4; ++j) acc[i][j] = fmaf(av[i], bv[j], acc[i][j]);
        }
    }
#pragma unroll
    for (int i = 0; i < 4; ++i) {
        int n = n0 + ty * 4 + i;
#pragma unroll
        for (int j = 0; j < 4; ++j) {
            int jg = j0 + tx * 4 + j;
            if (jg < H1) {
                float v = acc[i][j];
                if (half == 0) v += b1[jg];
                outp[n * HP + jg] = __float2half(v);
            } else if (jg < HP) {
                outp[n * HP + jg] = __float2half(0.f);
            }
        }
    }
}

// =========================================================================
// K2: PERSISTENT pair-MLP tensor GEMM, fp16, software-pipelined stage.
// (unchanged — validated at 4.1e-6)
// =========================================================================
__device__ __forceinline__ uint4 stage_ld(int idx, int bi, int a0, int b0) {
    int row = idx / 41, i = idx % 41;
    if (i >= 38) return make_uint4(0u, 0u, 0u, 0u);
    const uint4* srcp;
    int gr;
    if (row < 16)      { srcp = (const uint4*)g_hAa; gr = bi * NA + a0 + row; }
    else if (row < 32) { srcp = (const uint4*)g_hAb; gr = bi * NA + a0 + row - 16; }
    else if (row < 40) { srcp = (const uint4*)g_hBb; gr = bi * NB + b0 + row - 32; }
    else               { srcp = (const uint4*)g_hBa; gr = bi * NB + b0 + row - 40; }
    return srcp[gr * 38 + i];
}

__global__ void __launch_bounds__(768, 1) k2_hmma(const float* __restrict__ b2,
                                                  const float* __restrict__ W3,
                                                  const float* __restrict__ b3p) {
    extern __shared__ char smem[];
    const uint32_t sbase = smem_u32(smem);
    const int tid = threadIdx.x;
    const int wid = tid >> 5;
    const int lane = tid & 31;

    const int rg = wid / 6;
    const int r6 = wid % 6;
    const int side = r6 / 3;
    const int hh = r6 % 3;
    const int mbase = rg * 32;
    const int jt0 = hh * 5;
    const int g = lane >> 2;
    const int tq = lane & 3;
    const int c0 = tq * 2;
    const int blane = lane & 15;

    if (tid < 128) {
        *(float*)(smem + SM_B2 + tid * 4) = (tid < H2) ? b2[tid] : 0.f;
        *(float*)(smem + SM_W3 + tid * 4) = (tid < H2) ? W3[tid] : 0.f;
    }
    {
        uint4* dst = (uint4*)(smem + SM_W);
        const uint4* src = (const uint4*)g_Wimg;
        for (int i = tid; i < 4800; i += 768) dst[i] = src[i];
    }

    const float b3 = b3p[0];
    const float* b2s = (const float*)(smem + SM_B2);
    const float* W3s = (const float*)(smem + SM_W3);
    float* vp = (float*)(smem + SM_VP);

    const int srowB = 32 + side * 8 + g;
    const int sa_row0 = side * 16 + rg * 4;
    const __half2 z2 = __float2half2_rn(0.f);

    uint4 pf0, pf1;
    {
        int t0 = blockIdx.x;
        if (t0 < 1024) {
            int bi = t0 >> 9, rem = t0 & 511;
            int a0 = (rem >> 5) << 4, b0 = (rem & 31) << 3;
            pf0 = stage_ld(tid, bi, a0, b0);
            pf1 = stage_ld(tid + 768, bi, a0, b0);
        }
    }
    __syncthreads();

#pragma unroll 1
    for (int t = blockIdx.x; t < 1024; t += 148) {
        const int bi = t >> 9;
        const int rem = t & 511;
        const int a0 = (rem >> 5) << 4;
        const int b0 = (rem & 31) << 3;

        {
            int row0 = tid / 41, i0 = tid % 41;
            *(uint4*)(smem + SM_S + row0 * 656 + i0 * 16) = pf0;
            int idx1 = tid + 768;
            int row1 = idx1 / 41, i1 = idx1 % 41;
            *(uint4*)(smem + SM_S + row1 * 656 + i1 * 16) = pf1;
            int idx2 = tid + 1536;
            if (idx2 < 1968) {
                uint4 v = stage_ld(idx2, bi, a0, b0);
                int row2 = idx2 / 41, i2 = idx2 % 41;
                *(uint4*)(smem + SM_S + row2 * 656 + i2 * 16) = v;
            }
        }
        __syncthreads();

        float acc[2][5][4];
#pragma unroll
        for (int mt = 0; mt < 2; ++mt)
#pragma unroll
            for (int n = 0; n < 5; ++n)
#pragma unroll
                for (int q = 0; q < 4; ++q) acc[mt][n][q] = 0.f;

        const __half2* S2 = (const __half2*)(smem + SM_S);

#pragma unroll 1
        for (int ks = 0; ks < 20; ++ks) {
            const int kc = ks * 16 + c0;
            __half2 Blo = S2[(srowB * SPITCH_H + kc) >> 1];
            __half2 Bhi = S2[(srowB * SPITCH_H + kc + 8) >> 1];
            uint32_t afrag[2][4];
#pragma unroll
            for (int mt = 0; mt < 2; ++mt)
#pragma unroll
                for (int hf = 0; hf < 2; ++hf) {
                    int srow = sa_row0 + mt * 2 + hf;
                    __half2 Alo = S2[(srow * SPITCH_H + kc) >> 1];
                    __half2 Ahi = S2[(srow * SPITCH_H + kc + 8) >> 1];
                    __half2 x0 = __hmax2(__hadd2(Alo, Blo), z2);
                    __half2 x1 = __hmax2(__hadd2(Ahi, Bhi), z2);
                    afrag[mt][hf] = *(uint32_t*)&x0;
                    afrag[mt][hf + 2] = *(uint32_t*)&x1;
                }
            const uint32_t wa = sbase + SM_W + (uint32_t)(ks * 16 + blane) * WPITCH
                              + (uint32_t)jt0 * 16;
#pragma unroll
            for (int nt = 0; nt < 5; ++nt) {
                uint32_t br0, br1;
                ldsm_x2t(wa + nt * 16, br0, br1);
                mma16816(acc[0][nt], afrag[0], br0, br1);
                mma16816(acc[1][nt], afrag[1], br0, br1);
            }
        }

        if (t + 148 < 1024) {
            int tn = t + 148;
            int bin = tn >> 9, remn = tn & 511;
            int a0n = (remn >> 5) << 4, b0n = (remn & 31) << 3;
            pf0 = stage_ld(tid, bin, a0n, b0n);
            pf1 = stage_ld(tid + 768, bin, a0n, b0n);
        }

        float vs[2][2];
#pragma unroll
        for (int mt = 0; mt < 2; ++mt) {
            float s0 = 0.f, s1 = 0.f;
#pragma unroll
            for (int nt = 0; nt < 5; ++nt) {
                int j = (jt0 + nt) * 8 + c0;
                float w0 = W3s[j], w1 = W3s[j + 1];
                float bb0 = b2s[j], bb1 = b2s[j + 1];
                s0 += fmaxf(acc[mt][nt][0] + bb0, 0.f) * w0 + fmaxf(acc[mt][nt][1] + bb1, 0.f) * w1;
                s1 += fmaxf(acc[mt][nt][2] + bb0, 0.f) * w0 + fmaxf(acc[mt][nt][3] + bb1, 0.f) * w1;
            }
            s0 += __shfl_xor_sync(0xffffffffu, s0, 1);
            s0 += __shfl_xor_sync(0xffffffffu, s0, 2);
            s1 += __shfl_xor_sync(0xffffffffu, s1, 1);
            s1 += __shfl_xor_sync(0xffffffffu, s1, 2);
            vs[mt][0] = s0; vs[mt][1] = s1;
        }
        if (tq == 0) {
#pragma unroll
            for (int mt = 0; mt < 2; ++mt)
#pragma unroll
                for (int hf = 0; hf < 2; ++hf)
                    vp[hh * 256 + side * 128 + mbase + mt * 16 + hf * 8 + g] = vs[mt][hf];
        }
        __syncthreads();
        if (tid < 128) {
            float v1 = vp[tid] + vp[256 + tid] + vp[512 + tid];
            float v2 = vp[128 + tid] + vp[384 + tid] + vp[640 + tid];
            float s = 0.5f * (v1 + v2) + b3;
            float sp = fmaxf(s, 0.f) + log1pf(expf(-fabsf(s)));
            g_R2[(bi * NA + a0 + (tid >> 3)) * NB + b0 + (tid & 7)] = sp * sp;
        }
    }
}

// =========================================================================
// K46: fused pointnet tail + flow. Pointnet loops: float4 weights + 4 chains.
// =========================================================================
__global__ void k46(const float* __restrict__ W1, const float* __restrict__ b1,
                    const float* __restrict__ W2, const float* __restrict__ b2,
                    const float* __restrict__ W3, const float* __restrict__ b3,
                    const float* __restrict__ W4, const float* __restrict__ b4,
                    const float* __restrict__ hW,
                    const float* __restrict__ anch, const float* __restrict__ actp,
                    float* __restrict__ out) {
    int t = threadIdx.x;
    if (blockIdx.x < 64) {
        int bi = blockIdx.x >> 5, n0 = (blockIdx.x & 31) * 8;
        int nn = t & 7, og = t >> 3;
        __shared__ float ya[64 * 8];
        __shared__ float yb[64 * 8];
        __shared__ float yc[128 * 8];
        __shared__ float part[32 * 8];

        for (int f = t; f < 512; f += 256) {
            int i = f >> 3, nn2 = f & 7;
            ya[f] = g_y1[(bi * 64 + i) * NA + n0 + nn2];
        }
        __syncthreads();
        // L1: 64 -> 64 (float4 weights, 4 chains)
        for (int o = og; o < 64; o += 32) {
            float a0 = b1[o], a1 = 0.f, a2 = 0.f, a3 = 0.f;
            const float4* wr = (const float4*)&W1[o * 64];
#pragma unroll
            for (int i = 0; i < 64; i += 4) {
                float4 w = wr[i >> 2];
                a0 = fmaf(w.x, ya[i * 8 + nn], a0);
                a1 = fmaf(w.y, ya[(i + 1) * 8 + nn], a1);
                a2 = fmaf(w.z, ya[(i + 2) * 8 + nn], a2);
                a3 = fmaf(w.w, ya[(i + 3) * 8 + nn], a3);
            }
            yb[o * 8 + nn] = fmaxf((a0 + a1) + (a2 + a3), 0.f);
        }
        __syncthreads();
        // L2: 64 -> 64
        for (int o = og; o < 64; o += 32) {
            float a0 = b2[o], a1 = 0.f, a2 = 0.f, a3 = 0.f;
            const float4* wr = (const float4*)&W2[o * 64];
#pragma unroll
            for (int i = 0; i < 64; i += 4) {
                float4 w = wr[i >> 2];
                a0 = fmaf(w.x, yb[i * 8 + nn], a0);
                a1 = fmaf(w.y, yb[(i + 1) * 8 + nn], a1);
                a2 = fmaf(w.z, yb[(i + 2) * 8 + nn], a2);
                a3 = fmaf(w.w, yb[(i + 3) * 8 + nn], a3);
            }
            ya[o * 8 + nn] = fmaxf((a0 + a1) + (a2 + a3), 0.f);
        }
        __syncthreads();
        // L3: 64 -> 128
        for (int o = og; o < 128; o += 32) {
            float a0 = b3[o], a1 = 0.f, a2 = 0.f, a3 = 0.f;
            const float4* wr = (const float4*)&W3[o * 64];
#pragma unroll
            for (int i = 0; i < 64; i += 4) {
                float4 w = wr[i >> 2];
                a0 = fmaf(w.x, ya[i * 8 + nn], a0);
                a1 = fmaf(w.y, ya[(i + 1) * 8 + nn], a1);
                a2 = fmaf(w.z, ya[(i + 2) * 8 + nn], a2);
                a3 = fmaf(w.w, ya[(i + 3) * 8 + nn], a3);
            }
            yc[o * 8 + nn] = fmaxf((a0 + a1) + (a2 + a3), 0.f);
        }
        __syncthreads();
        // L4 (128 -> 512) + head
        float wp = 0.f;
        for (int o = og; o < 512; o += 32) {
            float a0 = b4[o], a1 = 0.f, a2 = 0.f, a3 = 0.f;
            const float4* wr = (const float4*)&W4[o * 128];
#pragma unroll
            for (int i = 0; i < 128; i += 4) {
                float4 w = wr[i >> 2];
                a0 = fmaf(w.x, yc[i * 8 + nn], a0);
                a1 = fmaf(w.y, yc[(i + 1) * 8 + nn], a1);
                a2 = fmaf(w.z, yc[(i + 2) * 8 + nn], a2);
                a3 = fmaf(w.w, yc[(i + 3) * 8 + nn], a3);
            }
            wp = fmaf(hW[o], fmaxf((a0 + a1) + (a2 + a3), 0.f), wp);
        }
        part[og * 8 + nn] = wp;
        __syncthreads();
        for (int s = 16; s; s >>= 1) {
            if (og < s) part[og * 8 + nn] += part[(og + s) * 8 + nn];
            __syncthreads();
        }
        if (og == 0) out[bi * 4 * NA + 3 * NA + n0 + nn] = part[nn];
        return;
    }
    // ---- flow: 4 anchors per block ----
    {
        int bl = blockIdx.x - 64;
        int bi = bl >> 6;
        int sub = t >> 6;
        int tt = t & 63;
        int a = (bl & 63) * 4 + sub;
        __shared__ float sx[256], sy[256], sz[256];
        const float* geo = g_geo + bi * 16;
        float q0 = geo[9], q1 = geo[10], q2 = geo[11];
        const float* ap = anch + bi * 3 * NB;
        const float* r2row = g_R2 + (bi * NA + a) * NB;
        float s0 = 0.f, s1 = 0.f, s2 = 0.f;
        for (int b = tt; b < NB; b += 64) {
            float r2 = r2row[b];
            s0 += 2.f * (ap[b] - q0) * r2;
            s1 += 2.f * (ap[NB + b] - q1) * r2;
            s2 += 2.f * (ap[2 * NB + b] - q2) * r2;
        }
        int base = sub * 64;
        sx[base + tt] = s0; sy[base + tt] = s1; sz[base + tt] = s2;
        __syncthreads();
        for (int s = 32; s; s >>= 1) {
            if (tt < s) {
                sx[base + tt] += sx[base + tt + s];
                sy[base + tt] += sy[base + tt + s];
                sz[base + tt] += sz[base + tt + s];
            }
            __syncthreads();
        }
        if (tt == 0) {
            float r0 = geo[6] - sx[base], r1 = geo[7] - sy[base], r2_ = geo[8] - sz[base];
            float p0 = geo[0] * r0 + geo[1] * r1 + geo[2] * r2_;
            float p1 = geo[1] * r0 + geo[3] * r1 + geo[4] * r2_;
            float p2 = geo[2] * r0 + geo[4] * r1 + geo[5] * r2_;
            const float* app = actp + bi * 3 * NA;
            out[bi * 4 * NA + 0 * NA + a] = p0 - app[a];
            out[bi * 4 * NA + 1 * NA + a] = p1 - app[NA + a];
            out[bi * 4 * NA + 2 * NA + a] = p2 - app[2 * NA + a];
        }
    }
}

// =========================================================================
extern "C" void kernel_launch(void* const* d_in, const int* in_sizes, int n_in,
                              void* d_out, int out_size) {
    const float* actE  = (const float*)d_in[0];
    const float* anchE = (const float*)d_in[1];
    const float* actP  = (const float*)d_in[2];
    const float* anchP = (const float*)d_in[3];
    const float* W1    = (const float*)d_in[4];
    const float* b1    = (const float*)d_in[5];
    const float* W2    = (const float*)d_in[6];
    const float* b2    = (const float*)d_in[7];
    const float* W3    = (const float*)d_in[8];
    const float* b3    = (const float*)d_in[9];
    const float* pnW0  = (const float*)d_in[10];
    const float* pnb0  = (const float*)d_in[11];
    const float* pnW1  = (const float*)d_in[12];
    const float* pnb1  = (const float*)d_in[13];
    const float* pnW2  = (const float*)d_in[14];
    const float* pnb2  = (const float*)d_in[15];
    const float* pnW3  = (const float*)d_in[16];
    const float* pnb3  = (const float*)d_in[17];
    const float* pnW4  = (const float*)d_in[18];
    const float* pnb4  = (const float*)d_in[19];
    const float* headW = (const float*)d_in[20];
    float* out = (float*)d_out;

    cudaFuncSetAttribute(k2_hmma, cudaFuncAttributeMaxDynamicSharedMemorySize, SM_TOTAL);

    kp_prep<<<160, 256>>>(W2, actE, pnW0, pnb0, anchP);
    k1_h<<<dim3(5, 4, 8), dim3(16, 16)>>>(actE, anchE, W1, b1);
    k2_hmma<<<148, 768, SM_TOTAL>>>(b2, W3, b3);
    k46<<<192, 256>>>(pnW1, pnb1, pnW2, pnb2, pnW3, pnb3, pnW4, pnb4, headW,
                      anchP, actP, out);
}

// round 13
// speedup vs baseline: 4.1567x; 1.0408x over previous
#include <cuda_runtime.h>
#include <cuda_fp16.h>
#include <cstdint>

// Problem constants
#define BATCH 2
#define NA 256
#define NB 256
#define EDIM 512
#define H1 300
#define H2 100
#define HP 304   // fp16 row pitch for h matrices (38 uint4 per row)

// ---------------- scratch (device globals; no allocation) ----------------
__device__ __half g_hAa[BATCH * NA * HP];
__device__ __half g_hAb[BATCH * NA * HP];
__device__ __half g_hBa[BATCH * NB * HP];
__device__ __half g_hBb[BATCH * NB * HP];
__device__ float g_R2[BATCH * NA * NB];
__device__ float g_geo[BATCH * 16];
__device__ float g_y1[BATCH * 64 * NA];
__device__ __half g_Wimg[320 * 120];   // W2 fp16 image, pitch 240 B, zero padded

// ---------------- helpers (baseline PTX only) ----------------------------
__device__ __forceinline__ uint32_t smem_u32(const void* p) {
    uint32_t a;
    asm("{ .reg .u64 t; cvta.to.shared.u64 t, %1; cvt.u32.u64 %0, t; }" : "=r"(a) : "l"(p));
    return a;
}
__device__ __forceinline__ void ldsm_x2t(uint32_t addr, uint32_t& r0, uint32_t& r1) {
    asm volatile("ldmatrix.sync.aligned.m8n8.x2.trans.shared.b16 {%0,%1}, [%2];"
                 : "=r"(r0), "=r"(r1) : "r"(addr));
}
__device__ __forceinline__ void mma16816(float* c, const uint32_t* a, uint32_t b0, uint32_t b1) {
    asm volatile("mma.sync.aligned.m16n8k16.row.col.f32.f16.f16.f32 "
                 "{%0,%1,%2,%3}, {%4,%5,%6,%7}, {%8,%9}, {%0,%1,%2,%3};"
                 : "+f"(c[0]), "+f"(c[1]), "+f"(c[2]), "+f"(c[3])
                 : "r"(a[0]), "r"(a[1]), "r"(a[2]), "r"(a[3]), "r"(b0), "r"(b1));
}

// smem layout for k2 (byte offsets; all 16B aligned)
#define WPITCH   240
#define SPITCH_H 328           // stage pitch in halves (656 B)
#define SM_W     0             // 320*240 = 76800
#define SM_S     76800         // 48*656 = 31488 -> 108288
#define SM_B2    108288        // 128 floats -> 108800
#define SM_W3    108800        // 128 floats -> 109312
#define SM_VP    109312        // 3*256 floats = 3072 -> 112384
#define SM_TOTAL 112384

// =========================================================================
// KP: fused prep. Blocks 0..149: W2 -> fp16 image. Blocks 150..157: pointnet
// layer0 GEMM. Blocks 158..159: per-batch geometry.
// =========================================================================
__global__ void kp_prep(const float* __restrict__ W2,
                        const float* __restrict__ actE, const float* __restrict__ W0,
                        const float* __restrict__ b0, const float* __restrict__ anch) {
    if (blockIdx.x < 150) {
        int idx = blockIdx.x * 256 + threadIdx.x;
        if (idx >= 320 * 120) return;
        int k = idx / 120, n = idx % 120;
        float w = (k < H1 && n < H2) ? W2[k * H2 + n] : 0.f;
        g_Wimg[idx] = __float2half(w);
        return;
    }
    if (blockIdx.x < 158) {
        int bl = blockIdx.x - 150;
        int bi = bl >> 2;
        int n0 = (bl & 3) * 64;
        const float* x = actE + bi * EDIM * NA;
        int tid = threadIdx.x;
        int tx = tid & 15, ty = tid >> 4;
        __shared__ float As[16][64];
        __shared__ float Bs[16][64];
        float acc[4][4];
#pragma unroll
        for (int i = 0; i < 4; ++i)
#pragma unroll
            for (int j = 0; j < 4; ++j) acc[i][j] = 0.f;
        int o_l = tid & 63;
        int k4 = (tid >> 6) * 4;
        int lkk = tid / 16, l4 = (tid % 16) * 4;
        for (int k0 = 0; k0 < EDIM; k0 += 16) {
            __syncthreads();
            float4 w = *(const float4*)&W0[o_l * EDIM + k0 + k4];
            As[k4 + 0][o_l] = w.x; As[k4 + 1][o_l] = w.y;
            As[k4 + 2][o_l] = w.z; As[k4 + 3][o_l] = w.w;
            *(float4*)&Bs[lkk][l4] = *(const float4*)&x[(k0 + lkk) * NA + n0 + l4];
            __syncthreads();
#pragma unroll
            for (int kk = 0; kk < 16; ++kk) {
                float av[4], bv[4];
#pragma unroll
                for (int i = 0; i < 4; ++i) av[i] = As[kk][ty * 4 + i];
#pragma unroll
                for (int j = 0; j < 4; ++j) bv[j] = Bs[kk][tx * 4 + j];
#pragma unroll
                for (int i = 0; i < 4; ++i)
#pragma unroll
                    for (int j = 0; j < 4; ++j) acc[i][j] = fmaf(av[i], bv[j], acc[i][j]);
            }
        }
#pragma unroll
        for (int i = 0; i < 4; ++i) {
            int o = ty * 4 + i;
            float bb = b0[o];
#pragma unroll
            for (int j = 0; j < 4; ++j) {
                int n = n0 + tx * 4 + j;
                g_y1[(bi * 64 + o) * NA + n] = fmaxf(acc[i][j] + bb, 0.f);
            }
        }
        return;
    }
    // ---- geometry ----
    {
        int bi = blockIdx.x - 158, t = threadIdx.x;
        __shared__ float buf[9 * 256];
        __shared__ float q[3];
        const float* ap = anch + bi * 3 * NB;
        float px = ap[t], py = ap[NB + t], pz = ap[2 * NB + t];
        buf[t] = px; buf[256 + t] = py; buf[512 + t] = pz;
        __syncthreads();
        for (int s = 128; s; s >>= 1) {
            if (t < s)
                for (int cc = 0; cc < 3; ++cc) buf[cc * 256 + t] += buf[cc * 256 + t + s];
            __syncthreads();
        }
        if (t == 0) { q[0] = buf[0] / NB; q[1] = buf[256] / NB; q[2] = buf[512] / NB; }
        __syncthreads();
        float ax = 2.f * (px - q[0]), ay = 2.f * (py - q[1]), az = 2.f * (pz - q[2]);
        float cv = px * px + py * py + pz * pz;
        buf[t] = ax * ax;          buf[256 + t] = ax * ay;   buf[512 + t] = ax * az;
        buf[768 + t] = ay * ay;    buf[1024 + t] = ay * az;  buf[1280 + t] = az * az;
        buf[1536 + t] = ax * cv;   buf[1792 + t] = ay * cv;  buf[2048 + t] = az * cv;
        __syncthreads();
        for (int s = 128; s; s >>= 1) {
            if (t < s)
                for (int cc = 0; cc < 9; ++cc) buf[cc * 256 + t] += buf[cc * 256 + t + s];
            __syncthreads();
        }
        if (t == 0) {
            float m00 = buf[0], m01 = buf[256], m02 = buf[512];
            float m11 = buf[768], m12 = buf[1024], m22 = buf[1280];
            float det = m00 * (m11 * m22 - m12 * m12) - m01 * (m01 * m22 - m12 * m02)
                      + m02 * (m01 * m12 - m11 * m02);
            float inv = 1.f / det;
            float* geo = g_geo + bi * 16;
            geo[0] = (m11 * m22 - m12 * m12) * inv;
            geo[1] = (m02 * m12 - m01 * m22) * inv;
            geo[2] = (m01 * m12 - m02 * m11) * inv;
            geo[3] = (m00 * m22 - m02 * m02) * inv;
            geo[4] = (m02 * m01 - m00 * m12) * inv;
            geo[5] = (m00 * m11 - m01 * m01) * inv;
            geo[6] = buf[1536]; geo[7] = buf[1792]; geo[8] = buf[2048];
            geo[9] = q[0]; geo[10] = q[1]; geo[11] = q[2];
        }
    }
}

// =========================================================================
// K1: h matrices (fp32 SIMT GEMM) -> fp16 output, pitch 304, zero pad.
// =========================================================================
__global__ void k1_h(const float* __restrict__ actE, const float* __restrict__ anchE,
                     const float* __restrict__ W1, const float* __restrict__ b1) {
    int bi   = blockIdx.z & 1;
    int src  = (blockIdx.z >> 1) & 1;
    int half = blockIdx.z >> 2;
    const float* emb = (src ? anchE : actE) + bi * EDIM * NA;
    __half* outp = (half == 0 ? (src ? g_hBa : g_hAa) : (src ? g_hBb : g_hAb)) + bi * NA * HP;

    int n0 = blockIdx.y * 64;
    int j0 = blockIdx.x * 64;
    int tx = threadIdx.x, ty = threadIdx.y;
    int tid = ty * 16 + tx;

    __shared__ float As[16 * 64];
    __shared__ float Bs[16 * 64];

    float acc[4][4];
#pragma unroll
    for (int i = 0; i < 4; ++i)
#pragma unroll
        for (int j = 0; j < 4; ++j) acc[i][j] = 0.f;

    int wbase = half * 512;
    int lkk = tid / 16;
    int l4  = (tid % 16) * 4;

    for (int k0 = 0; k0 < EDIM; k0 += 16) {
        __syncthreads();
        *(float4*)&As[lkk * 64 + l4] = *(const float4*)&emb[(k0 + lkk) * NA + n0 + l4];
        {
            int jg = j0 + l4;
            float4 bv = make_float4(0.f, 0.f, 0.f, 0.f);
            if (jg < H1) bv = *(const float4*)&W1[(wbase + k0 + lkk) * H1 + jg];
            *(float4*)&Bs[lkk * 64 + l4] = bv;
        }
        __syncthreads();
#pragma unroll
        for (int kk = 0; kk < 16; ++kk) {
            float4 a4 = *(const float4*)&As[kk * 64 + ty * 4];
            float4 b4 = *(const float4*)&Bs[kk * 64 + tx * 4];
            float av[4] = {a4.x, a4.y, a4.z, a4.w};
            float bv[4] = {b4.x, b4.y, b4.z, b4.w};
#pragma unroll
            for (int i = 0; i < 4; ++i)
#pragma unroll
                for (int j = 0; j < 4; ++j) acc[i][j] = fmaf(av[i], bv[j], acc[i][j]);
        }
    }
#pragma unroll
    for (int i = 0; i < 4; ++i) {
        int n = n0 + ty * 4 + i;
#pragma unroll
        for (int j = 0; j < 4; ++j) {
            int jg = j0 + tx * 4 + j;
            if (jg < H1) {
                float v = acc[i][j];
                if (half == 0) v += b1[jg];
                outp[n * HP + jg] = __float2half(v);
            } else if (jg < HP) {
                outp[n * HP + jg] = __float2half(0.f);
            }
        }
    }
}

// =========================================================================
// K2: PERSISTENT pair-MLP tensor GEMM, fp16, software-pipelined stage.
// (unchanged — validated at 4.1e-6)
// =========================================================================
__device__ __forceinline__ uint4 stage_ld(int idx, int bi, int a0, int b0) {
    int row = idx / 41, i = idx % 41;
    if (i >= 38) return make_uint4(0u, 0u, 0u, 0u);
    const uint4* srcp;
    int gr;
    if (row < 16)      { srcp = (const uint4*)g_hAa; gr = bi * NA + a0 + row; }
    else if (row < 32) { srcp = (const uint4*)g_hAb; gr = bi * NA + a0 + row - 16; }
    else if (row < 40) { srcp = (const uint4*)g_hBb; gr = bi * NB + b0 + row - 32; }
    else               { srcp = (const uint4*)g_hBa; gr = bi * NB + b0 + row - 40; }
    return srcp[gr * 38 + i];
}

__global__ void __launch_bounds__(768, 1) k2_hmma(const float* __restrict__ b2,
                                                  const float* __restrict__ W3,
                                                  const float* __restrict__ b3p) {
    extern __shared__ char smem[];
    const uint32_t sbase = smem_u32(smem);
    const int tid = threadIdx.x;
    const int wid = tid >> 5;
    const int lane = tid & 31;

    const int rg = wid / 6;
    const int r6 = wid % 6;
    const int side = r6 / 3;
    const int hh = r6 % 3;
    const int mbase = rg * 32;
    const int jt0 = hh * 5;
    const int g = lane >> 2;
    const int tq = lane & 3;
    const int c0 = tq * 2;
    const int blane = lane & 15;

    if (tid < 128) {
        *(float*)(smem + SM_B2 + tid * 4) = (tid < H2) ? b2[tid] : 0.f;
        *(float*)(smem + SM_W3 + tid * 4) = (tid < H2) ? W3[tid] : 0.f;
    }
    {
        uint4* dst = (uint4*)(smem + SM_W);
        const uint4* src = (const uint4*)g_Wimg;
        for (int i = tid; i < 4800; i += 768) dst[i] = src[i];
    }

    const float b3 = b3p[0];
    const float* b2s = (const float*)(smem + SM_B2);
    const float* W3s = (const float*)(smem + SM_W3);
    float* vp = (float*)(smem + SM_VP);

    const int srowB = 32 + side * 8 + g;
    const int sa_row0 = side * 16 + rg * 4;
    const __half2 z2 = __float2half2_rn(0.f);

    uint4 pf0, pf1;
    {
        int t0 = blockIdx.x;
        if (t0 < 1024) {
            int bi = t0 >> 9, rem = t0 & 511;
            int a0 = (rem >> 5) << 4, b0 = (rem & 31) << 3;
            pf0 = stage_ld(tid, bi, a0, b0);
            pf1 = stage_ld(tid + 768, bi, a0, b0);
        }
    }
    __syncthreads();

#pragma unroll 1
    for (int t = blockIdx.x; t < 1024; t += 148) {
        const int bi = t >> 9;
        const int rem = t & 511;
        const int a0 = (rem >> 5) << 4;
        const int b0 = (rem & 31) << 3;

        {
            int row0 = tid / 41, i0 = tid % 41;
            *(uint4*)(smem + SM_S + row0 * 656 + i0 * 16) = pf0;
            int idx1 = tid + 768;
            int row1 = idx1 / 41, i1 = idx1 % 41;
            *(uint4*)(smem + SM_S + row1 * 656 + i1 * 16) = pf1;
            int idx2 = tid + 1536;
            if (idx2 < 1968) {
                uint4 v = stage_ld(idx2, bi, a0, b0);
                int row2 = idx2 / 41, i2 = idx2 % 41;
                *(uint4*)(smem + SM_S + row2 * 656 + i2 * 16) = v;
            }
        }
        __syncthreads();

        float acc[2][5][4];
#pragma unroll
        for (int mt = 0; mt < 2; ++mt)
#pragma unroll
            for (int n = 0; n < 5; ++n)
#pragma unroll
                for (int q = 0; q < 4; ++q) acc[mt][n][q] = 0.f;

        const __half2* S2 = (const __half2*)(smem + SM_S);

#pragma unroll 1
        for (int ks = 0; ks < 20; ++ks) {
            const int kc = ks * 16 + c0;
            __half2 Blo = S2[(srowB * SPITCH_H + kc) >> 1];
            __half2 Bhi = S2[(srowB * SPITCH_H + kc + 8) >> 1];
            uint32_t afrag[2][4];
#pragma unroll
            for (int mt = 0; mt < 2; ++mt)
#pragma unroll
                for (int hf = 0; hf < 2; ++hf) {
                    int srow = sa_row0 + mt * 2 + hf;
                    __half2 Alo = S2[(srow * SPITCH_H + kc) >> 1];
                    __half2 Ahi = S2[(srow * SPITCH_H + kc + 8) >> 1];
                    __half2 x0 = __hmax2(__hadd2(Alo, Blo), z2);
                    __half2 x1 = __hmax2(__hadd2(Ahi, Bhi), z2);
                    afrag[mt][hf] = *(uint32_t*)&x0;
                    afrag[mt][hf + 2] = *(uint32_t*)&x1;
                }
            const uint32_t wa = sbase + SM_W + (uint32_t)(ks * 16 + blane) * WPITCH
                              + (uint32_t)jt0 * 16;
#pragma unroll
            for (int nt = 0; nt < 5; ++nt) {
                uint32_t br0, br1;
                ldsm_x2t(wa + nt * 16, br0, br1);
                mma16816(acc[0][nt], afrag[0], br0, br1);
                mma16816(acc[1][nt], afrag[1], br0, br1);
            }
        }

        if (t + 148 < 1024) {
            int tn = t + 148;
            int bin = tn >> 9, remn = tn & 511;
            int a0n = (remn >> 5) << 4, b0n = (remn & 31) << 3;
            pf0 = stage_ld(tid, bin, a0n, b0n);
            pf1 = stage_ld(tid + 768, bin, a0n, b0n);
        }

        float vs[2][2];
#pragma unroll
        for (int mt = 0; mt < 2; ++mt) {
            float s0 = 0.f, s1 = 0.f;
#pragma unroll
            for (int nt = 0; nt < 5; ++nt) {
                int j = (jt0 + nt) * 8 + c0;
                float w0 = W3s[j], w1 = W3s[j + 1];
                float bb0 = b2s[j], bb1 = b2s[j + 1];
                s0 += fmaxf(acc[mt][nt][0] + bb0, 0.f) * w0 + fmaxf(acc[mt][nt][1] + bb1, 0.f) * w1;
                s1 += fmaxf(acc[mt][nt][2] + bb0, 0.f) * w0 + fmaxf(acc[mt][nt][3] + bb1, 0.f) * w1;
            }
            s0 += __shfl_xor_sync(0xffffffffu, s0, 1);
            s0 += __shfl_xor_sync(0xffffffffu, s0, 2);
            s1 += __shfl_xor_sync(0xffffffffu, s1, 1);
            s1 += __shfl_xor_sync(0xffffffffu, s1, 2);
            vs[mt][0] = s0; vs[mt][1] = s1;
        }
        if (tq == 0) {
#pragma unroll
            for (int mt = 0; mt < 2; ++mt)
#pragma unroll
                for (int hf = 0; hf < 2; ++hf)
                    vp[hh * 256 + side * 128 + mbase + mt * 16 + hf * 8 + g] = vs[mt][hf];
        }
        __syncthreads();
        if (tid < 128) {
            float v1 = vp[tid] + vp[256 + tid] + vp[512 + tid];
            float v2 = vp[128 + tid] + vp[384 + tid] + vp[640 + tid];
            float s = 0.5f * (v1 + v2) + b3;
            float sp = fmaxf(s, 0.f) + log1pf(expf(-fabsf(s)));
            g_R2[(bi * NA + a0 + (tid >> 3)) * NB + b0 + (tid & 7)] = sp * sp;
        }
    }
}

// =========================================================================
// K46: fused pointnet tail + flow, 512 threads.
// Pointnet blocks 0..63: ONE THREAD PER NEURON o computing all 8 n-cols
// (W rows loaded once per block; ya reads are warp-broadcast LDS).
// Flow blocks 64..127: 8 anchors per block in 64-thread groups.
// =========================================================================
__device__ __forceinline__ void layer_oi(const float* __restrict__ Wrow,
                                         const float* __restrict__ ys, int K,
                                         float* acc) {
#pragma unroll 4
    for (int i = 0; i < K; i += 4) {
        float4 w = *(const float4*)(Wrow + i);
#pragma unroll
        for (int u = 0; u < 4; ++u) {
            float wv = (&w.x)[u];
            const float* y = ys + (i + u) * 8;
            float4 p = *(const float4*)y;
            float4 q = *(const float4*)(y + 4);
            acc[0] = fmaf(wv, p.x, acc[0]); acc[1] = fmaf(wv, p.y, acc[1]);
            acc[2] = fmaf(wv, p.z, acc[2]); acc[3] = fmaf(wv, p.w, acc[3]);
            acc[4] = fmaf(wv, q.x, acc[4]); acc[5] = fmaf(wv, q.y, acc[5]);
            acc[6] = fmaf(wv, q.z, acc[6]); acc[7] = fmaf(wv, q.w, acc[7]);
        }
    }
}

__global__ void __launch_bounds__(512) k46(
                    const float* __restrict__ W1, const float* __restrict__ b1,
                    const float* __restrict__ W2, const float* __restrict__ b2,
                    const float* __restrict__ W3, const float* __restrict__ b3,
                    const float* __restrict__ W4, const float* __restrict__ b4,
                    const float* __restrict__ hW,
                    const float* __restrict__ anch, const float* __restrict__ actp,
                    float* __restrict__ out) {
    int t = threadIdx.x;
    if (blockIdx.x < 64) {
        int bi = blockIdx.x >> 5, n0 = (blockIdx.x & 31) * 8;
        __shared__ __align__(16) float ya[64 * 8];
        __shared__ __align__(16) float yb[64 * 8];
        __shared__ __align__(16) float yc[128 * 8];
        __shared__ float red[8 * 512];   // [nn][o] transposed -> conflict-free

        // load ya: thread t -> (i = t>>3, nn = t&7)
        ya[t] = g_y1[(bi * 64 + (t >> 3)) * NA + n0 + (t & 7)];
        __syncthreads();
        // L1: threads 0..63, o = t
        if (t < 64) {
            float acc[8];
            float bb = b1[t];
#pragma unroll
            for (int nn = 0; nn < 8; ++nn) acc[nn] = bb;
            layer_oi(&W1[t * 64], ya, 64, acc);
#pragma unroll
            for (int nn = 0; nn < 8; ++nn) yb[t * 8 + nn] = fmaxf(acc[nn], 0.f);
        }
        __syncthreads();
        // L2: threads 0..63
        if (t < 64) {
            float acc[8];
            float bb = b2[t];
#pragma unroll
            for (int nn = 0; nn < 8; ++nn) acc[nn] = bb;
            layer_oi(&W2[t * 64], yb, 64, acc);
#pragma unroll
            for (int nn = 0; nn < 8; ++nn) ya[t * 8 + nn] = fmaxf(acc[nn], 0.f);
        }
        __syncthreads();
        // L3: threads 0..127
        if (t < 128) {
            float acc[8];
            float bb = b3[t];
#pragma unroll
            for (int nn = 0; nn < 8; ++nn) acc[nn] = bb;
            layer_oi(&W3[t * 64], ya, 64, acc);
#pragma unroll
            for (int nn = 0; nn < 8; ++nn) yc[t * 8 + nn] = fmaxf(acc[nn], 0.f);
        }
        __syncthreads();
        // L4 + head: all 512 threads, o = t
        {
            float acc[8];
            float bb = b4[t];
#pragma unroll
            for (int nn = 0; nn < 8; ++nn) acc[nn] = bb;
            layer_oi(&W4[t * 128], yc, 128, acc);
            float hw = hW[t];
#pragma unroll
            for (int nn = 0; nn < 8; ++nn)
                red[nn * 512 + t] = hw * fmaxf(acc[nn], 0.f);
        }
        __syncthreads();
        // tree reduction over o (deterministic)
        for (int s = 256; s >= 1; s >>= 1) {
            if (t < s) {
#pragma unroll
                for (int nn = 0; nn < 8; ++nn)
                    red[nn * 512 + t] += red[nn * 512 + t + s];
            }
            __syncthreads();
        }
        if (t < 8) out[bi * 4 * NA + 3 * NA + n0 + t] = red[t * 512];
        return;
    }
    // ---- flow: 8 anchors per block ----
    {
        int bl = blockIdx.x - 64;        // 0..63
        int bi = bl >> 5;
        int sub = t >> 6;                // 0..7
        int tt = t & 63;
        int a = (bl & 31) * 8 + sub;
        __shared__ float sx[512], sy[512], sz[512];
        const float* geo = g_geo + bi * 16;
        float q0 = geo[9], q1 = geo[10], q2 = geo[11];
        const float* ap = anch + bi * 3 * NB;
        const float* r2row = g_R2 + (bi * NA + a) * NB;
        float s0 = 0.f, s1 = 0.f, s2 = 0.f;
        for (int b = tt; b < NB; b += 64) {
            float r2 = r2row[b];
            s0 += 2.f * (ap[b] - q0) * r2;
            s1 += 2.f * (ap[NB + b] - q1) * r2;
            s2 += 2.f * (ap[2 * NB + b] - q2) * r2;
        }
        int base = sub * 64;
        sx[base + tt] = s0; sy[base + tt] = s1; sz[base + tt] = s2;
        __syncthreads();
        for (int s = 32; s; s >>= 1) {
            if (tt < s) {
                sx[base + tt] += sx[base + tt + s];
                sy[base + tt] += sy[base + tt + s];
                sz[base + tt] += sz[base + tt + s];
            }
            __syncthreads();
        }
        if (tt == 0) {
            float r0 = geo[6] - sx[base], r1 = geo[7] - sy[base], r2_ = geo[8] - sz[base];
            float p0 = geo[0] * r0 + geo[1] * r1 + geo[2] * r2_;
            float p1 = geo[1] * r0 + geo[3] * r1 + geo[4] * r2_;
            float p2 = geo[2] * r0 + geo[4] * r1 + geo[5] * r2_;
            const float* app = actp + bi * 3 * NA;
            out[bi * 4 * NA + 0 * NA + a] = p0 - app[a];
            out[bi * 4 * NA + 1 * NA + a] = p1 - app[NA + a];
            out[bi * 4 * NA + 2 * NA + a] = p2 - app[2 * NA + a];
        }
    }
}

// =========================================================================
extern "C" void kernel_launch(void* const* d_in, const int* in_sizes, int n_in,
                              void* d_out, int out_size) {
    const float* actE  = (const float*)d_in[0];
    const float* anchE = (const float*)d_in[1];
    const float* actP  = (const float*)d_in[2];
    const float* anchP = (const float*)d_in[3];
    const float* W1    = (const float*)d_in[4];
    const float* b1    = (const float*)d_in[5];
    const float* W2    = (const float*)d_in[6];
    const float* b2    = (const float*)d_in[7];
    const float* W3    = (const float*)d_in[8];
    const float* b3    = (const float*)d_in[9];
    const float* pnW0  = (const float*)d_in[10];
    const float* pnb0  = (const float*)d_in[11];
    const float* pnW1  = (const float*)d_in[12];
    const float* pnb1  = (const float*)d_in[13];
    const float* pnW2  = (const float*)d_in[14];
    const float* pnb2  = (const float*)d_in[15];
    const float* pnW3  = (const float*)d_in[16];
    const float* pnb3  = (const float*)d_in[17];
    const float* pnW4  = (const float*)d_in[18];
    const float* pnb4  = (const float*)d_in[19];
    const float* headW = (const float*)d_in[20];
    float* out = (float*)d_out;

    cudaFuncSetAttribute(k2_hmma, cudaFuncAttributeMaxDynamicSharedMemorySize, SM_TOTAL);

    kp_prep<<<160, 256>>>(W2, actE, pnW0, pnb0, anchP);
    k1_h<<<dim3(5, 4, 8), dim3(16, 16)>>>(actE, anchE, W1, b1);
    k2_hmma<<<148, 768, SM_TOTAL>>>(b2, W3, b3);
    k46<<<128, 512>>>(pnW1, pnb1, pnW2, pnb2, pnW3, pnb3, pnW4, pnb4, headW,
                      anchP, actP, out);
}

// round 15
// speedup vs baseline: 4.3288x; 1.0414x over previous
#include <cuda_runtime.h>
#include <cuda_fp16.h>
#include <cstdint>

// Problem constants
#define BATCH 2
#define NA 256
#define NB 256
#define EDIM 512
#define H1 300
#define H2 100
#define HP 304   // fp16 row pitch for h matrices (38 uint4 per row)

// ---------------- scratch (device globals; no allocation) ----------------
__device__ __half g_hAa[BATCH * NA * HP];
__device__ __half g_hAb[BATCH * NA * HP];
__device__ __half g_hBa[BATCH * NB * HP];
__device__ __half g_hBb[BATCH * NB * HP];
__device__ float g_R2[BATCH * NA * NB];
__device__ float g_geo[BATCH * 16];
__device__ float g_y1[BATCH * 64 * NA];
__device__ __half g_Wimg[304 * 104];   // W2 fp16 image, pitch 208 B, zero padded

// ---------------- helpers (baseline PTX only) ----------------------------
__device__ __forceinline__ uint32_t smem_u32(const void* p) {
    uint32_t a;
    asm("{ .reg .u64 t; cvta.to.shared.u64 t, %1; cvt.u32.u64 %0, t; }" : "=r"(a) : "l"(p));
    return a;
}
__device__ __forceinline__ void ldsm_x2t(uint32_t addr, uint32_t& r0, uint32_t& r1) {
    asm volatile("ldmatrix.sync.aligned.m8n8.x2.trans.shared.b16 {%0,%1}, [%2];"
                 : "=r"(r0), "=r"(r1) : "r"(addr));
}
__device__ __forceinline__ void mma16816(float* c, const uint32_t* a, uint32_t b0, uint32_t b1) {
    asm volatile("mma.sync.aligned.m16n8k16.row.col.f32.f16.f16.f32 "
                 "{%0,%1,%2,%3}, {%4,%5,%6,%7}, {%8,%9}, {%0,%1,%2,%3};"
                 : "+f"(c[0]), "+f"(c[1]), "+f"(c[2]), "+f"(c[3])
                 : "r"(a[0]), "r"(a[1]), "r"(a[2]), "r"(a[3]), "r"(b0), "r"(b1));
}

// smem layout for k2 (byte offsets; all 16B aligned)
#define WPITCH   208           // 104 fp16 cols per k-row (conflict-free ldsm)
#define SPITCH_H 328           // stage pitch in halves (656 B)
#define SM_W     0             // 304*208 = 63232
#define SM_S     63232         // 48*656 = 31488 -> 94720
#define SM_B2    94720         // 128 floats -> 95232
#define SM_W3    95232         // 128 floats -> 95744
#define SM_VP    95744         // 3*256 floats = 3072 -> 98816
#define SM_TOTAL 98816

#define KSTEPS   19            // ceil(300/16) -> 304 = HP exactly

// =========================================================================
// KP: fused prep. Blocks 0..149: W2 -> fp16 image [304][104]. Blocks
// 150..157: pointnet layer0 GEMM. Blocks 158..159: per-batch geometry.
// =========================================================================
__global__ void kp_prep(const float* __restrict__ W2,
                        const float* __restrict__ actE, const float* __restrict__ W0,
                        const float* __restrict__ b0, const float* __restrict__ anch) {
    if (blockIdx.x < 150) {
        int idx = blockIdx.x * 256 + threadIdx.x;
        if (idx >= 304 * 104) return;
        int k = idx / 104, n = idx % 104;
        float w = (k < H1 && n < H2) ? W2[k * H2 + n] : 0.f;
        g_Wimg[idx] = __float2half(w);
        return;
    }
    if (blockIdx.x < 158) {
        int bl = blockIdx.x - 150;
        int bi = bl >> 2;
        int n0 = (bl & 3) * 64;
        const float* x = actE + bi * EDIM * NA;
        int tid = threadIdx.x;
        int tx = tid & 15, ty = tid >> 4;
        __shared__ float As[16][64];
        __shared__ float Bs[16][64];
        float acc[4][4];
#pragma unroll
        for (int i = 0; i < 4; ++i)
#pragma unroll
            for (int j = 0; j < 4; ++j) acc[i][j] = 0.f;
        int o_l = tid & 63;
        int k4 = (tid >> 6) * 4;
        int lkk = tid / 16, l4 = (tid % 16) * 4;
        for (int k0 = 0; k0 < EDIM; k0 += 16) {
            __syncthreads();
            float4 w = *(const float4*)&W0[o_l * EDIM + k0 + k4];
            As[k4 + 0][o_l] = w.x; As[k4 + 1][o_l] = w.y;
            As[k4 + 2][o_l] = w.z; As[k4 + 3][o_l] = w.w;
            *(float4*)&Bs[lkk][l4] = *(const float4*)&x[(k0 + lkk) * NA + n0 + l4];
            __syncthreads();
#pragma unroll
            for (int kk = 0; kk < 16; ++kk) {
                float av[4], bv[4];
#pragma unroll
                for (int i = 0; i < 4; ++i) av[i] = As[kk][ty * 4 + i];
#pragma unroll
                for (int j = 0; j < 4; ++j) bv[j] = Bs[kk][tx * 4 + j];
#pragma unroll
                for (int i = 0; i < 4; ++i)
#pragma unroll
                    for (int j = 0; j < 4; ++j) acc[i][j] = fmaf(av[i], bv[j], acc[i][j]);
            }
        }
#pragma unroll
        for (int i = 0; i < 4; ++i) {
            int o = ty * 4 + i;
            float bb = b0[o];
#pragma unroll
            for (int j = 0; j < 4; ++j) {
                int n = n0 + tx * 4 + j;
                g_y1[(bi * 64 + o) * NA + n] = fmaxf(acc[i][j] + bb, 0.f);
            }
        }
        return;
    }
    // ---- geometry ----
    {
        int bi = blockIdx.x - 158, t = threadIdx.x;
        __shared__ float buf[9 * 256];
        __shared__ float q[3];
        const float* ap = anch + bi * 3 * NB;
        float px = ap[t], py = ap[NB + t], pz = ap[2 * NB + t];
        buf[t] = px; buf[256 + t] = py; buf[512 + t] = pz;
        __syncthreads();
        for (int s = 128; s; s >>= 1) {
            if (t < s)
                for (int cc = 0; cc < 3; ++cc) buf[cc * 256 + t] += buf[cc * 256 + t + s];
            __syncthreads();
        }
        if (t == 0) { q[0] = buf[0] / NB; q[1] = buf[256] / NB; q[2] = buf[512] / NB; }
        __syncthreads();
        float ax = 2.f * (px - q[0]), ay = 2.f * (py - q[1]), az = 2.f * (pz - q[2]);
        float cv = px * px + py * py + pz * pz;
        buf[t] = ax * ax;          buf[256 + t] = ax * ay;   buf[512 + t] = ax * az;
        buf[768 + t] = ay * ay;    buf[1024 + t] = ay * az;  buf[1280 + t] = az * az;
        buf[1536 + t] = ax * cv;   buf[1792 + t] = ay * cv;  buf[2048 + t] = az * cv;
        __syncthreads();
        for (int s = 128; s; s >>= 1) {
            if (t < s)
                for (int cc = 0; cc < 9; ++cc) buf[cc * 256 + t] += buf[cc * 256 + t + s];
            __syncthreads();
        }
        if (t == 0) {
            float m00 = buf[0], m01 = buf[256], m02 = buf[512];
            float m11 = buf[768], m12 = buf[1024], m22 = buf[1280];
            float det = m00 * (m11 * m22 - m12 * m12) - m01 * (m01 * m22 - m12 * m02)
                      + m02 * (m01 * m12 - m11 * m02);
            float inv = 1.f / det;
            float* geo = g_geo + bi * 16;
            geo[0] = (m11 * m22 - m12 * m12) * inv;
            geo[1] = (m02 * m12 - m01 * m22) * inv;
            geo[2] = (m01 * m12 - m02 * m11) * inv;
            geo[3] = (m00 * m22 - m02 * m02) * inv;
            geo[4] = (m02 * m01 - m00 * m12) * inv;
            geo[5] = (m00 * m11 - m01 * m01) * inv;
            geo[6] = buf[1536]; geo[7] = buf[1792]; geo[8] = buf[2048];
            geo[9] = q[0]; geo[10] = q[1]; geo[11] = q[2];
        }
    }
}

// =========================================================================
// K1: h matrices (fp32 SIMT GEMM) -> fp16 output, pitch 304, zero pad.
// =========================================================================
__global__ void k1_h(const float* __restrict__ actE, const float* __restrict__ anchE,
                     const float* __restrict__ W1, const float* __restrict__ b1) {
    int bi   = blockIdx.z & 1;
    int src  = (blockIdx.z >> 1) & 1;
    int half = blockIdx.z >> 2;
    const float* emb = (src ? anchE : actE) + bi * EDIM * NA;
    __half* outp = (half == 0 ? (src ? g_hBa : g_hAa) : (src ? g_hBb : g_hAb)) + bi * NA * HP;

    int n0 = blockIdx.y * 64;
    int j0 = blockIdx.x * 64;
    int tx = threadIdx.x, ty = threadIdx.y;
    int tid = ty * 16 + tx;

    __shared__ float As[16 * 64];
    __shared__ float Bs[16 * 64];

    float acc[4][4];
#pragma unroll
    for (int i = 0; i < 4; ++i)
#pragma unroll
        for (int j = 0; j < 4; ++j) acc[i][j] = 0.f;

    int wbase = half * 512;
    int lkk = tid / 16;
    int l4  = (tid % 16) * 4;

    for (int k0 = 0; k0 < EDIM; k0 += 16) {
        __syncthreads();
        *(float4*)&As[lkk * 64 + l4] = *(const float4*)&emb[(k0 + lkk) * NA + n0 + l4];
        {
            int jg = j0 + l4;
            float4 bv = make_float4(0.f, 0.f, 0.f, 0.f);
            if (jg < H1) bv = *(const float4*)&W1[(wbase + k0 + lkk) * H1 + jg];
            *(float4*)&Bs[lkk * 64 + l4] = bv;
        }
        __syncthreads();
#pragma unroll
        for (int kk = 0; kk < 16; ++kk) {
            float4 a4 = *(const float4*)&As[kk * 64 + ty * 4];
            float4 b4 = *(const float4*)&Bs[kk * 64 + tx * 4];
            float av[4] = {a4.x, a4.y, a4.z, a4.w};
            float bv[4] = {b4.x, b4.y, b4.z, b4.w};
#pragma unroll
            for (int i = 0; i < 4; ++i)
#pragma unroll
                for (int j = 0; j < 4; ++j) acc[i][j] = fmaf(av[i], bv[j], acc[i][j]);
        }
    }
#pragma unroll
    for (int i = 0; i < 4; ++i) {
        int n = n0 + ty * 4 + i;
#pragma unroll
        for (int j = 0; j < 4; ++j) {
            int jg = j0 + tx * 4 + j;
            if (jg < H1) {
                float v = acc[i][j];
                if (half == 0) v += b1[jg];
                outp[n * HP + jg] = __float2half(v);
            } else if (jg < HP) {
                outp[n * HP + jg] = __float2half(0.f);
            }
        }
    }
}

// =========================================================================
// K2: PERSISTENT pair-MLP tensor GEMM, fp16, 19 k-steps, 13 n-tiles (5/4/4).
// 768 threads (24 warps): warp = (rg 0..3, side 0..1, hh 0..2).
// =========================================================================
__device__ __forceinline__ uint4 stage_ld(int idx, int bi, int a0, int b0) {
    int row = idx / 41, i = idx % 41;
    if (i >= 38) return make_uint4(0u, 0u, 0u, 0u);
    const uint4* srcp;
    int gr;
    if (row < 16)      { srcp = (const uint4*)g_hAa; gr = bi * NA + a0 + row; }
    else if (row < 32) { srcp = (const uint4*)g_hAb; gr = bi * NA + a0 + row - 16; }
    else if (row < 40) { srcp = (const uint4*)g_hBb; gr = bi * NB + b0 + row - 32; }
    else               { srcp = (const uint4*)g_hBa; gr = bi * NB + b0 + row - 40; }
    return srcp[gr * 38 + i];
}

template <int NT>
__device__ __forceinline__ void k2_mainloop(float acc[2][5][4], const __half2* S2,
                                            uint32_t sbase, int srowB, int sa_row0,
                                            int jt0, int blane, int c0) {
    const __half2 z2 = __float2half2_rn(0.f);
#pragma unroll 1
    for (int ks = 0; ks < KSTEPS; ++ks) {
        const int kc = ks * 16 + c0;
        __half2 Blo = S2[(srowB * SPITCH_H + kc) >> 1];
        __half2 Bhi = S2[(srowB * SPITCH_H + kc + 8) >> 1];
        uint32_t afrag[2][4];
#pragma unroll
        for (int mt = 0; mt < 2; ++mt)
#pragma unroll
            for (int hf = 0; hf < 2; ++hf) {
                int srow = sa_row0 + mt * 2 + hf;
                __half2 Alo = S2[(srow * SPITCH_H + kc) >> 1];
                __half2 Ahi = S2[(srow * SPITCH_H + kc + 8) >> 1];
                __half2 x0 = __hmax2(__hadd2(Alo, Blo), z2);
                __half2 x1 = __hmax2(__hadd2(Ahi, Bhi), z2);
                afrag[mt][hf] = *(uint32_t*)&x0;
                afrag[mt][hf + 2] = *(uint32_t*)&x1;
            }
        const uint32_t wa = sbase + SM_W + (uint32_t)(ks * 16 + blane) * WPITCH
                          + (uint32_t)jt0 * 16;
#pragma unroll
        for (int nt = 0; nt < NT; ++nt) {
            uint32_t br0, br1;
            ldsm_x2t(wa + nt * 16, br0, br1);
            mma16816(acc[0][nt], afrag[0], br0, br1);
            mma16816(acc[1][nt], afrag[1], br0, br1);
        }
    }
}

__global__ void __launch_bounds__(768, 1) k2_hmma(const float* __restrict__ b2,
                                                  const float* __restrict__ W3,
                                                  const float* __restrict__ b3p) {
    extern __shared__ char smem[];
    const uint32_t sbase = smem_u32(smem);
    const int tid = threadIdx.x;
    const int wid = tid >> 5;
    const int lane = tid & 31;

    const int rg = wid / 6;
    const int r6 = wid % 6;
    const int side = r6 / 3;
    const int hh = r6 % 3;
    const int mbase = rg * 32;
    const int jt0 = (hh == 0) ? 0 : (1 + 4 * hh);   // 0, 5, 9
    const int NTv = (hh == 0) ? 5 : 4;
    const int g = lane >> 2;
    const int tq = lane & 3;
    const int c0 = tq * 2;
    const int blane = lane & 15;

    if (tid < 128) {
        *(float*)(smem + SM_B2 + tid * 4) = (tid < H2) ? b2[tid] : 0.f;
        *(float*)(smem + SM_W3 + tid * 4) = (tid < H2) ? W3[tid] : 0.f;
    }
    {   // W image -> smem (63232 B = 3952 uint4)
        uint4* dst = (uint4*)(smem + SM_W);
        const uint4* src = (const uint4*)g_Wimg;
        for (int i = tid; i < 3952; i += 768) dst[i] = src[i];
    }

    const float b3 = b3p[0];
    const float* b2s = (const float*)(smem + SM_B2);
    const float* W3s = (const float*)(smem + SM_W3);
    float* vp = (float*)(smem + SM_VP);

    const int srowB = 32 + side * 8 + g;
    const int sa_row0 = side * 16 + rg * 4;

    uint4 pf0, pf1;
    {
        int t0 = blockIdx.x;
        if (t0 < 1024) {
            int bi = t0 >> 9, rem = t0 & 511;
            int a0 = (rem >> 5) << 4, b0 = (rem & 31) << 3;
            pf0 = stage_ld(tid, bi, a0, b0);
            pf1 = stage_ld(tid + 768, bi, a0, b0);
        }
    }
    __syncthreads();

#pragma unroll 1
    for (int t = blockIdx.x; t < 1024; t += 148) {
        const int bi = t >> 9;
        const int rem = t & 511;
        const int a0 = (rem >> 5) << 4;
        const int b0 = (rem & 31) << 3;

        {
            int row0 = tid / 41, i0 = tid % 41;
            *(uint4*)(smem + SM_S + row0 * 656 + i0 * 16) = pf0;
            int idx1 = tid + 768;
            int row1 = idx1 / 41, i1 = idx1 % 41;
            *(uint4*)(smem + SM_S + row1 * 656 + i1 * 16) = pf1;
            int idx2 = tid + 1536;
            if (idx2 < 1968) {
                uint4 v = stage_ld(idx2, bi, a0, b0);
                int row2 = idx2 / 41, i2 = idx2 % 41;
                *(uint4*)(smem + SM_S + row2 * 656 + i2 * 16) = v;
            }
        }
        __syncthreads();

        float acc[2][5][4];
#pragma unroll
        for (int mt = 0; mt < 2; ++mt)
#pragma unroll
            for (int n = 0; n < 5; ++n)
#pragma unroll
                for (int q = 0; q < 4; ++q) acc[mt][n][q] = 0.f;

        const __half2* S2 = (const __half2*)(smem + SM_S);
        if (hh == 0)
            k2_mainloop<5>(acc, S2, sbase, srowB, sa_row0, jt0, blane, c0);
        else
            k2_mainloop<4>(acc, S2, sbase, srowB, sa_row0, jt0, blane, c0);

        if (t + 148 < 1024) {
            int tn = t + 148;
            int bin = tn >> 9, remn = tn & 511;
            int a0n = (remn >> 5) << 4, b0n = (remn & 31) << 3;
            pf0 = stage_ld(tid, bin, a0n, b0n);
            pf1 = stage_ld(tid + 768, bin, a0n, b0n);
        }

        float vs[2][2];
#pragma unroll
        for (int mt = 0; mt < 2; ++mt) {
            float s0 = 0.f, s1 = 0.f;
#pragma unroll
            for (int nt = 0; nt < 5; ++nt) {
                if (nt < NTv) {
                    int j = (jt0 + nt) * 8 + c0;
                    float w0 = W3s[j], w1 = W3s[j + 1];
                    float bb0 = b2s[j], bb1 = b2s[j + 1];
                    s0 += fmaxf(acc[mt][nt][0] + bb0, 0.f) * w0 + fmaxf(acc[mt][nt][1] + bb1, 0.f) * w1;
                    s1 += fmaxf(acc[mt][nt][2] + bb0, 0.f) * w0 + fmaxf(acc[mt][nt][3] + bb1, 0.f) * w1;
                }
            }
            s0 += __shfl_xor_sync(0xffffffffu, s0, 1);
            s0 += __shfl_xor_sync(0xffffffffu, s0, 2);
            s1 += __shfl_xor_sync(0xffffffffu, s1, 1);
            s1 += __shfl_xor_sync(0xffffffffu, s1, 2);
            vs[mt][0] = s0; vs[mt][1] = s1;
        }
        if (tq == 0) {
#pragma unroll
            for (int mt = 0; mt < 2; ++mt)
#pragma unroll
                for (int hf = 0; hf < 2; ++hf)
                    vp[hh * 256 + side * 128 + mbase + mt * 16 + hf * 8 + g] = vs[mt][hf];
        }
        __syncthreads();
        if (tid < 128) {
            float v1 = vp[tid] + vp[256 + tid] + vp[512 + tid];
            float v2 = vp[128 + tid] + vp[384 + tid] + vp[640 + tid];
            float s = 0.5f * (v1 + v2) + b3;
            float sp = fmaxf(s, 0.f) + log1pf(expf(-fabsf(s)));
            g_R2[(bi * NA + a0 + (tid >> 3)) * NB + b0 + (tid & 7)] = sp * sp;
        }
    }
}

// =========================================================================
// K46: fused pointnet tail + flow, 512 threads. Reduction via warp shuffles.
// =========================================================================
__device__ __forceinline__ void layer_oi(const float* __restrict__ Wrow,
                                         const float* __restrict__ ys, int K,
                                         float* acc) {
#pragma unroll 4
    for (int i = 0; i < K; i += 4) {
        float4 w = *(const float4*)(Wrow + i);
#pragma unroll
        for (int u = 0; u < 4; ++u) {
            float wv = (&w.x)[u];
            const float* y = ys + (i + u) * 8;
            float4 p = *(const float4*)y;
            float4 q = *(const float4*)(y + 4);
            acc[0] = fmaf(wv, p.x, acc[0]); acc[1] = fmaf(wv, p.y, acc[1]);
            acc[2] = fmaf(wv, p.z, acc[2]); acc[3] = fmaf(wv, p.w, acc[3]);
            acc[4] = fmaf(wv, q.x, acc[4]); acc[5] = fmaf(wv, q.y, acc[5]);
            acc[6] = fmaf(wv, q.z, acc[6]); acc[7] = fmaf(wv, q.w, acc[7]);
        }
    }
}

__global__ void __launch_bounds__(512) k46(
                    const float* __restrict__ W1, const float* __restrict__ b1,
                    const float* __restrict__ W2, const float* __restrict__ b2,
                    const float* __restrict__ W3, const float* __restrict__ b3,
                    const float* __restrict__ W4, const float* __restrict__ b4,
                    const float* __restrict__ hW,
                    const float* __restrict__ anch, const float* __restrict__ actp,
                    float* __restrict__ out) {
    int t = threadIdx.x;
    if (blockIdx.x < 64) {
        int bi = blockIdx.x >> 5, n0 = (blockIdx.x & 31) * 8;
        __shared__ __align__(16) float ya[64 * 8];
        __shared__ __align__(16) float yb[64 * 8];
        __shared__ __align__(16) float yc[128 * 8];
        __shared__ float red2[128];   // [nn][warp] partials

        ya[t] = g_y1[(bi * 64 + (t >> 3)) * NA + n0 + (t & 7)];
        __syncthreads();
        if (t < 64) {
            float acc[8];
            float bb = b1[t];
#pragma unroll
            for (int nn = 0; nn < 8; ++nn) acc[nn] = bb;
            layer_oi(&W1[t * 64], ya, 64, acc);
#pragma unroll
            for (int nn = 0; nn < 8; ++nn) yb[t * 8 + nn] = fmaxf(acc[nn], 0.f);
        }
        __syncthreads();
        if (t < 64) {
            float acc[8];
            float bb = b2[t];
#pragma unroll
            for (int nn = 0; nn < 8; ++nn) acc[nn] = bb;
            layer_oi(&W2[t * 64], yb, 64, acc);
#pragma unroll
            for (int nn = 0; nn < 8; ++nn) ya[t * 8 + nn] = fmaxf(acc[nn], 0.f);
        }
        __syncthreads();
        if (t < 128) {
            float acc[8];
            float bb = b3[t];
#pragma unroll
            for (int nn = 0; nn < 8; ++nn) acc[nn] = bb;
            layer_oi(&W3[t * 64], ya, 64, acc);
#pragma unroll
            for (int nn = 0; nn < 8; ++nn) yc[t * 8 + nn] = fmaxf(acc[nn], 0.f);
        }
        __syncthreads();
        {
            float acc[8];
            float bb = b4[t];
#pragma unroll
            for (int nn = 0; nn < 8; ++nn) acc[nn] = bb;
            layer_oi(&W4[t * 128], yc, 128, acc);
            float hw = hW[t];
            float val[8];
#pragma unroll
            for (int nn = 0; nn < 8; ++nn) val[nn] = hw * fmaxf(acc[nn], 0.f);
#pragma unroll
            for (int nn = 0; nn < 8; ++nn) {
#pragma unroll
                for (int off = 16; off; off >>= 1)
                    val[nn] += __shfl_xor_sync(0xffffffffu, val[nn], off);
            }
            if ((t & 31) == 0) {
                int w = t >> 5;   // 0..15
#pragma unroll
                for (int nn = 0; nn < 8; ++nn) red2[nn * 16 + w] = val[nn];
            }
        }
        __syncthreads();
        if (t < 128) {
            float v = red2[t];   // t = nn*16 + w
#pragma unroll
            for (int off = 1; off < 16; off <<= 1)
                v += __shfl_xor_sync(0xffffffffu, v, off);
            if ((t & 15) == 0)
                out[bi * 4 * NA + 3 * NA + n0 + (t >> 4)] = v;
        }
        return;
    }
    // ---- flow: 8 anchors per block ----
    {
        int bl = blockIdx.x - 64;
        int bi = bl >> 5;
        int sub = t >> 6;
        int tt = t & 63;
        int a = (bl & 31) * 8 + sub;
        __shared__ float sx[512], sy[512], sz[512];
        const float* geo = g_geo + bi * 16;
        float q0 = geo[9], q1 = geo[10], q2 = geo[11];
        const float* ap = anch + bi * 3 * NB;
        const float* r2row = g_R2 + (bi * NA + a) * NB;
        float s0 = 0.f, s1 = 0.f, s2 = 0.f;
        for (int b = tt; b < NB; b += 64) {
            float r2 = r2row[b];
            s0 += 2.f * (ap[b] - q0) * r2;
            s1 += 2.f * (ap[NB + b] - q1) * r2;
            s2 += 2.f * (ap[2 * NB + b] - q2) * r2;
        }
        int base = sub * 64;
        sx[base + tt] = s0; sy[base + tt] = s1; sz[base + tt] = s2;
        __syncthreads();
        for (int s = 32; s; s >>= 1) {
            if (tt < s) {
                sx[base + tt] += sx[base + tt + s];
                sy[base + tt] += sy[base + tt + s];
                sz[base + tt] += sz[base + tt + s];
            }
            __syncthreads();
        }
        if (tt == 0) {
            float r0 = geo[6] - sx[base], r1 = geo[7] - sy[base], r2_ = geo[8] - sz[base];
            float p0 = geo[0] * r0 + geo[1] * r1 + geo[2] * r2_;
            float p1 = geo[1] * r0 + geo[3] * r1 + geo[4] * r2_;
            float p2 = geo[2] * r0 + geo[4] * r1 + geo[5] * r2_;
            const float* app = actp + bi * 3 * NA;
            out[bi * 4 * NA + 0 * NA + a] = p0 - app[a];
            out[bi * 4 * NA + 1 * NA + a] = p1 - app[NA + a];
            out[bi * 4 * NA + 2 * NA + a] = p2 - app[2 * NA + a];
        }
    }
}

// =========================================================================
extern "C" void kernel_launch(void* const* d_in, const int* in_sizes, int n_in,
                              void* d_out, int out_size) {
    const float* actE  = (const float*)d_in[0];
    const float* anchE = (const float*)d_in[1];
    const float* actP  = (const float*)d_in[2];
    const float* anchP = (const float*)d_in[3];
    const float* W1    = (const float*)d_in[4];
    const float* b1    = (const float*)d_in[5];
    const float* W2    = (const float*)d_in[6];
    const float* b2    = (const float*)d_in[7];
    const float* W3    = (const float*)d_in[8];
    const float* b3    = (const float*)d_in[9];
    const float* pnW0  = (const float*)d_in[10];
    const float* pnb0  = (const float*)d_in[11];
    const float* pnW1  = (const float*)d_in[12];
    const float* pnb1  = (const float*)d_in[13];
    const float* pnW2  = (const float*)d_in[14];
    const float* pnb2  = (const float*)d_in[15];
    const float* pnW3  = (const float*)d_in[16];
    const float* pnb3  = (const float*)d_in[17];
    const float* pnW4  = (const float*)d_in[18];
    const float* pnb4  = (const float*)d_in[19];
    const float* headW = (const float*)d_in[20];
    float* out = (float*)d_out;

    cudaFuncSetAttribute(k2_hmma, cudaFuncAttributeMaxDynamicSharedMemorySize, SM_TOTAL);

    kp_prep<<<160, 256>>>(W2, actE, pnW0, pnb0, anchP);
    k1_h<<<dim3(5, 4, 8), dim3(16, 16)>>>(actE, anchE, W1, b1);
    k2_hmma<<<148, 768, SM_TOTAL>>>(b2, W3, b3);
    k46<<<128, 512>>>(pnW1, pnb1, pnW2, pnb2, pnW3, pnb3, pnW4, pnb4, headW,
                      anchP, actP, out);
}